// round 1
// baseline (speedup 1.0000x reference)
#include <cuda_runtime.h>
#include <math.h>

#define NTOK 512
#define CSD 384
#define CZD 128
#define NH 12
#define CDIM 16
#define PQN 4
#define PVN 8
#define NBLK 8
#define QKV_W 1152
#define CAT_W 2112

// ---------------- device scratch (no allocation allowed) ----------------
__device__ __align__(16) float d_s[NTOK*CSD];
__device__ __align__(16) float d_Wall[CSD*QKV_W];
__device__ __align__(16) float d_qkv[NTOK*QKV_W];
__device__ __align__(16) float d_bT[NTOK*NTOK*NH];     // [i*512+j][h]
__device__ __align__(16) float d_a[NH*NTOK*NTOK];      // [h][i][j]
__device__ __align__(16) float d_kt[NH*NTOK*CDIM];     // [h][j][c]
__device__ __align__(16) float d_vallT[NH*40*NTOK];    // [h][d][j], d<16: v, d>=16: v_pts
__device__ __align__(16) float d_kpts[NH*NTOK*12];     // [h][j][p*3+x]
__device__ __align__(16) float d_qpts[NTOK*NH*12];     // [i][h][p*3+x]
__device__ __align__(16) float d_sqq[NTOK*NH];
__device__ __align__(16) float d_sqk[NH*NTOK];
__device__ __align__(16) float d_cat[NTOK*CAT_W];
__device__ __align__(16) float d_optraw[NTOK*NH*PVN*3];
__device__ __align__(16) float d_tmp[NTOK*CSD];
__device__ __align__(16) float d_tmp2[NTOK*CSD];
__device__ __align__(16) float d_R[NTOK*9];
__device__ __align__(16) float d_t[NTOK*3];

// ---------------- init ----------------
__global__ void k_init(const float* __restrict__ s_in) {
    int idx = blockIdx.x*blockDim.x + threadIdx.x;
    if (idx < NTOK*CSD) d_s[idx] = s_in[idx];
    if (idx < NTOK*9)   d_R[idx] = ((idx % 9) % 4 == 0) ? 1.f : 0.f;
    if (idx < NTOK*3)   d_t[idx] = 0.f;
}

__global__ void k_catW(const float* __restrict__ wq, const float* __restrict__ wkv,
                       const float* __restrict__ wqp, const float* __restrict__ wkvp) {
    int idx = blockIdx.x*blockDim.x + threadIdx.x;
    if (idx >= CSD*QKV_W) return;
    int k = idx / QKV_W, c = idx % QKV_W;
    float v;
    if (c < 192)      v = wq[k*192 + c];
    else if (c < 576) v = wkv[k*384 + (c-192)];
    else if (c < 720) v = wqp[k*144 + (c-576)];
    else              v = wkvp[k*432 + (c-720)];
    d_Wall[idx] = v;
}

// b = z @ w_b, once per launch.  One warp per (i,j) row, z read coalesced.
__global__ void k_bT(const float* __restrict__ z, const float* __restrict__ wb) {
    int gwarp = (blockIdx.x*blockDim.x + threadIdx.x) >> 5;
    int lane  = threadIdx.x & 31;
    int nwarps = (gridDim.x*blockDim.x) >> 5;
    float wreg[4][NH];
    #pragma unroll
    for (int k = 0; k < 4; k++)
        #pragma unroll
        for (int h = 0; h < NH; h++)
            wreg[k][h] = wb[(lane + 32*k)*NH + h];
    for (int row = gwarp; row < NTOK*NTOK; row += nwarps) {
        const float* zr = z + (size_t)row*CZD;
        float zv[4];
        #pragma unroll
        for (int k = 0; k < 4; k++) zv[k] = zr[lane + 32*k];
        float acc[NH];
        #pragma unroll
        for (int h = 0; h < NH; h++)
            acc[h] = zv[0]*wreg[0][h] + zv[1]*wreg[1][h] + zv[2]*wreg[2][h] + zv[3]*wreg[3][h];
        #pragma unroll
        for (int h = 0; h < NH; h++)
            #pragma unroll
            for (int o = 16; o; o >>= 1)
                acc[h] += __shfl_xor_sync(0xffffffffu, acc[h], o);
        if (lane == 0) {
            #pragma unroll
            for (int h = 0; h < NH; h++) d_bT[row*NH + h] = acc[h];
        }
    }
}

// ---------------- generic SGEMM: C[M,N] = A[M,K] @ B[K,N] (+bias)(+relu) ----------------
// 64x64 tile, 256 threads, 4x4 microtile.  K must be a multiple of 16, M of 64.
__global__ void sgemm(const float* __restrict__ A, const float* __restrict__ B,
                      float* __restrict__ C, int M, int N, int K,
                      const float* __restrict__ bias, int doRelu) {
    __shared__ float As[16][64];
    __shared__ float Bs[16][64];
    int tid = threadIdx.x;
    int tx = tid & 15, ty = tid >> 4;
    int row0 = blockIdx.y * 64, col0 = blockIdx.x * 64;
    float acc[4][4] = {};
    for (int k0 = 0; k0 < K; k0 += 16) {
        {
            int r = tid >> 2, c = (tid & 3) * 4;
            const float4 av = *reinterpret_cast<const float4*>(A + (size_t)(row0 + r)*K + k0 + c);
            As[c+0][r] = av.x; As[c+1][r] = av.y; As[c+2][r] = av.z; As[c+3][r] = av.w;
        }
        #pragma unroll
        for (int i = 0; i < 4; i++) {
            int l = tid + i*256;
            int r = l >> 6, c = l & 63;
            int gc = col0 + c;
            Bs[r][c] = (gc < N) ? B[(size_t)(k0 + r)*N + gc] : 0.f;
        }
        __syncthreads();
        #pragma unroll
        for (int k = 0; k < 16; k++) {
            float4 a4 = *reinterpret_cast<const float4*>(&As[k][ty*4]);
            float4 b4 = *reinterpret_cast<const float4*>(&Bs[k][tx*4]);
            float am[4] = {a4.x, a4.y, a4.z, a4.w};
            float bn[4] = {b4.x, b4.y, b4.z, b4.w};
            #pragma unroll
            for (int mi = 0; mi < 4; mi++)
                #pragma unroll
                for (int ni = 0; ni < 4; ni++)
                    acc[mi][ni] += am[mi]*bn[ni];
        }
        __syncthreads();
    }
    #pragma unroll
    for (int mi = 0; mi < 4; mi++) {
        int r = row0 + ty*4 + mi;
        #pragma unroll
        for (int ni = 0; ni < 4; ni++) {
            int c = col0 + tx*4 + ni;
            if (c < N) {
                float v = acc[mi][ni];
                if (bias) v += bias[c];
                if (doRelu) v = fmaxf(v, 0.f);
                C[(size_t)r*N + c] = v;
            }
        }
    }
}

// ---------------- point transform + k/v layout ----------------
__global__ void k_transform() {
    int n = blockIdx.x;
    int tid = threadIdx.x;  // 128
    __shared__ float Rs[9], ts[3], sqq_s[NH], sqk_s[NH];
    if (tid < 9)  Rs[tid] = d_R[n*9 + tid];
    if (tid < 3)  ts[tid] = d_t[n*3 + tid];
    if (tid < NH) { sqq_s[tid] = 0.f; sqk_s[tid] = 0.f; }
    __syncthreads();
    const float* row = d_qkv + (size_t)n*QKV_W;
    // k, v: cols 192..575, layout h*32 + (c | 16+c)
    for (int l = tid; l < 384; l += 128) {
        int h = l >> 5, c = l & 31;
        float val = row[192 + l];
        if (c < 16) d_kt[(h*NTOK + n)*16 + c] = val;
        else        d_vallT[(h*40 + (c-16))*NTOK + n] = val;
    }
    // q points: 48, cols 576..719
    for (int p = tid; p < 48; p += 128) {
        float x = row[576 + p*3 + 0], y = row[576 + p*3 + 1], zz = row[576 + p*3 + 2];
        float px = Rs[0]*x + Rs[1]*y + Rs[2]*zz + ts[0];
        float py = Rs[3]*x + Rs[4]*y + Rs[5]*zz + ts[1];
        float pz = Rs[6]*x + Rs[7]*y + Rs[8]*zz + ts[2];
        int h = p >> 2, pp = p & 3;
        float* q = &d_qpts[(n*NH + h)*12 + pp*3];
        q[0] = px; q[1] = py; q[2] = pz;
        atomicAdd(&sqq_s[h], px*px + py*py + pz*pz);
    }
    // kv points: 144, cols 720..1151
    for (int p = tid; p < 144; p += 128) {
        float x = row[720 + p*3 + 0], y = row[720 + p*3 + 1], zz = row[720 + p*3 + 2];
        float px = Rs[0]*x + Rs[1]*y + Rs[2]*zz + ts[0];
        float py = Rs[3]*x + Rs[4]*y + Rs[5]*zz + ts[1];
        float pz = Rs[6]*x + Rs[7]*y + Rs[8]*zz + ts[2];
        int h = p / 12, pp = p % 12;
        if (pp < PQN) {
            float* kp = &d_kpts[(h*NTOK + n)*12 + pp*3];
            kp[0] = px; kp[1] = py; kp[2] = pz;
            atomicAdd(&sqk_s[h], px*px + py*py + pz*pz);
        } else {
            int d = 16 + (pp - PQN)*3;
            d_vallT[(h*40 + d + 0)*NTOK + n] = px;
            d_vallT[(h*40 + d + 1)*NTOK + n] = py;
            d_vallT[(h*40 + d + 2)*NTOK + n] = pz;
        }
    }
    __syncthreads();
    if (tid < NH) {
        d_sqq[n*NH + tid]  = sqq_s[tid];
        d_sqk[tid*NTOK + n] = sqk_s[tid];
    }
}

// ---------------- logits + softmax, one block per (i,h) ----------------
__global__ void k_attn(const float* __restrict__ hw) {
    int i = blockIdx.x, h = blockIdx.y;
    int tid = threadIdx.x;  // 256
    __shared__ float qv[16], qp[12], red[8];
    if (tid < 16) qv[tid] = d_qkv[(size_t)i*QKV_W + h*16 + tid];
    else if (tid < 28) qp[tid-16] = d_qpts[(i*NH + h)*12 + (tid-16)];
    float hwv = hw[h];
    float gamma = (hwv > 20.f) ? hwv : log1pf(expf(hwv));
    float sqi = d_sqq[i*NH + h];
    __syncthreads();
    const float wL = 0.5773502691896258f;             // sqrt(1/3)
    const float halfwC = 0.5f * 0.23570226039551587f; // sqrt(2/(9*PQ))/2
    float coef = gamma * halfwC;
    float lv[2];
    #pragma unroll
    for (int u = 0; u < 2; u++) {
        int j = tid + u*256;
        const float4* kr = reinterpret_cast<const float4*>(&d_kt[(h*NTOK + j)*16]);
        float sc = 0.f;
        #pragma unroll
        for (int c4 = 0; c4 < 4; c4++) {
            float4 kk = kr[c4];
            sc += qv[c4*4+0]*kk.x + qv[c4*4+1]*kk.y + qv[c4*4+2]*kk.z + qv[c4*4+3]*kk.w;
        }
        const float* kp = &d_kpts[(h*NTOK + j)*12];
        float cr = 0.f;
        #pragma unroll
        for (int d = 0; d < 12; d++) cr += qp[d]*kp[d];
        float d2 = sqi + d_sqk[h*NTOK + j] - 2.f*cr;
        lv[u] = wL*(0.25f*sc + d_bT[((size_t)i*NTOK + j)*NH + h] - coef*d2);
    }
    // block max
    float m = fmaxf(lv[0], lv[1]);
    #pragma unroll
    for (int o = 16; o; o >>= 1) m = fmaxf(m, __shfl_xor_sync(0xffffffffu, m, o));
    if ((tid & 31) == 0) red[tid >> 5] = m;
    __syncthreads();
    float gm = red[tid & 7];
    #pragma unroll
    for (int o = 4; o; o >>= 1) gm = fmaxf(gm, __shfl_xor_sync(0xffffffffu, gm, o));
    float e0 = __expf(lv[0] - gm), e1 = __expf(lv[1] - gm);
    float ssum = e0 + e1;
    #pragma unroll
    for (int o = 16; o; o >>= 1) ssum += __shfl_xor_sync(0xffffffffu, ssum, o);
    __syncthreads();
    if ((tid & 31) == 0) red[tid >> 5] = ssum;
    __syncthreads();
    float gs = red[tid & 7];
    #pragma unroll
    for (int o = 4; o; o >>= 1) gs += __shfl_xor_sync(0xffffffffu, gs, o);
    float inv = 1.f / gs;
    float* ar = &d_a[((size_t)h*NTOK + i)*NTOK];
    ar[tid]       = e0*inv;
    ar[tid + 256] = e1*inv;
}

// ---------------- o and o_pt (global frame): one block per (i,h) ----------------
__global__ void k_ov() {
    int i = blockIdx.x, h = blockIdx.y;
    int tid = threadIdx.x;  // 128
    __shared__ float as[NTOK];
    const float* ar = &d_a[((size_t)h*NTOK + i)*NTOK];
    for (int l = tid; l < NTOK; l += 128) as[l] = ar[l];
    __syncthreads();
    int warp = tid >> 5, lane = tid & 31;
    for (int d = warp; d < 40; d += 4) {
        const float* vr = &d_vallT[(h*40 + d)*NTOK];
        float acc = 0.f;
        for (int j = lane; j < NTOK; j += 32) acc += as[j]*vr[j];
        #pragma unroll
        for (int o = 16; o; o >>= 1) acc += __shfl_xor_sync(0xffffffffu, acc, o);
        if (lane == 0) {
            if (d < 16) d_cat[(size_t)i*CAT_W + h*16 + d] = acc;
            else        d_optraw[i*288 + h*24 + (d-16)]   = acc;
        }
    }
}

// ---------------- o_pair: one block per i, z read once ----------------
__global__ void k_opair(const float* __restrict__ z) {
    int i = blockIdx.x;
    int tid = threadIdx.x;  // 128
    __shared__ float as[NH*NTOK];   // 24 KB
    __shared__ float zs[32*CZD];    // 16 KB
    for (int l = tid; l < NH*NTOK; l += 128) {
        int h = l >> 9, j = l & 511;
        as[l] = d_a[((size_t)h*NTOK + i)*NTOK + j];
    }
    int zc0 = (tid & 31)*4;
    int h0  = tid >> 5;
    float acc[3][4] = {};
    for (int jt = 0; jt < NTOK; jt += 32) {
        __syncthreads();
        const float* zsrc = z + ((size_t)i*NTOK + jt)*CZD;
        for (int l = tid; l < 32*CZD; l += 128) zs[l] = zsrc[l];
        __syncthreads();
        #pragma unroll 4
        for (int jj = 0; jj < 32; jj++) {
            float4 zv = *reinterpret_cast<const float4*>(&zs[jj*CZD + zc0]);
            float a0 = as[(h0+0)*NTOK + jt + jj];
            float a1 = as[(h0+4)*NTOK + jt + jj];
            float a2 = as[(h0+8)*NTOK + jt + jj];
            acc[0][0] += a0*zv.x; acc[0][1] += a0*zv.y; acc[0][2] += a0*zv.z; acc[0][3] += a0*zv.w;
            acc[1][0] += a1*zv.x; acc[1][1] += a1*zv.y; acc[1][2] += a1*zv.z; acc[1][3] += a1*zv.w;
            acc[2][0] += a2*zv.x; acc[2][1] += a2*zv.y; acc[2][2] += a2*zv.z; acc[2][3] += a2*zv.w;
        }
    }
    #pragma unroll
    for (int hh = 0; hh < 3; hh++) {
        int h = h0 + hh*4;
        #pragma unroll
        for (int c = 0; c < 4; c++)
            d_cat[(size_t)i*CAT_W + 576 + h*CZD + zc0 + c] = acc[hh][c];
    }
}

// ---------------- o_pt back-transform + norm ----------------
__global__ void k_optback() {
    int i = blockIdx.x;
    int tid = threadIdx.x;  // 96 = H*PV
    __shared__ float Rs[9], ts[3];
    if (tid < 9) Rs[tid] = d_R[i*9 + tid];
    if (tid < 3) ts[tid] = d_t[i*3 + tid];
    __syncthreads();
    float gx = d_optraw[i*288 + tid*3 + 0] - ts[0];
    float gy = d_optraw[i*288 + tid*3 + 1] - ts[1];
    float gz = d_optraw[i*288 + tid*3 + 2] - ts[2];
    float lx = Rs[0]*gx + Rs[3]*gy + Rs[6]*gz;
    float ly = Rs[1]*gx + Rs[4]*gy + Rs[7]*gz;
    float lz = Rs[2]*gx + Rs[5]*gy + Rs[8]*gz;
    float* cr = &d_cat[(size_t)i*CAT_W];
    cr[192 + tid*3 + 0] = lx;
    cr[192 + tid*3 + 1] = ly;
    cr[192 + tid*3 + 2] = lz;
    cr[480 + tid] = sqrtf(lx*lx + ly*ly + lz*lz + 1e-8f);
}

// ---------------- s = LN(s + add) ----------------
__global__ void k_addln(const float* __restrict__ add, const float* __restrict__ g,
                        const float* __restrict__ b) {
    int i = blockIdx.x;
    int tid = threadIdx.x;  // 128
    __shared__ float red[4];
    float v[3];
    float sum = 0.f;
    #pragma unroll
    for (int k = 0; k < 3; k++) {
        int c = tid + k*128;
        v[k] = d_s[(size_t)i*CSD + c] + add[(size_t)i*CSD + c];
        sum += v[k];
    }
    #pragma unroll
    for (int o = 16; o; o >>= 1) sum += __shfl_xor_sync(0xffffffffu, sum, o);
    if ((tid & 31) == 0) red[tid >> 5] = sum;
    __syncthreads();
    float tot = red[tid & 3];
    #pragma unroll
    for (int o = 2; o; o >>= 1) tot += __shfl_xor_sync(0xffffffffu, tot, o);
    float mean = tot * (1.f/384.f);
    float var = 0.f;
    #pragma unroll
    for (int k = 0; k < 3; k++) { float d = v[k] - mean; var += d*d; }
    #pragma unroll
    for (int o = 16; o; o >>= 1) var += __shfl_xor_sync(0xffffffffu, var, o);
    __syncthreads();
    if ((tid & 31) == 0) red[tid >> 5] = var;
    __syncthreads();
    float tv = red[tid & 3];
    #pragma unroll
    for (int o = 2; o; o >>= 1) tv += __shfl_xor_sync(0xffffffffu, tv, o);
    float inv = rsqrtf(tv*(1.f/384.f) + 1e-5f);
    #pragma unroll
    for (int k = 0; k < 3; k++) {
        int c = tid + k*128;
        d_s[(size_t)i*CSD + c] = (v[k] - mean)*inv*g[c] + b[c];
    }
}

// ---------------- backbone update ----------------
__global__ void k_backbone(const float* __restrict__ wbb, const float* __restrict__ bbb) {
    int i = blockIdx.x;
    int tid = threadIdx.x;  // 192
    int warp = tid >> 5, lane = tid & 31;
    __shared__ float upd[6];
    float acc = 0.f;
    for (int k = lane; k < CSD; k += 32) acc += d_s[(size_t)i*CSD + k]*wbb[k*6 + warp];
    #pragma unroll
    for (int o = 16; o; o >>= 1) acc += __shfl_xor_sync(0xffffffffu, acc, o);
    if (lane == 0) upd[warp] = acc + bbb[warp];
    __syncthreads();
    if (tid == 0) {
        float qb = upd[0], qc = upd[1], qd = upd[2];
        float inv = rsqrtf(1.f + qb*qb + qc*qc + qd*qd);
        float w = inv, x = qb*inv, y = qc*inv, zq = qd*inv;
        float Ru[9];
        Ru[0] = 1.f - 2.f*(y*y + zq*zq); Ru[1] = 2.f*(x*y - w*zq);      Ru[2] = 2.f*(x*zq + w*y);
        Ru[3] = 2.f*(x*y + w*zq);        Ru[4] = 1.f - 2.f*(x*x + zq*zq); Ru[5] = 2.f*(y*zq - w*x);
        Ru[6] = 2.f*(x*zq - w*y);        Ru[7] = 2.f*(y*zq + w*x);      Ru[8] = 1.f - 2.f*(x*x + y*y);
        float Ro[9];
        #pragma unroll
        for (int k = 0; k < 9; k++) Ro[k] = d_R[i*9 + k];
        float tu0 = upd[3], tu1 = upd[4], tu2 = upd[5];
        #pragma unroll
        for (int r = 0; r < 3; r++)
            d_t[i*3 + r] += Ro[r*3+0]*tu0 + Ro[r*3+1]*tu1 + Ro[r*3+2]*tu2;
        #pragma unroll
        for (int r = 0; r < 3; r++)
            #pragma unroll
            for (int c = 0; c < 3; c++)
                d_R[i*9 + r*3 + c] = Ro[r*3+0]*Ru[0*3+c] + Ro[r*3+1]*Ru[1*3+c] + Ro[r*3+2]*Ru[2*3+c];
    }
}

// ---------------- final output [s | t] ----------------
__global__ void k_out(float* __restrict__ out) {
    int idx = blockIdx.x*blockDim.x + threadIdx.x;
    if (idx >= NTOK*387) return;
    int i = idx / 387, c = idx % 387;
    out[idx] = (c < 384) ? d_s[(size_t)i*CSD + c] : d_t[i*3 + (c - 384)];
}

// ---------------- host ----------------
extern "C" void kernel_launch(void* const* d_in, const int* in_sizes, int n_in,
                              void* d_out, int out_size) {
    (void)in_sizes; (void)n_in; (void)out_size;
    const float* s     = (const float*)d_in[0];
    const float* z     = (const float*)d_in[1];
    const float* wq    = (const float*)d_in[2];
    const float* wkv   = (const float*)d_in[3];
    const float* wqp   = (const float*)d_in[4];
    const float* wkvp  = (const float*)d_in[5];
    const float* wb    = (const float*)d_in[6];
    const float* hw    = (const float*)d_in[7];
    const float* wout  = (const float*)d_in[8];
    const float* bout  = (const float*)d_in[9];
    const float* ln1g  = (const float*)d_in[10];
    const float* ln1b  = (const float*)d_in[11];
    const float* wt1   = (const float*)d_in[12];
    const float* wt2   = (const float*)d_in[13];
    const float* wt3   = (const float*)d_in[14];
    const float* ln2g  = (const float*)d_in[15];
    const float* ln2b  = (const float*)d_in[16];
    const float* wbb   = (const float*)d_in[17];
    const float* bbb   = (const float*)d_in[18];

    float *p_s, *p_Wall, *p_qkv, *p_cat, *p_tmp, *p_tmp2;
    cudaGetSymbolAddress((void**)&p_s,    d_s);
    cudaGetSymbolAddress((void**)&p_Wall, d_Wall);
    cudaGetSymbolAddress((void**)&p_qkv,  d_qkv);
    cudaGetSymbolAddress((void**)&p_cat,  d_cat);
    cudaGetSymbolAddress((void**)&p_tmp,  d_tmp);
    cudaGetSymbolAddress((void**)&p_tmp2, d_tmp2);

    k_init<<<(NTOK*CSD + 255)/256, 256>>>(s);
    k_catW<<<(CSD*QKV_W + 255)/256, 256>>>(wq, wkv, wqp, wkvp);
    k_bT<<<512, 256>>>(z, wb);

    for (int it = 0; it < NBLK; it++) {
        // fused q/kv/qpts/kvpts projection
        sgemm<<<dim3(QKV_W/64, NTOK/64), 256>>>(p_s, p_Wall, p_qkv, NTOK, QKV_W, CSD, nullptr, 0);
        k_transform<<<NTOK, 128>>>();
        k_attn<<<dim3(NTOK, NH), 256>>>(hw);
        k_ov<<<dim3(NTOK, NH), 128>>>();
        k_opair<<<NTOK, 128>>>(z);
        k_optback<<<NTOK, 96>>>();
        // out projection + residual + LN1
        sgemm<<<dim3(CSD/64, NTOK/64), 256>>>(p_cat, wout, p_tmp, NTOK, CSD, CAT_W, bout, 0);
        k_addln<<<NTOK, 128>>>(p_tmp, ln1g, ln1b);
        // transition
        sgemm<<<dim3(CSD/64, NTOK/64), 256>>>(p_s,    wt1, p_tmp,  NTOK, CSD, CSD, nullptr, 1);
        sgemm<<<dim3(CSD/64, NTOK/64), 256>>>(p_tmp,  wt2, p_tmp2, NTOK, CSD, CSD, nullptr, 1);
        sgemm<<<dim3(CSD/64, NTOK/64), 256>>>(p_tmp2, wt3, p_tmp,  NTOK, CSD, CSD, nullptr, 0);
        k_addln<<<NTOK, 128>>>(p_tmp, ln2g, ln2b);
        // backbone update
        k_backbone<<<NTOK, 192>>>(wbb, bbb);
    }
    k_out<<<(NTOK*387 + 255)/256, 256>>>((float*)d_out);
}

// round 2
// speedup vs baseline: 1.0127x; 1.0127x over previous
#include <cuda_runtime.h>
#include <math.h>

#define NTOK 512
#define CSD 384
#define CZD 128
#define NH 12
#define CDIM 16
#define PQN 4
#define PVN 8
#define NBLK 8
#define QKV_W 1152
#define CAT_W 2112

// ---------------- device scratch (no allocation allowed) ----------------
__device__ __align__(16) float d_s[NTOK*CSD];
__device__ __align__(16) float d_Wall[CSD*QKV_W];
__device__ __align__(16) float d_qkv[NTOK*QKV_W];
__device__ __align__(16) float d_bT[NTOK*NTOK*NH];     // [i*512+j][h]
__device__ __align__(16) float d_a[NH*NTOK*NTOK];      // [h][i][j]
__device__ __align__(16) float d_kt[NH*NTOK*CDIM];     // [h][j][c]
__device__ __align__(16) float d_vallT[NH*40*NTOK];    // [h][d][j], d<16: v, d>=16: v_pts
__device__ __align__(16) float d_kpts[NH*NTOK*12];     // [h][j][p*3+x]
__device__ __align__(16) float d_qpts[NTOK*NH*12];     // [i][h][p*3+x]
__device__ __align__(16) float d_sqq[NTOK*NH];
__device__ __align__(16) float d_sqk[NH*NTOK];
__device__ __align__(16) float d_cat[NTOK*CAT_W];
__device__ __align__(16) float d_optraw[NTOK*NH*PVN*3];
__device__ __align__(16) float d_tmp[NTOK*CSD];
__device__ __align__(16) float d_tmp2[NTOK*CSD];
__device__ __align__(16) float d_R[NTOK*9];
__device__ __align__(16) float d_t[NTOK*3];

// ---------------- init ----------------
__global__ void k_init(const float* __restrict__ s_in) {
    int idx = blockIdx.x*blockDim.x + threadIdx.x;
    if (idx < NTOK*CSD) d_s[idx] = s_in[idx];
    if (idx < NTOK*9)   d_R[idx] = ((idx % 9) % 4 == 0) ? 1.f : 0.f;
    if (idx < NTOK*3)   d_t[idx] = 0.f;
}

__global__ void k_catW(const float* __restrict__ wq, const float* __restrict__ wkv,
                       const float* __restrict__ wqp, const float* __restrict__ wkvp) {
    int idx = blockIdx.x*blockDim.x + threadIdx.x;
    if (idx >= CSD*QKV_W) return;
    int k = idx / QKV_W, c = idx % QKV_W;
    float v;
    if (c < 192)      v = wq[k*192 + c];
    else if (c < 576) v = wkv[k*384 + (c-192)];
    else if (c < 720) v = wqp[k*144 + (c-576)];
    else              v = wkvp[k*432 + (c-720)];
    d_Wall[idx] = v;
}

// b = z @ w_b, once per launch.  One warp per (i,j) row, z read coalesced.
__global__ void k_bT(const float* __restrict__ z, const float* __restrict__ wb) {
    int gwarp = (blockIdx.x*blockDim.x + threadIdx.x) >> 5;
    int lane  = threadIdx.x & 31;
    int nwarps = (gridDim.x*blockDim.x) >> 5;
    float wreg[4][NH];
    #pragma unroll
    for (int k = 0; k < 4; k++)
        #pragma unroll
        for (int h = 0; h < NH; h++)
            wreg[k][h] = wb[(lane + 32*k)*NH + h];
    for (int row = gwarp; row < NTOK*NTOK; row += nwarps) {
        const float* zr = z + (size_t)row*CZD;
        float zv[4];
        #pragma unroll
        for (int k = 0; k < 4; k++) zv[k] = zr[lane + 32*k];
        float acc[NH];
        #pragma unroll
        for (int h = 0; h < NH; h++)
            acc[h] = zv[0]*wreg[0][h] + zv[1]*wreg[1][h] + zv[2]*wreg[2][h] + zv[3]*wreg[3][h];
        #pragma unroll
        for (int h = 0; h < NH; h++)
            #pragma unroll
            for (int o = 16; o; o >>= 1)
                acc[h] += __shfl_xor_sync(0xffffffffu, acc[h], o);
        if (lane == 0) {
            #pragma unroll
            for (int h = 0; h < NH; h++) d_bT[row*NH + h] = acc[h];
        }
    }
}

// ---------------- generic SGEMM: C[M,N] = A[M,K] @ B[K,N] (+bias)(+relu) ----------------
// 64x64 tile, 256 threads, 4x4 microtile.  K must be a multiple of 16, M of 64.
__global__ void sgemm(const float* __restrict__ A, const float* __restrict__ B,
                      float* __restrict__ C, int M, int N, int K,
                      const float* __restrict__ bias, int doRelu) {
    __shared__ float As[16][64];
    __shared__ float Bs[16][64];
    int tid = threadIdx.x;
    int tx = tid & 15, ty = tid >> 4;
    int row0 = blockIdx.y * 64, col0 = blockIdx.x * 64;
    float acc[4][4] = {};
    for (int k0 = 0; k0 < K; k0 += 16) {
        {
            int r = tid >> 2, c = (tid & 3) * 4;
            const float4 av = *reinterpret_cast<const float4*>(A + (size_t)(row0 + r)*K + k0 + c);
            As[c+0][r] = av.x; As[c+1][r] = av.y; As[c+2][r] = av.z; As[c+3][r] = av.w;
        }
        #pragma unroll
        for (int i = 0; i < 4; i++) {
            int l = tid + i*256;
            int r = l >> 6, c = l & 63;
            int gc = col0 + c;
            Bs[r][c] = (gc < N) ? B[(size_t)(k0 + r)*N + gc] : 0.f;
        }
        __syncthreads();
        #pragma unroll
        for (int k = 0; k < 16; k++) {
            float4 a4 = *reinterpret_cast<const float4*>(&As[k][ty*4]);
            float4 b4 = *reinterpret_cast<const float4*>(&Bs[k][tx*4]);
            float am[4] = {a4.x, a4.y, a4.z, a4.w};
            float bn[4] = {b4.x, b4.y, b4.z, b4.w};
            #pragma unroll
            for (int mi = 0; mi < 4; mi++)
                #pragma unroll
                for (int ni = 0; ni < 4; ni++)
                    acc[mi][ni] += am[mi]*bn[ni];
        }
        __syncthreads();
    }
    #pragma unroll
    for (int mi = 0; mi < 4; mi++) {
        int r = row0 + ty*4 + mi;
        #pragma unroll
        for (int ni = 0; ni < 4; ni++) {
            int c = col0 + tx*4 + ni;
            if (c < N) {
                float v = acc[mi][ni];
                if (bias) v += bias[c];
                if (doRelu) v = fmaxf(v, 0.f);
                C[(size_t)r*N + c] = v;
            }
        }
    }
}

// ---------------- point transform + k/v layout ----------------
__global__ void k_transform() {
    int n = blockIdx.x;
    int tid = threadIdx.x;  // 128
    __shared__ float Rs[9], ts[3], sqq_s[NH], sqk_s[NH];
    if (tid < 9)  Rs[tid] = d_R[n*9 + tid];
    if (tid < 3)  ts[tid] = d_t[n*3 + tid];
    if (tid < NH) { sqq_s[tid] = 0.f; sqk_s[tid] = 0.f; }
    __syncthreads();
    const float* row = d_qkv + (size_t)n*QKV_W;
    // k, v: cols 192..575, layout h*32 + (c | 16+c)
    for (int l = tid; l < 384; l += 128) {
        int h = l >> 5, c = l & 31;
        float val = row[192 + l];
        if (c < 16) d_kt[(h*NTOK + n)*16 + c] = val;
        else        d_vallT[(h*40 + (c-16))*NTOK + n] = val;
    }
    // q points: 48, cols 576..719
    for (int p = tid; p < 48; p += 128) {
        float x = row[576 + p*3 + 0], y = row[576 + p*3 + 1], zz = row[576 + p*3 + 2];
        float px = Rs[0]*x + Rs[1]*y + Rs[2]*zz + ts[0];
        float py = Rs[3]*x + Rs[4]*y + Rs[5]*zz + ts[1];
        float pz = Rs[6]*x + Rs[7]*y + Rs[8]*zz + ts[2];
        int h = p >> 2, pp = p & 3;
        float* q = &d_qpts[(n*NH + h)*12 + pp*3];
        q[0] = px; q[1] = py; q[2] = pz;
        atomicAdd(&sqq_s[h], px*px + py*py + pz*pz);
    }
    // kv points: 144, cols 720..1151
    for (int p = tid; p < 144; p += 128) {
        float x = row[720 + p*3 + 0], y = row[720 + p*3 + 1], zz = row[720 + p*3 + 2];
        float px = Rs[0]*x + Rs[1]*y + Rs[2]*zz + ts[0];
        float py = Rs[3]*x + Rs[4]*y + Rs[5]*zz + ts[1];
        float pz = Rs[6]*x + Rs[7]*y + Rs[8]*zz + ts[2];
        int h = p / 12, pp = p % 12;
        if (pp < PQN) {
            float* kp = &d_kpts[(h*NTOK + n)*12 + pp*3];
            kp[0] = px; kp[1] = py; kp[2] = pz;
            atomicAdd(&sqk_s[h], px*px + py*py + pz*pz);
        } else {
            int d = 16 + (pp - PQN)*3;
            d_vallT[(h*40 + d + 0)*NTOK + n] = px;
            d_vallT[(h*40 + d + 1)*NTOK + n] = py;
            d_vallT[(h*40 + d + 2)*NTOK + n] = pz;
        }
    }
    __syncthreads();
    if (tid < NH) {
        d_sqq[n*NH + tid]  = sqq_s[tid];
        d_sqk[tid*NTOK + n] = sqk_s[tid];
    }
}

// ---------------- logits + softmax, one block per (i,h) ----------------
__global__ void k_attn(const float* __restrict__ hw) {
    int i = blockIdx.x, h = blockIdx.y;
    int tid = threadIdx.x;  // 256
    __shared__ float qv[16], qp[12], red[8];
    if (tid < 16) qv[tid] = d_qkv[(size_t)i*QKV_W + h*16 + tid];
    else if (tid < 28) qp[tid-16] = d_qpts[(i*NH + h)*12 + (tid-16)];
    float hwv = hw[h];
    float gamma = (hwv > 20.f) ? hwv : log1pf(expf(hwv));
    float sqi = d_sqq[i*NH + h];
    __syncthreads();
    const float wL = 0.5773502691896258f;             // sqrt(1/3)
    const float halfwC = 0.5f * 0.23570226039551587f; // sqrt(2/(9*PQ))/2
    float coef = gamma * halfwC;
    float lv[2];
    #pragma unroll
    for (int u = 0; u < 2; u++) {
        int j = tid + u*256;
        const float4* kr = reinterpret_cast<const float4*>(&d_kt[(h*NTOK + j)*16]);
        float sc = 0.f;
        #pragma unroll
        for (int c4 = 0; c4 < 4; c4++) {
            float4 kk = kr[c4];
            sc += qv[c4*4+0]*kk.x + qv[c4*4+1]*kk.y + qv[c4*4+2]*kk.z + qv[c4*4+3]*kk.w;
        }
        const float* kp = &d_kpts[(h*NTOK + j)*12];
        float cr = 0.f;
        #pragma unroll
        for (int d = 0; d < 12; d++) cr += qp[d]*kp[d];
        float d2 = sqi + d_sqk[h*NTOK + j] - 2.f*cr;
        lv[u] = wL*(0.25f*sc + d_bT[((size_t)i*NTOK + j)*NH + h] - coef*d2);
    }
    // block max
    float m = fmaxf(lv[0], lv[1]);
    #pragma unroll
    for (int o = 16; o; o >>= 1) m = fmaxf(m, __shfl_xor_sync(0xffffffffu, m, o));
    if ((tid & 31) == 0) red[tid >> 5] = m;
    __syncthreads();
    float gm = red[tid & 7];
    #pragma unroll
    for (int o = 4; o; o >>= 1) gm = fmaxf(gm, __shfl_xor_sync(0xffffffffu, gm, o));
    float e0 = __expf(lv[0] - gm), e1 = __expf(lv[1] - gm);
    float ssum = e0 + e1;
    #pragma unroll
    for (int o = 16; o; o >>= 1) ssum += __shfl_xor_sync(0xffffffffu, ssum, o);
    __syncthreads();
    if ((tid & 31) == 0) red[tid >> 5] = ssum;
    __syncthreads();
    float gs = red[tid & 7];
    #pragma unroll
    for (int o = 4; o; o >>= 1) gs += __shfl_xor_sync(0xffffffffu, gs, o);
    float inv = 1.f / gs;
    float* ar = &d_a[((size_t)h*NTOK + i)*NTOK];
    ar[tid]       = e0*inv;
    ar[tid + 256] = e1*inv;
}

// ---------------- o and o_pt (global frame): one block per (i,h) ----------------
__global__ void k_ov() {
    int i = blockIdx.x, h = blockIdx.y;
    int tid = threadIdx.x;  // 128
    __shared__ float as[NTOK];
    const float* ar = &d_a[((size_t)h*NTOK + i)*NTOK];
    for (int l = tid; l < NTOK; l += 128) as[l] = ar[l];
    __syncthreads();
    int warp = tid >> 5, lane = tid & 31;
    for (int d = warp; d < 40; d += 4) {
        const float* vr = &d_vallT[(h*40 + d)*NTOK];
        float acc = 0.f;
        for (int j = lane; j < NTOK; j += 32) acc += as[j]*vr[j];
        #pragma unroll
        for (int o = 16; o; o >>= 1) acc += __shfl_xor_sync(0xffffffffu, acc, o);
        if (lane == 0) {
            if (d < 16) d_cat[(size_t)i*CAT_W + h*16 + d] = acc;
            else        d_optraw[i*288 + h*24 + (d-16)]   = acc;
        }
    }
}

// ---------------- o_pair: one block per i, z read once ----------------
__global__ void k_opair(const float* __restrict__ z) {
    int i = blockIdx.x;
    int tid = threadIdx.x;  // 128
    __shared__ float as[NH*NTOK];   // 24 KB
    __shared__ float zs[32*CZD];    // 16 KB
    for (int l = tid; l < NH*NTOK; l += 128) {
        int h = l >> 9, j = l & 511;
        as[l] = d_a[((size_t)h*NTOK + i)*NTOK + j];
    }
    int zc0 = (tid & 31)*4;
    int h0  = tid >> 5;
    float acc[3][4] = {};
    for (int jt = 0; jt < NTOK; jt += 32) {
        __syncthreads();
        const float* zsrc = z + ((size_t)i*NTOK + jt)*CZD;
        for (int l = tid; l < 32*CZD; l += 128) zs[l] = zsrc[l];
        __syncthreads();
        #pragma unroll 4
        for (int jj = 0; jj < 32; jj++) {
            float4 zv = *reinterpret_cast<const float4*>(&zs[jj*CZD + zc0]);
            float a0 = as[(h0+0)*NTOK + jt + jj];
            float a1 = as[(h0+4)*NTOK + jt + jj];
            float a2 = as[(h0+8)*NTOK + jt + jj];
            acc[0][0] += a0*zv.x; acc[0][1] += a0*zv.y; acc[0][2] += a0*zv.z; acc[0][3] += a0*zv.w;
            acc[1][0] += a1*zv.x; acc[1][1] += a1*zv.y; acc[1][2] += a1*zv.z; acc[1][3] += a1*zv.w;
            acc[2][0] += a2*zv.x; acc[2][1] += a2*zv.y; acc[2][2] += a2*zv.z; acc[2][3] += a2*zv.w;
        }
    }
    #pragma unroll
    for (int hh = 0; hh < 3; hh++) {
        int h = h0 + hh*4;
        #pragma unroll
        for (int c = 0; c < 4; c++)
            d_cat[(size_t)i*CAT_W + 576 + h*CZD + zc0 + c] = acc[hh][c];
    }
}

// ---------------- o_pt back-transform + norm ----------------
__global__ void k_optback() {
    int i = blockIdx.x;
    int tid = threadIdx.x;  // 96 = H*PV
    __shared__ float Rs[9], ts[3];
    if (tid < 9) Rs[tid] = d_R[i*9 + tid];
    if (tid < 3) ts[tid] = d_t[i*3 + tid];
    __syncthreads();
    float gx = d_optraw[i*288 + tid*3 + 0] - ts[0];
    float gy = d_optraw[i*288 + tid*3 + 1] - ts[1];
    float gz = d_optraw[i*288 + tid*3 + 2] - ts[2];
    float lx = Rs[0]*gx + Rs[3]*gy + Rs[6]*gz;
    float ly = Rs[1]*gx + Rs[4]*gy + Rs[7]*gz;
    float lz = Rs[2]*gx + Rs[5]*gy + Rs[8]*gz;
    float* cr = &d_cat[(size_t)i*CAT_W];
    cr[192 + tid*3 + 0] = lx;
    cr[192 + tid*3 + 1] = ly;
    cr[192 + tid*3 + 2] = lz;
    cr[480 + tid] = sqrtf(lx*lx + ly*ly + lz*lz + 1e-8f);
}

// ---------------- s = LN(s + add) ----------------
__global__ void k_addln(const float* __restrict__ add, const float* __restrict__ g,
                        const float* __restrict__ b) {
    int i = blockIdx.x;
    int tid = threadIdx.x;  // 128
    __shared__ float red[4];
    float v[3];
    float sum = 0.f;
    #pragma unroll
    for (int k = 0; k < 3; k++) {
        int c = tid + k*128;
        v[k] = d_s[(size_t)i*CSD + c] + add[(size_t)i*CSD + c];
        sum += v[k];
    }
    #pragma unroll
    for (int o = 16; o; o >>= 1) sum += __shfl_xor_sync(0xffffffffu, sum, o);
    if ((tid & 31) == 0) red[tid >> 5] = sum;
    __syncthreads();
    float tot = red[tid & 3];
    #pragma unroll
    for (int o = 2; o; o >>= 1) tot += __shfl_xor_sync(0xffffffffu, tot, o);
    float mean = tot * (1.f/384.f);
    float var = 0.f;
    #pragma unroll
    for (int k = 0; k < 3; k++) { float d = v[k] - mean; var += d*d; }
    #pragma unroll
    for (int o = 16; o; o >>= 1) var += __shfl_xor_sync(0xffffffffu, var, o);
    __syncthreads();
    if ((tid & 31) == 0) red[tid >> 5] = var;
    __syncthreads();
    float tv = red[tid & 3];
    #pragma unroll
    for (int o = 2; o; o >>= 1) tv += __shfl_xor_sync(0xffffffffu, tv, o);
    float inv = rsqrtf(tv*(1.f/384.f) + 1e-5f);
    #pragma unroll
    for (int k = 0; k < 3; k++) {
        int c = tid + k*128;
        d_s[(size_t)i*CSD + c] = (v[k] - mean)*inv*g[c] + b[c];
    }
}

// ---------------- backbone update ----------------
__global__ void k_backbone(const float* __restrict__ wbb, const float* __restrict__ bbb) {
    int i = blockIdx.x;
    int tid = threadIdx.x;  // 192
    int warp = tid >> 5, lane = tid & 31;
    __shared__ float upd[6];
    float acc = 0.f;
    for (int k = lane; k < CSD; k += 32) acc += d_s[(size_t)i*CSD + k]*wbb[k*6 + warp];
    #pragma unroll
    for (int o = 16; o; o >>= 1) acc += __shfl_xor_sync(0xffffffffu, acc, o);
    if (lane == 0) upd[warp] = acc + bbb[warp];
    __syncthreads();
    if (tid == 0) {
        float qb = upd[0], qc = upd[1], qd = upd[2];
        float inv = rsqrtf(1.f + qb*qb + qc*qc + qd*qd);
        float w = inv, x = qb*inv, y = qc*inv, zq = qd*inv;
        float Ru[9];
        Ru[0] = 1.f - 2.f*(y*y + zq*zq); Ru[1] = 2.f*(x*y - w*zq);      Ru[2] = 2.f*(x*zq + w*y);
        Ru[3] = 2.f*(x*y + w*zq);        Ru[4] = 1.f - 2.f*(x*x + zq*zq); Ru[5] = 2.f*(y*zq - w*x);
        Ru[6] = 2.f*(x*zq - w*y);        Ru[7] = 2.f*(y*zq + w*x);      Ru[8] = 1.f - 2.f*(x*x + y*y);
        float Ro[9];
        #pragma unroll
        for (int k = 0; k < 9; k++) Ro[k] = d_R[i*9 + k];
        float tu0 = upd[3], tu1 = upd[4], tu2 = upd[5];
        #pragma unroll
        for (int r = 0; r < 3; r++)
            d_t[i*3 + r] += Ro[r*3+0]*tu0 + Ro[r*3+1]*tu1 + Ro[r*3+2]*tu2;
        #pragma unroll
        for (int r = 0; r < 3; r++)
            #pragma unroll
            for (int c = 0; c < 3; c++)
                d_R[i*9 + r*3 + c] = Ro[r*3+0]*Ru[0*3+c] + Ro[r*3+1]*Ru[1*3+c] + Ro[r*3+2]*Ru[2*3+c];
    }
}

// ---------------- final output [s | t] ----------------
__global__ void k_out(float* __restrict__ out) {
    int idx = blockIdx.x*blockDim.x + threadIdx.x;
    if (idx >= NTOK*387) return;
    int i = idx / 387, c = idx % 387;
    out[idx] = (c < 384) ? d_s[(size_t)i*CSD + c] : d_t[i*3 + (c - 384)];
}

// ---------------- host ----------------
extern "C" void kernel_launch(void* const* d_in, const int* in_sizes, int n_in,
                              void* d_out, int out_size) {
    (void)in_sizes; (void)n_in; (void)out_size;
    const float* s     = (const float*)d_in[0];
    const float* z     = (const float*)d_in[1];
    const float* wq    = (const float*)d_in[2];
    const float* wkv   = (const float*)d_in[3];
    const float* wqp   = (const float*)d_in[4];
    const float* wkvp  = (const float*)d_in[5];
    const float* wb    = (const float*)d_in[6];
    const float* hw    = (const float*)d_in[7];
    const float* wout  = (const float*)d_in[8];
    const float* bout  = (const float*)d_in[9];
    const float* ln1g  = (const float*)d_in[10];
    const float* ln1b  = (const float*)d_in[11];
    const float* wt1   = (const float*)d_in[12];
    const float* wt2   = (const float*)d_in[13];
    const float* wt3   = (const float*)d_in[14];
    const float* ln2g  = (const float*)d_in[15];
    const float* ln2b  = (const float*)d_in[16];
    const float* wbb   = (const float*)d_in[17];
    const float* bbb   = (const float*)d_in[18];

    float *p_s, *p_Wall, *p_qkv, *p_cat, *p_tmp, *p_tmp2;
    cudaGetSymbolAddress((void**)&p_s,    d_s);
    cudaGetSymbolAddress((void**)&p_Wall, d_Wall);
    cudaGetSymbolAddress((void**)&p_qkv,  d_qkv);
    cudaGetSymbolAddress((void**)&p_cat,  d_cat);
    cudaGetSymbolAddress((void**)&p_tmp,  d_tmp);
    cudaGetSymbolAddress((void**)&p_tmp2, d_tmp2);

    k_init<<<(NTOK*CSD + 255)/256, 256>>>(s);
    k_catW<<<(CSD*QKV_W + 255)/256, 256>>>(wq, wkv, wqp, wkvp);
    k_bT<<<512, 256>>>(z, wb);

    for (int it = 0; it < NBLK; it++) {
        // fused q/kv/qpts/kvpts projection
        sgemm<<<dim3(QKV_W/64, NTOK/64), 256>>>(p_s, p_Wall, p_qkv, NTOK, QKV_W, CSD, nullptr, 0);
        k_transform<<<NTOK, 128>>>();
        k_attn<<<dim3(NTOK, NH), 256>>>(hw);
        k_ov<<<dim3(NTOK, NH), 128>>>();
        k_opair<<<NTOK, 128>>>(z);
        k_optback<<<NTOK, 96>>>();
        // out projection + residual + LN1
        sgemm<<<dim3(CSD/64, NTOK/64), 256>>>(p_cat, wout, p_tmp, NTOK, CSD, CAT_W, bout, 0);
        k_addln<<<NTOK, 128>>>(p_tmp, ln1g, ln1b);
        // transition
        sgemm<<<dim3(CSD/64, NTOK/64), 256>>>(p_s,    wt1, p_tmp,  NTOK, CSD, CSD, nullptr, 1);
        sgemm<<<dim3(CSD/64, NTOK/64), 256>>>(p_tmp,  wt2, p_tmp2, NTOK, CSD, CSD, nullptr, 1);
        sgemm<<<dim3(CSD/64, NTOK/64), 256>>>(p_tmp2, wt3, p_tmp,  NTOK, CSD, CSD, nullptr, 0);
        k_addln<<<NTOK, 128>>>(p_tmp, ln2g, ln2b);
        // backbone update
        k_backbone<<<NTOK, 192>>>(wbb, bbb);
    }
    k_out<<<(NTOK*387 + 255)/256, 256>>>((float*)d_out);
}

// round 4
// speedup vs baseline: 1.9420x; 1.9176x over previous
#include <cuda_runtime.h>
#include <math.h>

#define NTOK 512
#define CSD 384
#define CZD 128
#define NH 12
#define PQN 4
#define PVN 8
#define NBLK 8
#define QKV_W 1152
#define CAT_W 2112
#define MNS (NTOK*CSD)

#define WL 0.57735026918962576f             /* sqrt(1/3) */
#define HALFWC 0.11785113019775793f         /* 0.5*sqrt(2/(9*4)) */

// ---------------- device scratch ----------------
__device__ __align__(16) float d_s[NTOK*CSD];
__device__ __align__(16) float d_Wall[CSD*QKV_W];
__device__ __align__(16) float d_qkv[NTOK*QKV_W];
__device__ __align__(16) float d_bT[(size_t)NH*NTOK*NTOK];   // [h][i][j], pre-scaled by wL
__device__ __align__(16) float d_a[(size_t)NH*NTOK*NTOK];    // [h][i][j] logits -> attn
__device__ __align__(16) float d_QfT[NH*32*NTOK];            // [h][f][i], f<29 used, 29..31 zero
__device__ __align__(16) float d_KfT[NH*32*NTOK];            // [h][f][j]
__device__ __align__(16) float d_vJ[NH*NTOK*64];             // [h][j][d], d<40 used, 40..63 zero
__device__ __align__(16) float d_cat[NTOK*CAT_W];
__device__ __align__(16) float d_optraw[NTOK*NH*PVN*3];
__device__ __align__(16) float d_tmp[NTOK*CSD];
__device__ __align__(16) float d_tmp2[NTOK*CSD];
__device__ __align__(16) float d_part[6*NTOK*CSD];
__device__ __align__(16) float d_R[NTOK*9];
__device__ __align__(16) float d_t[NTOK*3];

// ---------------- init ----------------
__global__ void k_init(const float* __restrict__ s_in) {
    int idx = blockIdx.x*blockDim.x + threadIdx.x;
    if (idx < NTOK*CSD) d_s[idx] = s_in[idx];
    if (idx < NTOK*9)   d_R[idx] = ((idx % 9) % 4 == 0) ? 1.f : 0.f;
    if (idx < NTOK*3)   d_t[idx] = 0.f;
}

__global__ void k_catW(const float* __restrict__ wq, const float* __restrict__ wkv,
                       const float* __restrict__ wqp, const float* __restrict__ wkvp) {
    int idx = blockIdx.x*blockDim.x + threadIdx.x;
    if (idx >= CSD*QKV_W) return;
    int k = idx / QKV_W, c = idx % QKV_W;
    float v;
    if (c < 192)      v = wq[k*192 + c];
    else if (c < 576) v = wkv[k*384 + (c-192)];
    else if (c < 720) v = wqp[k*144 + (c-576)];
    else              v = wkvp[k*432 + (c-720)];
    d_Wall[idx] = v;
}

// b = wL * (z @ w_b), once per launch, layout [h][i][j]
__global__ void k_bT(const float* __restrict__ z, const float* __restrict__ wb) {
    int gwarp = (blockIdx.x*blockDim.x + threadIdx.x) >> 5;
    int lane  = threadIdx.x & 31;
    int nwarps = (gridDim.x*blockDim.x) >> 5;
    float wreg[4][NH];
    #pragma unroll
    for (int k = 0; k < 4; k++)
        #pragma unroll
        for (int h = 0; h < NH; h++)
            wreg[k][h] = wb[(lane + 32*k)*NH + h];
    for (int row = gwarp; row < NTOK*NTOK; row += nwarps) {
        const float* zr = z + (size_t)row*CZD;
        float zv[4];
        #pragma unroll
        for (int k = 0; k < 4; k++) zv[k] = zr[lane + 32*k];
        float acc[NH];
        #pragma unroll
        for (int h = 0; h < NH; h++)
            acc[h] = zv[0]*wreg[0][h] + zv[1]*wreg[1][h] + zv[2]*wreg[2][h] + zv[3]*wreg[3][h];
        #pragma unroll
        for (int h = 0; h < NH; h++)
            #pragma unroll
            for (int o = 16; o; o >>= 1)
                acc[h] += __shfl_xor_sync(0xffffffffu, acc[h], o);
        if (lane == 0) {
            int i = row >> 9, j = row & 511;
            #pragma unroll
            for (int h = 0; h < NH; h++)
                d_bT[((size_t)h*NTOK + i)*NTOK + j] = WL * acc[h];
        }
    }
}

// ------- double-buffered SGEMM with split-K: partial C[z] = A[.,Kp-slice] @ B -------
// 64x64 tile, 256 threads, 4x4 microtile. M%64==0, N%64==0, Kp%16==0.
__global__ void sgemm_split(const float* __restrict__ A, const float* __restrict__ B,
                            float* __restrict__ C, int M, int N, int K, int Kp) {
    __shared__ float As[2][16][68];
    __shared__ float Bs[2][16][64];
    int tid = threadIdx.x;
    int tx = tid & 15, ty = tid >> 4;
    int row0 = blockIdx.y * 64, col0 = blockIdx.x * 64;
    int kbase = blockIdx.z * Kp;
    const float* Ab = A + (size_t)row0*K + kbase;
    const float* Bb = B + (size_t)kbase*N + col0;
    float* Cb = C + (size_t)blockIdx.z*M*N;
    int ar = tid >> 2, ac = (tid & 3)*4;
    int br = tid >> 4, bc = (tid & 15)*4;

    float4 aR = *reinterpret_cast<const float4*>(&Ab[(size_t)ar*K + ac]);
    float4 bR = *reinterpret_cast<const float4*>(&Bb[(size_t)br*N + bc]);
    As[0][ac+0][ar] = aR.x; As[0][ac+1][ar] = aR.y; As[0][ac+2][ar] = aR.z; As[0][ac+3][ar] = aR.w;
    *reinterpret_cast<float4*>(&Bs[0][br][bc]) = bR;
    __syncthreads();

    float acc[4][4] = {};
    int KT = Kp >> 4;
    for (int kt = 0; kt < KT; kt++) {
        int cur = kt & 1;
        if (kt+1 < KT) {
            aR = *reinterpret_cast<const float4*>(&Ab[(size_t)ar*K + (kt+1)*16 + ac]);
            bR = *reinterpret_cast<const float4*>(&Bb[(size_t)((kt+1)*16 + br)*N + bc]);
        }
        #pragma unroll
        for (int k = 0; k < 16; k++) {
            float4 a4 = *reinterpret_cast<const float4*>(&As[cur][k][ty*4]);
            float4 b4 = *reinterpret_cast<const float4*>(&Bs[cur][k][tx*4]);
            float am[4] = {a4.x, a4.y, a4.z, a4.w};
            float bn[4] = {b4.x, b4.y, b4.z, b4.w};
            #pragma unroll
            for (int mi = 0; mi < 4; mi++)
                #pragma unroll
                for (int ni = 0; ni < 4; ni++)
                    acc[mi][ni] += am[mi]*bn[ni];
        }
        if (kt+1 < KT) {
            int nxt = cur ^ 1;
            As[nxt][ac+0][ar] = aR.x; As[nxt][ac+1][ar] = aR.y;
            As[nxt][ac+2][ar] = aR.z; As[nxt][ac+3][ar] = aR.w;
            *reinterpret_cast<float4*>(&Bs[nxt][br][bc]) = bR;
        }
        __syncthreads();
    }
    #pragma unroll
    for (int mi = 0; mi < 4; mi++) {
        float4 o4 = make_float4(acc[mi][0], acc[mi][1], acc[mi][2], acc[mi][3]);
        *reinterpret_cast<float4*>(&Cb[(size_t)(row0 + ty*4 + mi)*N + col0 + tx*4]) = o4;
    }
}

// ---------------- point transform + attention feature build ----------------
__global__ void k_transform(const float* __restrict__ hw) {
    int n = blockIdx.x;
    int tid = threadIdx.x;  // 128
    __shared__ float Rs[9], ts[3], sqk_s[NH], coef_s[NH];
    if (tid < 9)  Rs[tid] = d_R[n*9 + tid];
    if (tid < 3)  ts[tid] = d_t[n*3 + tid];
    if (tid < NH) {
        sqk_s[tid] = 0.f;
        float x = hw[tid];
        float g = (x > 20.f) ? x : log1pf(__expf(x));
        coef_s[tid] = g * HALFWC;
    }
    __syncthreads();
    const float* row = d_qkv + (size_t)n*QKV_W;
    // scalar q features, scaled by wL/4
    for (int l = tid; l < 192; l += 128) {
        int h = l >> 4, c = l & 15;
        d_QfT[(h*32 + c)*NTOK + n] = row[l] * (0.25f*WL);
    }
    // k scalar features + v scalars
    for (int l = tid; l < 384; l += 128) {
        int h = l >> 5, c = l & 31;
        float val = row[192 + l];
        if (c < 16) d_KfT[(h*32 + c)*NTOK + n] = val;
        else        d_vJ[((size_t)h*NTOK + n)*64 + (c-16)] = val;
    }
    // q points (scaled by 2*wL*coef)
    for (int p = tid; p < 48; p += 128) {
        float x = row[576 + p*3 + 0], y = row[576 + p*3 + 1], zz = row[576 + p*3 + 2];
        float px = Rs[0]*x + Rs[1]*y + Rs[2]*zz + ts[0];
        float py = Rs[3]*x + Rs[4]*y + Rs[5]*zz + ts[1];
        float pz = Rs[6]*x + Rs[7]*y + Rs[8]*zz + ts[2];
        int h = p >> 2, pp = p & 3;
        float s2 = 2.f*WL*coef_s[h];
        d_QfT[(h*32 + 16 + pp*3 + 0)*NTOK + n] = px*s2;
        d_QfT[(h*32 + 16 + pp*3 + 1)*NTOK + n] = py*s2;
        d_QfT[(h*32 + 16 + pp*3 + 2)*NTOK + n] = pz*s2;
    }
    if (tid < NH) d_QfT[(tid*32 + 28)*NTOK + n] = 1.f;
    // kv points
    for (int p = tid; p < 144; p += 128) {
        float x = row[720 + p*3 + 0], y = row[720 + p*3 + 1], zz = row[720 + p*3 + 2];
        float px = Rs[0]*x + Rs[1]*y + Rs[2]*zz + ts[0];
        float py = Rs[3]*x + Rs[4]*y + Rs[5]*zz + ts[1];
        float pz = Rs[6]*x + Rs[7]*y + Rs[8]*zz + ts[2];
        int h = p / 12, pp = p % 12;
        if (pp < PQN) {
            d_KfT[(h*32 + 16 + pp*3 + 0)*NTOK + n] = px;
            d_KfT[(h*32 + 16 + pp*3 + 1)*NTOK + n] = py;
            d_KfT[(h*32 + 16 + pp*3 + 2)*NTOK + n] = pz;
            atomicAdd(&sqk_s[h], px*px + py*py + pz*pz);
        } else {
            int d = 16 + (pp - PQN)*3;
            size_t base = ((size_t)h*NTOK + n)*64 + d;
            d_vJ[base + 0] = px;
            d_vJ[base + 1] = py;
            d_vJ[base + 2] = pz;
        }
    }
    __syncthreads();
    if (tid < NH) d_KfT[(tid*32 + 28)*NTOK + n] = -WL*coef_s[tid]*sqk_s[tid];
}

// ---------------- logits GEMM: a[h][i][j] = Qf^T Kf + bT ----------------
__global__ void k_logits() {
    __shared__ float Qs[32][64];
    __shared__ float Ks[32][64];
    int tid = threadIdx.x;
    int tx = tid & 15, ty = tid >> 4;
    int j0 = blockIdx.x * 64, i0 = blockIdx.y * 64, h = blockIdx.z;
    #pragma unroll
    for (int u = 0; u < 2; u++) {
        int l = tid + u*256;
        int f = l >> 4, c = (l & 15)*4;
        *reinterpret_cast<float4*>(&Qs[f][c]) =
            *reinterpret_cast<const float4*>(&d_QfT[(h*32 + f)*NTOK + i0 + c]);
        *reinterpret_cast<float4*>(&Ks[f][c]) =
            *reinterpret_cast<const float4*>(&d_KfT[(h*32 + f)*NTOK + j0 + c]);
    }
    __syncthreads();
    float acc[4][4] = {};
    #pragma unroll
    for (int f = 0; f < 32; f++) {
        float4 a4 = *reinterpret_cast<const float4*>(&Qs[f][ty*4]);
        float4 b4 = *reinterpret_cast<const float4*>(&Ks[f][tx*4]);
        float am[4] = {a4.x, a4.y, a4.z, a4.w};
        float bn[4] = {b4.x, b4.y, b4.z, b4.w};
        #pragma unroll
        for (int mi = 0; mi < 4; mi++)
            #pragma unroll
            for (int ni = 0; ni < 4; ni++)
                acc[mi][ni] += am[mi]*bn[ni];
    }
    #pragma unroll
    for (int mi = 0; mi < 4; mi++) {
        size_t off = ((size_t)h*NTOK + i0 + ty*4 + mi)*NTOK + j0 + tx*4;
        float4 bt = *reinterpret_cast<const float4*>(&d_bT[off]);
        float4 o = make_float4(acc[mi][0]+bt.x, acc[mi][1]+bt.y,
                               acc[mi][2]+bt.z, acc[mi][3]+bt.w);
        *reinterpret_cast<float4*>(&d_a[off]) = o;
    }
}

// ---------------- softmax over j (in place on d_a) ----------------
__global__ void k_softmax() {
    int i = blockIdx.x, h = blockIdx.y;
    int tid = threadIdx.x;  // 128
    __shared__ float red[4];
    float* row = &d_a[((size_t)h*NTOK + i)*NTOK];
    float4 v = *reinterpret_cast<const float4*>(&row[tid*4]);
    float m = fmaxf(fmaxf(v.x, v.y), fmaxf(v.z, v.w));
    #pragma unroll
    for (int o = 16; o; o >>= 1) m = fmaxf(m, __shfl_xor_sync(0xffffffffu, m, o));
    if ((tid & 31) == 0) red[tid >> 5] = m;
    __syncthreads();
    float gm = red[tid & 3];
    #pragma unroll
    for (int o = 2; o; o >>= 1) gm = fmaxf(gm, __shfl_xor_sync(0xffffffffu, gm, o));
    float e0 = __expf(v.x - gm), e1 = __expf(v.y - gm);
    float e2 = __expf(v.z - gm), e3 = __expf(v.w - gm);
    float s = e0 + e1 + e2 + e3;
    #pragma unroll
    for (int o = 16; o; o >>= 1) s += __shfl_xor_sync(0xffffffffu, s, o);
    __syncthreads();
    if ((tid & 31) == 0) red[tid >> 5] = s;
    __syncthreads();
    float gs = red[tid & 3];
    #pragma unroll
    for (int o = 2; o; o >>= 1) gs += __shfl_xor_sync(0xffffffffu, gs, o);
    float inv = 1.f / gs;
    *reinterpret_cast<float4*>(&row[tid*4]) = make_float4(e0*inv, e1*inv, e2*inv, e3*inv);
}

// ---------------- O = A @ V per head (double-buffered), scatter epilogue ----------------
__global__ void k_av() {
    __shared__ float As[2][16][68];
    __shared__ float Bs[2][16][64];
    int tid = threadIdx.x;
    int tx = tid & 15, ty = tid >> 4;
    int i0 = blockIdx.y * 64, h = blockIdx.z;
    const float* Ab = &d_a[((size_t)h*NTOK + i0)*NTOK];
    const float* Bb = &d_vJ[(size_t)h*NTOK*64];
    int ar = tid >> 2, ac = (tid & 3)*4;
    int br = tid >> 4, bc = (tid & 15)*4;

    float4 aR = *reinterpret_cast<const float4*>(&Ab[(size_t)ar*NTOK + ac]);
    float4 bR = *reinterpret_cast<const float4*>(&Bb[(size_t)br*64 + bc]);
    As[0][ac+0][ar] = aR.x; As[0][ac+1][ar] = aR.y; As[0][ac+2][ar] = aR.z; As[0][ac+3][ar] = aR.w;
    *reinterpret_cast<float4*>(&Bs[0][br][bc]) = bR;
    __syncthreads();

    float acc[4][4] = {};
    const int KT = NTOK/16;
    for (int kt = 0; kt < KT; kt++) {
        int cur = kt & 1;
        if (kt+1 < KT) {
            aR = *reinterpret_cast<const float4*>(&Ab[(size_t)ar*NTOK + (kt+1)*16 + ac]);
            bR = *reinterpret_cast<const float4*>(&Bb[(size_t)((kt+1)*16 + br)*64 + bc]);
        }
        #pragma unroll
        for (int k = 0; k < 16; k++) {
            float4 a4 = *reinterpret_cast<const float4*>(&As[cur][k][ty*4]);
            float4 b4 = *reinterpret_cast<const float4*>(&Bs[cur][k][tx*4]);
            float am[4] = {a4.x, a4.y, a4.z, a4.w};
            float bn[4] = {b4.x, b4.y, b4.z, b4.w};
            #pragma unroll
            for (int mi = 0; mi < 4; mi++)
                #pragma unroll
                for (int ni = 0; ni < 4; ni++)
                    acc[mi][ni] += am[mi]*bn[ni];
        }
        if (kt+1 < KT) {
            int nxt = cur ^ 1;
            As[nxt][ac+0][ar] = aR.x; As[nxt][ac+1][ar] = aR.y;
            As[nxt][ac+2][ar] = aR.z; As[nxt][ac+3][ar] = aR.w;
            *reinterpret_cast<float4*>(&Bs[nxt][br][bc]) = bR;
        }
        __syncthreads();
    }
    #pragma unroll
    for (int mi = 0; mi < 4; mi++) {
        int i = i0 + ty*4 + mi;
        #pragma unroll
        for (int ni = 0; ni < 4; ni++) {
            int d = tx*4 + ni;
            if (d < 16)      d_cat[(size_t)i*CAT_W + h*16 + d] = acc[mi][ni];
            else if (d < 40) d_optraw[i*288 + h*24 + (d-16)]   = acc[mi][ni];
        }
    }
}

// ---------------- o_pair: block per i, warp per head, z read once ----------------
__global__ void k_opair(const float* __restrict__ z) {
    int i = blockIdx.x;
    int tid = threadIdx.x;  // 384
    int h = tid >> 5, lane = tid & 31;
    __shared__ float as[NH*NTOK];   // 24 KB
    __shared__ float zs[32*CZD];    // 16 KB
    float4* as4 = reinterpret_cast<float4*>(as);
    for (int l = tid; l < NH*128; l += 384) {
        int hh = l >> 7, q = l & 127;
        as4[hh*128 + q] = *reinterpret_cast<const float4*>(&d_a[((size_t)hh*NTOK + i)*NTOK + q*4]);
    }
    float acc[4] = {};
    float4* zs4 = reinterpret_cast<float4*>(zs);
    for (int jt = 0; jt < NTOK; jt += 32) {
        __syncthreads();
        const float4* zsrc = reinterpret_cast<const float4*>(z + ((size_t)i*NTOK + jt)*CZD);
        for (int l = tid; l < 32*CZD/4; l += 384) zs4[l] = zsrc[l];
        __syncthreads();
        #pragma unroll 8
        for (int jj = 0; jj < 32; jj++) {
            float4 zv = zs4[jj*32 + lane];
            float a0 = as[h*NTOK + jt + jj];
            acc[0] += a0*zv.x; acc[1] += a0*zv.y; acc[2] += a0*zv.z; acc[3] += a0*zv.w;
        }
    }
    *reinterpret_cast<float4*>(&d_cat[(size_t)i*CAT_W + 576 + h*CZD + lane*4]) =
        make_float4(acc[0], acc[1], acc[2], acc[3]);
}

// ---------------- o_pt back-transform + norm ----------------
__global__ void k_optback() {
    int i = blockIdx.x;
    int tid = threadIdx.x;  // 96
    __shared__ float Rs[9], ts[3];
    if (tid < 9) Rs[tid] = d_R[i*9 + tid];
    if (tid < 3) ts[tid] = d_t[i*3 + tid];
    __syncthreads();
    float gx = d_optraw[i*288 + tid*3 + 0] - ts[0];
    float gy = d_optraw[i*288 + tid*3 + 1] - ts[1];
    float gz = d_optraw[i*288 + tid*3 + 2] - ts[2];
    float lx = Rs[0]*gx + Rs[3]*gy + Rs[6]*gz;
    float ly = Rs[1]*gx + Rs[4]*gy + Rs[7]*gz;
    float lz = Rs[2]*gx + Rs[5]*gy + Rs[8]*gz;
    float* cr = &d_cat[(size_t)i*CAT_W];
    cr[192 + tid*3 + 0] = lx;
    cr[192 + tid*3 + 1] = ly;
    cr[192 + tid*3 + 2] = lz;
    cr[480 + tid] = sqrtf(lx*lx + ly*ly + lz*lz + 1e-8f);
}

// ---------------- s = LN(s + bias + sum_p part[p]) ----------------
__global__ void k_addln(const float* __restrict__ part, int P,
                        const float* __restrict__ bias,
                        const float* __restrict__ g, const float* __restrict__ b) {
    int i = blockIdx.x;
    int tid = threadIdx.x;  // 128
    __shared__ float red[4];
    float v[3];
    float sum = 0.f;
    #pragma unroll
    for (int k = 0; k < 3; k++) {
        int c = tid + k*128;
        float x = d_s[(size_t)i*CSD + c];
        if (bias) x += bias[c];
        for (int p = 0; p < P; p++) x += part[(size_t)p*MNS + (size_t)i*CSD + c];
        v[k] = x;
        sum += x;
    }
    #pragma unroll
    for (int o = 16; o; o >>= 1) sum += __shfl_xor_sync(0xffffffffu, sum, o);
    if ((tid & 31) == 0) red[tid >> 5] = sum;
    __syncthreads();
    float tot = red[tid & 3];
    #pragma unroll
    for (int o = 2; o; o >>= 1) tot += __shfl_xor_sync(0xffffffffu, tot, o);
    float mean = tot * (1.f/384.f);
    float var = 0.f;
    #pragma unroll
    for (int k = 0; k < 3; k++) { float d = v[k] - mean; var += d*d; }
    #pragma unroll
    for (int o = 16; o; o >>= 1) var += __shfl_xor_sync(0xffffffffu, var, o);
    __syncthreads();
    if ((tid & 31) == 0) red[tid >> 5] = var;
    __syncthreads();
    float tv = red[tid & 3];
    #pragma unroll
    for (int o = 2; o; o >>= 1) tv += __shfl_xor_sync(0xffffffffu, tv, o);
    float inv = rsqrtf(tv*(1.f/384.f) + 1e-5f);
    #pragma unroll
    for (int k = 0; k < 3; k++) {
        int c = tid + k*128;
        d_s[(size_t)i*CSD + c] = (v[k] - mean)*inv*g[c] + b[c];
    }
}

// ---------------- relu(sum of 2 partials) ----------------
__global__ void k_relusum(const float* __restrict__ part, float* __restrict__ out) {
    int idx = blockIdx.x*blockDim.x + threadIdx.x;
    if (idx >= MNS) return;
    out[idx] = fmaxf(part[idx] + part[MNS + idx], 0.f);
}

// ---------------- backbone update ----------------
__global__ void k_backbone(const float* __restrict__ wbb, const float* __restrict__ bbb) {
    int i = blockIdx.x;
    int tid = threadIdx.x;  // 192
    int warp = tid >> 5, lane = tid & 31;
    __shared__ float upd[6];
    float acc = 0.f;
    for (int k = lane; k < CSD; k += 32) acc += d_s[(size_t)i*CSD + k]*wbb[k*6 + warp];
    #pragma unroll
    for (int o = 16; o; o >>= 1) acc += __shfl_xor_sync(0xffffffffu, acc, o);
    if (lane == 0) upd[warp] = acc + bbb[warp];
    __syncthreads();
    if (tid == 0) {
        float qb = upd[0], qc = upd[1], qd = upd[2];
        float inv = rsqrtf(1.f + qb*qb + qc*qc + qd*qd);
        float w = inv, x = qb*inv, y = qc*inv, zq = qd*inv;
        float Ru[9];
        Ru[0] = 1.f - 2.f*(y*y + zq*zq); Ru[1] = 2.f*(x*y - w*zq);        Ru[2] = 2.f*(x*zq + w*y);
        Ru[3] = 2.f*(x*y + w*zq);        Ru[4] = 1.f - 2.f*(x*x + zq*zq); Ru[5] = 2.f*(y*zq - w*x);
        Ru[6] = 2.f*(x*zq - w*y);        Ru[7] = 2.f*(y*zq + w*x);        Ru[8] = 1.f - 2.f*(x*x + y*y);
        float Ro[9];
        #pragma unroll
        for (int k = 0; k < 9; k++) Ro[k] = d_R[i*9 + k];
        float tu0 = upd[3], tu1 = upd[4], tu2 = upd[5];
        #pragma unroll
        for (int r = 0; r < 3; r++)
            d_t[i*3 + r] += Ro[r*3+0]*tu0 + Ro[r*3+1]*tu1 + Ro[r*3+2]*tu2;
        #pragma unroll
        for (int r = 0; r < 3; r++)
            #pragma unroll
            for (int c = 0; c < 3; c++)
                d_R[i*9 + r*3 + c] = Ro[r*3+0]*Ru[0*3+c] + Ro[r*3+1]*Ru[1*3+c] + Ro[r*3+2]*Ru[2*3+c];
    }
}

// ---------------- final output [s | t] ----------------
__global__ void k_out(float* __restrict__ out) {
    int idx = blockIdx.x*blockDim.x + threadIdx.x;
    if (idx >= NTOK*387) return;
    int i = idx / 387, c = idx % 387;
    out[idx] = (c < 384) ? d_s[(size_t)i*CSD + c] : d_t[i*3 + (c - 384)];
}

// ---------------- host ----------------
extern "C" void kernel_launch(void* const* d_in, const int* in_sizes, int n_in,
                              void* d_out, int out_size) {
    (void)in_sizes; (void)n_in; (void)out_size;
    const float* s     = (const float*)d_in[0];
    const float* z     = (const float*)d_in[1];
    const float* wq    = (const float*)d_in[2];
    const float* wkv   = (const float*)d_in[3];
    const float* wqp   = (const float*)d_in[4];
    const float* wkvp  = (const float*)d_in[5];
    const float* wb    = (const float*)d_in[6];
    const float* hw    = (const float*)d_in[7];
    const float* wout  = (const float*)d_in[8];
    const float* bout  = (const float*)d_in[9];
    const float* ln1g  = (const float*)d_in[10];
    const float* ln1b  = (const float*)d_in[11];
    const float* wt1   = (const float*)d_in[12];
    const float* wt2   = (const float*)d_in[13];
    const float* wt3   = (const float*)d_in[14];
    const float* ln2g  = (const float*)d_in[15];
    const float* ln2b  = (const float*)d_in[16];
    const float* wbb   = (const float*)d_in[17];
    const float* bbb   = (const float*)d_in[18];

    float *p_s, *p_Wall, *p_qkv, *p_cat, *p_tmp, *p_tmp2, *p_part;
    cudaGetSymbolAddress((void**)&p_s,    d_s);
    cudaGetSymbolAddress((void**)&p_Wall, d_Wall);
    cudaGetSymbolAddress((void**)&p_qkv,  d_qkv);
    cudaGetSymbolAddress((void**)&p_cat,  d_cat);
    cudaGetSymbolAddress((void**)&p_tmp,  d_tmp);
    cudaGetSymbolAddress((void**)&p_tmp2, d_tmp2);
    cudaGetSymbolAddress((void**)&p_part, d_part);

    k_init<<<(NTOK*CSD + 255)/256, 256>>>(s);
    k_catW<<<(CSD*QKV_W + 255)/256, 256>>>(wq, wkv, wqp, wkvp);
    k_bT<<<512, 256>>>(z, wb);

    for (int it = 0; it < NBLK; it++) {
        // fused qkv/points projection: 512x1152, K=384 (no split)
        sgemm_split<<<dim3(QKV_W/64, NTOK/64, 1), 256>>>(p_s, p_Wall, p_qkv, NTOK, QKV_W, CSD, CSD);
        k_transform<<<NTOK, 128>>>(hw);
        k_logits<<<dim3(8, 8, NH), 256>>>();
        k_softmax<<<dim3(NTOK, NH), 128>>>();
        k_av<<<dim3(1, 8, NH), 256>>>();
        k_opair<<<NTOK, 384>>>(z);
        k_optback<<<NTOK, 96>>>();
        // out projection: 512x384, K=2112, split 6
        sgemm_split<<<dim3(CSD/64, NTOK/64, 6), 256>>>(p_cat, wout, p_part, NTOK, CSD, CAT_W, CAT_W/6);
        k_addln<<<NTOK, 128>>>(p_part, 6, bout, ln1g, ln1b);
        // transition, split 2 each
        sgemm_split<<<dim3(CSD/64, NTOK/64, 2), 256>>>(p_s, wt1, p_part, NTOK, CSD, CSD, CSD/2);
        k_relusum<<<(MNS + 255)/256, 256>>>(p_part, p_tmp);
        sgemm_split<<<dim3(CSD/64, NTOK/64, 2), 256>>>(p_tmp, wt2, p_part, NTOK, CSD, CSD, CSD/2);
        k_relusum<<<(MNS + 255)/256, 256>>>(p_part, p_tmp2);
        sgemm_split<<<dim3(CSD/64, NTOK/64, 2), 256>>>(p_tmp2, wt3, p_part, NTOK, CSD, CSD, CSD/2);
        k_addln<<<NTOK, 128>>>(p_part, 2, nullptr, ln2g, ln2b);
        k_backbone<<<NTOK, 192>>>(wbb, bbb);
    }
    k_out<<<(NTOK*387 + 255)/256, 256>>>((float*)d_out);
}

// round 6
// speedup vs baseline: 2.2353x; 1.1510x over previous
#include <cuda_runtime.h>
#include <math.h>

#define NTOK 512
#define CSD 384
#define CZD 128
#define NH 12
#define PQN 4
#define PVN 8
#define NBLK 8
#define QKV_W 1152
#define CAT_W 2112
#define MNS (NTOK*CSD)
#define QOFF (NTOK*QKV_W)   /* 589824 = 3*MNS */

#define WL 0.57735026918962576f             /* sqrt(1/3) */
#define HALFWC 0.11785113019775793f         /* 0.5*sqrt(2/(9*4)) */

// ---------------- device scratch ----------------
__device__ __align__(16) float d_s[NTOK*CSD];
__device__ __align__(16) float d_Wall[CSD*QKV_W];
__device__ __align__(16) float d_bT[(size_t)NH*NTOK*NTOK];   // [h][i][j], pre-scaled by wL
__device__ __align__(16) float d_a[(size_t)NH*NTOK*NTOK];    // [h][i][j] attn weights
__device__ __align__(16) float d_QfT[NH*32*NTOK];            // [h][f][i], f<29 used
__device__ __align__(16) float d_KfT[NH*32*NTOK];            // [h][f][j]
__device__ __align__(16) float d_vJ[NH*NTOK*64];             // [h][j][d], d<40 used
__device__ __align__(16) float d_cat[NTOK*CAT_W];
__device__ __align__(16) float d_optraw[NTOK*NH*PVN*3];
__device__ __align__(16) float d_tmp[NTOK*CSD];
__device__ __align__(16) float d_tmp2[NTOK*CSD];
__device__ __align__(16) float d_part[6*NTOK*CSD];           // split-K partials (also qkv 2x)
__device__ __align__(16) float d_R[NTOK*9];
__device__ __align__(16) float d_t[NTOK*3];

// ---------------- init ----------------
__global__ void k_init(const float* __restrict__ s_in) {
    int idx = blockIdx.x*blockDim.x + threadIdx.x;
    if (idx < NTOK*CSD) d_s[idx] = s_in[idx];
    if (idx < NTOK*9)   d_R[idx] = ((idx % 9) % 4 == 0) ? 1.f : 0.f;
    if (idx < NTOK*3)   d_t[idx] = 0.f;
}

__global__ void k_catW(const float* __restrict__ wq, const float* __restrict__ wkv,
                       const float* __restrict__ wqp, const float* __restrict__ wkvp) {
    int idx = blockIdx.x*blockDim.x + threadIdx.x;
    if (idx >= CSD*QKV_W) return;
    int k = idx / QKV_W, c = idx % QKV_W;
    float v;
    if (c < 192)      v = wq[k*192 + c];
    else if (c < 576) v = wkv[k*384 + (c-192)];
    else if (c < 720) v = wqp[k*144 + (c-576)];
    else              v = wkvp[k*432 + (c-720)];
    d_Wall[idx] = v;
}

// b = wL * (z @ w_b), once per launch, layout [h][i][j]
__global__ void k_bT(const float* __restrict__ z, const float* __restrict__ wb) {
    int gwarp = (blockIdx.x*blockDim.x + threadIdx.x) >> 5;
    int lane  = threadIdx.x & 31;
    int nwarps = (gridDim.x*blockDim.x) >> 5;
    float wreg[4][NH];
    #pragma unroll
    for (int k = 0; k < 4; k++)
        #pragma unroll
        for (int h = 0; h < NH; h++)
            wreg[k][h] = wb[(lane + 32*k)*NH + h];
    for (int row = gwarp; row < NTOK*NTOK; row += nwarps) {
        const float* zr = z + (size_t)row*CZD;
        float zv[4];
        #pragma unroll
        for (int k = 0; k < 4; k++) zv[k] = zr[lane + 32*k];
        float acc[NH];
        #pragma unroll
        for (int h = 0; h < NH; h++)
            acc[h] = zv[0]*wreg[0][h] + zv[1]*wreg[1][h] + zv[2]*wreg[2][h] + zv[3]*wreg[3][h];
        #pragma unroll
        for (int h = 0; h < NH; h++)
            #pragma unroll
            for (int o = 16; o; o >>= 1)
                acc[h] += __shfl_xor_sync(0xffffffffu, acc[h], o);
        if (lane == 0) {
            int i = row >> 9, j = row & 511;
            #pragma unroll
            for (int h = 0; h < NH; h++)
                d_bT[((size_t)h*NTOK + i)*NTOK + j] = WL * acc[h];
        }
    }
}

// ------- double-buffered SGEMM with split-K: partial C[z] = A[.,Kp-slice] @ B -------
__global__ void sgemm_split(const float* __restrict__ A, const float* __restrict__ B,
                            float* __restrict__ C, int M, int N, int K, int Kp) {
    __shared__ float As[2][16][68];
    __shared__ float Bs[2][16][64];
    int tid = threadIdx.x;
    int tx = tid & 15, ty = tid >> 4;
    int row0 = blockIdx.y * 64, col0 = blockIdx.x * 64;
    int kbase = blockIdx.z * Kp;
    const float* Ab = A + (size_t)row0*K + kbase;
    const float* Bb = B + (size_t)kbase*N + col0;
    float* Cb = C + (size_t)blockIdx.z*M*N;
    int ar = tid >> 2, ac = (tid & 3)*4;
    int br = tid >> 4, bc = (tid & 15)*4;

    float4 aR = *reinterpret_cast<const float4*>(&Ab[(size_t)ar*K + ac]);
    float4 bR = *reinterpret_cast<const float4*>(&Bb[(size_t)br*N + bc]);
    As[0][ac+0][ar] = aR.x; As[0][ac+1][ar] = aR.y; As[0][ac+2][ar] = aR.z; As[0][ac+3][ar] = aR.w;
    *reinterpret_cast<float4*>(&Bs[0][br][bc]) = bR;
    __syncthreads();

    float acc[4][4] = {};
    int KT = Kp >> 4;
    for (int kt = 0; kt < KT; kt++) {
        int cur = kt & 1;
        if (kt+1 < KT) {
            aR = *reinterpret_cast<const float4*>(&Ab[(size_t)ar*K + (kt+1)*16 + ac]);
            bR = *reinterpret_cast<const float4*>(&Bb[(size_t)((kt+1)*16 + br)*N + bc]);
        }
        #pragma unroll
        for (int k = 0; k < 16; k++) {
            float4 a4 = *reinterpret_cast<const float4*>(&As[cur][k][ty*4]);
            float4 b4 = *reinterpret_cast<const float4*>(&Bs[cur][k][tx*4]);
            float am[4] = {a4.x, a4.y, a4.z, a4.w};
            float bn[4] = {b4.x, b4.y, b4.z, b4.w};
            #pragma unroll
            for (int mi = 0; mi < 4; mi++)
                #pragma unroll
                for (int ni = 0; ni < 4; ni++)
                    acc[mi][ni] += am[mi]*bn[ni];
        }
        if (kt+1 < KT) {
            int nxt = cur ^ 1;
            As[nxt][ac+0][ar] = aR.x; As[nxt][ac+1][ar] = aR.y;
            As[nxt][ac+2][ar] = aR.z; As[nxt][ac+3][ar] = aR.w;
            *reinterpret_cast<float4*>(&Bs[nxt][br][bc]) = bR;
        }
        __syncthreads();
    }
    #pragma unroll
    for (int mi = 0; mi < 4; mi++) {
        float4 o4 = make_float4(acc[mi][0], acc[mi][1], acc[mi][2], acc[mi][3]);
        *reinterpret_cast<float4*>(&Cb[(size_t)(row0 + ty*4 + mi)*N + col0 + tx*4]) = o4;
    }
}

// ---------------- point transform + feature build (sums 2 qkv split partials) ----------------
__global__ void k_transform(const float* __restrict__ hw) {
    int n = blockIdx.x;
    int tid = threadIdx.x;  // 128
    __shared__ float Rs[9], ts[3], sqk_s[NH], coef_s[NH];
    if (tid < 9)  Rs[tid] = d_R[n*9 + tid];
    if (tid < 3)  ts[tid] = d_t[n*3 + tid];
    if (tid < NH) {
        sqk_s[tid] = 0.f;
        float x = hw[tid];
        float g = (x > 20.f) ? x : log1pf(__expf(x));
        coef_s[tid] = g * HALFWC;
    }
    __syncthreads();
    const float* q0 = &d_part[(size_t)n*QKV_W];
    const float* q1 = &d_part[QOFF + (size_t)n*QKV_W];
    // scalar q features, scaled by wL/4
    for (int l = tid; l < 192; l += 128) {
        int h = l >> 4, c = l & 15;
        d_QfT[(h*32 + c)*NTOK + n] = (q0[l] + q1[l]) * (0.25f*WL);
    }
    // k scalar features + v scalars
    for (int l = tid; l < 384; l += 128) {
        int h = l >> 5, c = l & 31;
        float val = q0[192 + l] + q1[192 + l];
        if (c < 16) d_KfT[(h*32 + c)*NTOK + n] = val;
        else        d_vJ[((size_t)h*NTOK + n)*64 + (c-16)] = val;
    }
    // q points (scaled by 2*wL*coef)
    for (int p = tid; p < 48; p += 128) {
        float x  = q0[576 + p*3 + 0] + q1[576 + p*3 + 0];
        float y  = q0[576 + p*3 + 1] + q1[576 + p*3 + 1];
        float zz = q0[576 + p*3 + 2] + q1[576 + p*3 + 2];
        float px = Rs[0]*x + Rs[1]*y + Rs[2]*zz + ts[0];
        float py = Rs[3]*x + Rs[4]*y + Rs[5]*zz + ts[1];
        float pz = Rs[6]*x + Rs[7]*y + Rs[8]*zz + ts[2];
        int h = p >> 2, pp = p & 3;
        float s2 = 2.f*WL*coef_s[h];
        d_QfT[(h*32 + 16 + pp*3 + 0)*NTOK + n] = px*s2;
        d_QfT[(h*32 + 16 + pp*3 + 1)*NTOK + n] = py*s2;
        d_QfT[(h*32 + 16 + pp*3 + 2)*NTOK + n] = pz*s2;
    }
    if (tid < NH) d_QfT[(tid*32 + 28)*NTOK + n] = 1.f;
    // kv points
    for (int p = tid; p < 144; p += 128) {
        float x  = q0[720 + p*3 + 0] + q1[720 + p*3 + 0];
        float y  = q0[720 + p*3 + 1] + q1[720 + p*3 + 1];
        float zz = q0[720 + p*3 + 2] + q1[720 + p*3 + 2];
        float px = Rs[0]*x + Rs[1]*y + Rs[2]*zz + ts[0];
        float py = Rs[3]*x + Rs[4]*y + Rs[5]*zz + ts[1];
        float pz = Rs[6]*x + Rs[7]*y + Rs[8]*zz + ts[2];
        int h = p / 12, pp = p % 12;
        if (pp < PQN) {
            d_KfT[(h*32 + 16 + pp*3 + 0)*NTOK + n] = px;
            d_KfT[(h*32 + 16 + pp*3 + 1)*NTOK + n] = py;
            d_KfT[(h*32 + 16 + pp*3 + 2)*NTOK + n] = pz;
            atomicAdd(&sqk_s[h], px*px + py*py + pz*pz);
        } else {
            int d = 16 + (pp - PQN)*3;
            size_t base = ((size_t)h*NTOK + n)*64 + d;
            d_vJ[base + 0] = px;
            d_vJ[base + 1] = py;
            d_vJ[base + 2] = pz;
        }
    }
    __syncthreads();
    if (tid < NH) d_KfT[(tid*32 + 28)*NTOK + n] = -WL*coef_s[tid]*sqk_s[tid];
}

// ------- fused logits + bT + softmax: block = (16 i-rows, one head), full j row -------
__global__ void k_lsm() {
    int i0 = blockIdx.x * 16, h = blockIdx.y;
    int tid = threadIdx.x;          // 256
    int iloc = tid >> 4, jg = tid & 15;
    __shared__ float Qs[32][16];
    __shared__ float Ks[32][68];
    for (int l = tid; l < 512; l += 256) {
        int f = l >> 4, il = l & 15;
        Qs[f][il] = d_QfT[(h*32 + f)*NTOK + i0 + il];
    }
    float lv[32];
    #pragma unroll
    for (int t = 0; t < 8; t++) {
        __syncthreads();
        #pragma unroll
        for (int u = 0; u < 8; u++) {
            int l = tid + u*256;
            int f = l >> 6, jl = l & 63;
            Ks[f][jl] = d_KfT[(h*32 + f)*NTOK + t*64 + jl];
        }
        __syncthreads();
        float a0 = 0.f, a1 = 0.f, a2 = 0.f, a3 = 0.f;
        #pragma unroll
        for (int f = 0; f < 32; f++) {
            float qf = Qs[f][iloc];
            float4 kv = *reinterpret_cast<const float4*>(&Ks[f][jg*4]);
            a0 += qf*kv.x; a1 += qf*kv.y; a2 += qf*kv.z; a3 += qf*kv.w;
        }
        lv[t*4+0] = a0; lv[t*4+1] = a1; lv[t*4+2] = a2; lv[t*4+3] = a3;
    }
    int i = i0 + iloc;
    size_t rowoff = ((size_t)h*NTOK + i)*NTOK;
    float m = -1e30f;
    #pragma unroll
    for (int t = 0; t < 8; t++) {
        float4 bt = *reinterpret_cast<const float4*>(&d_bT[rowoff + t*64 + jg*4]);
        lv[t*4+0] += bt.x; lv[t*4+1] += bt.y; lv[t*4+2] += bt.z; lv[t*4+3] += bt.w;
        m = fmaxf(m, fmaxf(fmaxf(lv[t*4+0], lv[t*4+1]), fmaxf(lv[t*4+2], lv[t*4+3])));
    }
    #pragma unroll
    for (int o = 8; o; o >>= 1) m = fmaxf(m, __shfl_xor_sync(0xffffffffu, m, o));
    float s = 0.f;
    #pragma unroll
    for (int q = 0; q < 32; q++) { lv[q] = __expf(lv[q] - m); s += lv[q]; }
    #pragma unroll
    for (int o = 8; o; o >>= 1) s += __shfl_xor_sync(0xffffffffu, s, o);
    float inv = 1.f / s;
    #pragma unroll
    for (int t = 0; t < 8; t++) {
        float4 o4 = make_float4(lv[t*4+0]*inv, lv[t*4+1]*inv, lv[t*4+2]*inv, lv[t*4+3]*inv);
        *reinterpret_cast<float4*>(&d_a[rowoff + t*64 + jg*4]) = o4;
    }
}

// ---------------- O = A @ V per head, 32-row tiles (192 blocks), scatter epilogue ----------------
__global__ void k_av() {
    __shared__ float As[2][16][36];
    __shared__ float Bs[2][16][64];
    int tid = threadIdx.x;   // 128
    int tx = tid & 15, ty = tid >> 4;
    int i0 = blockIdx.y * 32, h = blockIdx.z;
    const float* Ab = &d_a[((size_t)h*NTOK + i0)*NTOK];
    const float* Bb = &d_vJ[(size_t)h*NTOK*64];
    int ar = tid >> 2, ac = (tid & 3)*4;   // 32 rows x 16 k
    int br = tid >> 4, bc = (tid & 15)*4;  // 16 k x 64 (rows br and br+8)

    float4 aR = *reinterpret_cast<const float4*>(&Ab[(size_t)ar*NTOK + ac]);
    float4 bR0 = *reinterpret_cast<const float4*>(&Bb[(size_t)br*64 + bc]);
    float4 bR1 = *reinterpret_cast<const float4*>(&Bb[(size_t)(br+8)*64 + bc]);
    As[0][ac+0][ar] = aR.x; As[0][ac+1][ar] = aR.y; As[0][ac+2][ar] = aR.z; As[0][ac+3][ar] = aR.w;
    *reinterpret_cast<float4*>(&Bs[0][br][bc]) = bR0;
    *reinterpret_cast<float4*>(&Bs[0][br+8][bc]) = bR1;
    __syncthreads();

    float acc[4][4] = {};
    const int KT = NTOK/16;
    for (int kt = 0; kt < KT; kt++) {
        int cur = kt & 1;
        if (kt+1 < KT) {
            aR  = *reinterpret_cast<const float4*>(&Ab[(size_t)ar*NTOK + (kt+1)*16 + ac]);
            bR0 = *reinterpret_cast<const float4*>(&Bb[(size_t)((kt+1)*16 + br)*64 + bc]);
            bR1 = *reinterpret_cast<const float4*>(&Bb[(size_t)((kt+1)*16 + br + 8)*64 + bc]);
        }
        #pragma unroll
        for (int k = 0; k < 16; k++) {
            float4 a4 = *reinterpret_cast<const float4*>(&As[cur][k][ty*4]);
            float4 b4 = *reinterpret_cast<const float4*>(&Bs[cur][k][tx*4]);
            float am[4] = {a4.x, a4.y, a4.z, a4.w};
            float bn[4] = {b4.x, b4.y, b4.z, b4.w};
            #pragma unroll
            for (int mi = 0; mi < 4; mi++)
                #pragma unroll
                for (int ni = 0; ni < 4; ni++)
                    acc[mi][ni] += am[mi]*bn[ni];
        }
        if (kt+1 < KT) {
            int nxt = cur ^ 1;
            As[nxt][ac+0][ar] = aR.x; As[nxt][ac+1][ar] = aR.y;
            As[nxt][ac+2][ar] = aR.z; As[nxt][ac+3][ar] = aR.w;
            *reinterpret_cast<float4*>(&Bs[nxt][br][bc]) = bR0;
            *reinterpret_cast<float4*>(&Bs[nxt][br+8][bc]) = bR1;
        }
        __syncthreads();
    }
    #pragma unroll
    for (int mi = 0; mi < 4; mi++) {
        int i = i0 + ty*4 + mi;
        #pragma unroll
        for (int ni = 0; ni < 4; ni++) {
            int d = tx*4 + ni;
            if (d < 16)      d_cat[(size_t)i*CAT_W + h*16 + d] = acc[mi][ni];
            else if (d < 40) d_optraw[i*288 + h*24 + (d-16)]   = acc[mi][ni];
        }
    }
}

// ---------------- o_pair: block per i, 3 heads per thread, z read once ----------------
__global__ void k_opair(const float* __restrict__ z) {
    int i = blockIdx.x;
    int tid = threadIdx.x;  // 128
    __shared__ float as[NH*NTOK];   // 24 KB
    __shared__ float zs[32*CZD];    // 16 KB
    float4* as4 = reinterpret_cast<float4*>(as);
    for (int l = tid; l < NH*128; l += 128) {
        int hh = l >> 7, q = l & 127;
        as4[hh*128 + q] = *reinterpret_cast<const float4*>(&d_a[((size_t)hh*NTOK + i)*NTOK + q*4]);
    }
    int lane = tid & 31, h0 = tid >> 5;
    float acc[3][4] = {};
    float4* zs4 = reinterpret_cast<float4*>(zs);
    for (int jt = 0; jt < NTOK; jt += 32) {
        __syncthreads();
        const float4* zsrc = reinterpret_cast<const float4*>(z + ((size_t)i*NTOK + jt)*CZD);
        for (int l = tid; l < 32*CZD/4; l += 128) zs4[l] = zsrc[l];
        __syncthreads();
        #pragma unroll 4
        for (int jj = 0; jj < 32; jj++) {
            float4 zv = zs4[jj*32 + lane];
            float a0 = as[(h0+0)*NTOK + jt + jj];
            float a1 = as[(h0+4)*NTOK + jt + jj];
            float a2 = as[(h0+8)*NTOK + jt + jj];
            acc[0][0] += a0*zv.x; acc[0][1] += a0*zv.y; acc[0][2] += a0*zv.z; acc[0][3] += a0*zv.w;
            acc[1][0] += a1*zv.x; acc[1][1] += a1*zv.y; acc[1][2] += a1*zv.z; acc[1][3] += a1*zv.w;
            acc[2][0] += a2*zv.x; acc[2][1] += a2*zv.y; acc[2][2] += a2*zv.z; acc[2][3] += a2*zv.w;
        }
    }
    #pragma unroll
    for (int hh = 0; hh < 3; hh++) {
        int h = h0 + hh*4;
        *reinterpret_cast<float4*>(&d_cat[(size_t)i*CAT_W + 576 + h*CZD + lane*4]) =
            make_float4(acc[hh][0], acc[hh][1], acc[hh][2], acc[hh][3]);
    }
}

// ---------------- o_pt back-transform + norm ----------------
__global__ void k_optback() {
    int i = blockIdx.x;
    int tid = threadIdx.x;  // 96
    __shared__ float Rs[9], ts[3];
    if (tid < 9) Rs[tid] = d_R[i*9 + tid];
    if (tid < 3) ts[tid] = d_t[i*3 + tid];
    __syncthreads();
    float gx = d_optraw[i*288 + tid*3 + 0] - ts[0];
    float gy = d_optraw[i*288 + tid*3 + 1] - ts[1];
    float gz = d_optraw[i*288 + tid*3 + 2] - ts[2];
    float lx = Rs[0]*gx + Rs[3]*gy + Rs[6]*gz;
    float ly = Rs[1]*gx + Rs[4]*gy + Rs[7]*gz;
    float lz = Rs[2]*gx + Rs[5]*gy + Rs[8]*gz;
    float* cr = &d_cat[(size_t)i*CAT_W];
    cr[192 + tid*3 + 0] = lx;
    cr[192 + tid*3 + 1] = ly;
    cr[192 + tid*3 + 2] = lz;
    cr[480 + tid] = sqrtf(lx*lx + ly*ly + lz*lz + 1e-8f);
}

// ---------------- s = LN(s + bias + sum_p part[p]) ----------------
__global__ void k_addln(const float* __restrict__ part, int P,
                        const float* __restrict__ bias,
                        const float* __restrict__ g, const float* __restrict__ b) {
    int i = blockIdx.x;
    int tid = threadIdx.x;  // 128
    __shared__ float red[4];
    float v[3];
    float sum = 0.f;
    #pragma unroll
    for (int k = 0; k < 3; k++) {
        int c = tid + k*128;
        float x = d_s[(size_t)i*CSD + c];
        if (bias) x += bias[c];
        for (int p = 0; p < P; p++) x += part[(size_t)p*MNS + (size_t)i*CSD + c];
        v[k] = x;
        sum += x;
    }
    #pragma unroll
    for (int o = 16; o; o >>= 1) sum += __shfl_xor_sync(0xffffffffu, sum, o);
    if ((tid & 31) == 0) red[tid >> 5] = sum;
    __syncthreads();
    float tot = red[tid & 3];
    #pragma unroll
    for (int o = 2; o; o >>= 1) tot += __shfl_xor_sync(0xffffffffu, tot, o);
    float mean = tot * (1.f/384.f);
    float var = 0.f;
    #pragma unroll
    for (int k = 0; k < 3; k++) { float d = v[k] - mean; var += d*d; }
    #pragma unroll
    for (int o = 16; o; o >>= 1) var += __shfl_xor_sync(0xffffffffu, var, o);
    __syncthreads();
    if ((tid & 31) == 0) red[tid >> 5] = var;
    __syncthreads();
    float tv = red[tid & 3];
    #pragma unroll
    for (int o = 2; o; o >>= 1) tv += __shfl_xor_sync(0xffffffffu, tv, o);
    float inv = rsqrtf(tv*(1.f/384.f) + 1e-5f);
    #pragma unroll
    for (int k = 0; k < 3; k++) {
        int c = tid + k*128;
        d_s[(size_t)i*CSD + c] = (v[k] - mean)*inv*g[c] + b[c];
    }
}

// ---------------- relu(sum of P partials) ----------------
__global__ void k_relusum(const float* __restrict__ part, int P, float* __restrict__ out) {
    int idx = blockIdx.x*blockDim.x + threadIdx.x;
    if (idx >= MNS) return;
    float x = 0.f;
    for (int p = 0; p < P; p++) x += part[(size_t)p*MNS + idx];
    out[idx] = fmaxf(x, 0.f);
}

// ---------------- backbone update ----------------
__global__ void k_backbone(const float* __restrict__ wbb, const float* __restrict__ bbb) {
    int i = blockIdx.x;
    int tid = threadIdx.x;  // 192
    int warp = tid >> 5, lane = tid & 31;
    __shared__ float upd[6];
    float acc = 0.f;
    for (int k = lane; k < CSD; k += 32) acc += d_s[(size_t)i*CSD + k]*wbb[k*6 + warp];
    #pragma unroll
    for (int o = 16; o; o >>= 1) acc += __shfl_xor_sync(0xffffffffu, acc, o);
    if (lane == 0) upd[warp] = acc + bbb[warp];
    __syncthreads();
    if (tid == 0) {
        float qb = upd[0], qc = upd[1], qd = upd[2];
        float inv = rsqrtf(1.f + qb*qb + qc*qc + qd*qd);
        float w = inv, x = qb*inv, y = qc*inv, zq = qd*inv;
        float Ru[9];
        Ru[0] = 1.f - 2.f*(y*y + zq*zq); Ru[1] = 2.f*(x*y - w*zq);        Ru[2] = 2.f*(x*zq + w*y);
        Ru[3] = 2.f*(x*y + w*zq);        Ru[4] = 1.f - 2.f*(x*x + zq*zq); Ru[5] = 2.f*(y*zq - w*x);
        Ru[6] = 2.f*(x*zq - w*y);        Ru[7] = 2.f*(y*zq + w*x);        Ru[8] = 1.f - 2.f*(x*x + y*y);
        float Ro[9];
        #pragma unroll
        for (int k = 0; k < 9; k++) Ro[k] = d_R[i*9 + k];
        float tu0 = upd[3], tu1 = upd[4], tu2 = upd[5];
        #pragma unroll
        for (int r = 0; r < 3; r++)
            d_t[i*3 + r] += Ro[r*3+0]*tu0 + Ro[r*3+1]*tu1 + Ro[r*3+2]*tu2;
        #pragma unroll
        for (int r = 0; r < 3; r++)
            #pragma unroll
            for (int c = 0; c < 3; c++)
                d_R[i*9 + r*3 + c] = Ro[r*3+0]*Ru[0*3+c] + Ro[r*3+1]*Ru[1*3+c] + Ro[r*3+2]*Ru[2*3+c];
    }
}

// ---------------- final output [s | t] ----------------
__global__ void k_out(float* __restrict__ out) {
    int idx = blockIdx.x*blockDim.x + threadIdx.x;
    if (idx >= NTOK*387) return;
    int i = idx / 387, c = idx % 387;
    out[idx] = (c < 384) ? d_s[(size_t)i*CSD + c] : d_t[i*3 + (c - 384)];
}

// ---------------- host ----------------
extern "C" void kernel_launch(void* const* d_in, const int* in_sizes, int n_in,
                              void* d_out, int out_size) {
    (void)in_sizes; (void)n_in; (void)out_size;
    const float* s     = (const float*)d_in[0];
    const float* z     = (const float*)d_in[1];
    const float* wq    = (const float*)d_in[2];
    const float* wkv   = (const float*)d_in[3];
    const float* wqp   = (const float*)d_in[4];
    const float* wkvp  = (const float*)d_in[5];
    const float* wb    = (const float*)d_in[6];
    const float* hw    = (const float*)d_in[7];
    const float* wout  = (const float*)d_in[8];
    const float* bout  = (const float*)d_in[9];
    const float* ln1g  = (const float*)d_in[10];
    const float* ln1b  = (const float*)d_in[11];
    const float* wt1   = (const float*)d_in[12];
    const float* wt2   = (const float*)d_in[13];
    const float* wt3   = (const float*)d_in[14];
    const float* ln2g  = (const float*)d_in[15];
    const float* ln2b  = (const float*)d_in[16];
    const float* wbb   = (const float*)d_in[17];
    const float* bbb   = (const float*)d_in[18];

    float *p_s, *p_Wall, *p_cat, *p_tmp, *p_tmp2, *p_part;
    cudaGetSymbolAddress((void**)&p_s,    d_s);
    cudaGetSymbolAddress((void**)&p_Wall, d_Wall);
    cudaGetSymbolAddress((void**)&p_cat,  d_cat);
    cudaGetSymbolAddress((void**)&p_tmp,  d_tmp);
    cudaGetSymbolAddress((void**)&p_tmp2, d_tmp2);
    cudaGetSymbolAddress((void**)&p_part, d_part);

    k_init<<<(NTOK*CSD + 255)/256, 256>>>(s);
    k_catW<<<(CSD*QKV_W + 255)/256, 256>>>(wq, wkv, wqp, wkvp);
    k_bT<<<512, 256>>>(z, wb);

    for (int it = 0; it < NBLK; it++) {
        // fused qkv/points projection: 512x1152, K=384 split 2 -> 288 blocks
        sgemm_split<<<dim3(QKV_W/64, NTOK/64, 2), 256>>>(p_s, p_Wall, p_part, NTOK, QKV_W, CSD, CSD/2);
        k_transform<<<NTOK, 128>>>(hw);
        // fused logits + softmax: 384 blocks
        k_lsm<<<dim3(32, NH), 256>>>();
        // A@V: 192 blocks
        k_av<<<dim3(1, 16, NH), 128>>>();
        k_opair<<<NTOK, 128>>>(z);
        k_optback<<<NTOK, 96>>>();
        // out projection: 512x384, K=2112 split 6 -> 288 blocks
        sgemm_split<<<dim3(CSD/64, NTOK/64, 6), 256>>>(p_cat, wout, p_part, NTOK, CSD, CAT_W, CAT_W/6);
        k_addln<<<NTOK, 128>>>(p_part, 6, bout, ln1g, ln1b);
        // transition, split 6 each -> 288 blocks
        sgemm_split<<<dim3(CSD/64, NTOK/64, 6), 256>>>(p_s, wt1, p_part, NTOK, CSD, CSD, CSD/6);
        k_relusum<<<(MNS + 255)/256, 256>>>(p_part, 6, p_tmp);
        sgemm_split<<<dim3(CSD/64, NTOK/64, 6), 256>>>(p_tmp, wt2, p_part, NTOK, CSD, CSD, CSD/6);
        k_relusum<<<(MNS + 255)/256, 256>>>(p_part, 6, p_tmp2);
        sgemm_split<<<dim3(CSD/64, NTOK/64, 6), 256>>>(p_tmp2, wt3, p_part, NTOK, CSD, CSD, CSD/6);
        k_addln<<<NTOK, 128>>>(p_part, 6, nullptr, ln2g, ln2b);
        k_backbone<<<NTOK, 192>>>(wbb, bbb);
    }
    k_out<<<(NTOK*387 + 255)/256, 256>>>((float*)d_out);
}

// round 7
// speedup vs baseline: 2.2768x; 1.0186x over previous
#include <cuda_runtime.h>
#include <math.h>
#include <stdint.h>

#define NTOK 512
#define CSD 384
#define CZD 128
#define NH 12
#define PQN 4
#define PVN 8
#define NBLK 8
#define QKV_W 1152
#define CAT_W 2112
#define MNS (NTOK*CSD)
#define QOFF (NTOK*QKV_W)

#define WL 0.57735026918962576f             /* sqrt(1/3) */
#define HALFWC 0.11785113019775793f         /* 0.5*sqrt(2/(9*4)) */

// ---------------- device scratch ----------------
__device__ __align__(16) float d_s[NTOK*CSD];
__device__ __align__(16) float d_Wall[CSD*QKV_W];
__device__ __align__(16) float d_WallHi[CSD*QKV_W];
__device__ __align__(16) float d_WallLo[CSD*QKV_W];
__device__ __align__(16) float d_woutHi[CAT_W*CSD];
__device__ __align__(16) float d_woutLo[CAT_W*CSD];
__device__ __align__(16) float d_wtHi[3*CSD*CSD];
__device__ __align__(16) float d_wtLo[3*CSD*CSD];
__device__ __align__(16) float d_bT[(size_t)NH*NTOK*NTOK];   // [h][i][j], pre-scaled by wL
__device__ __align__(16) float d_a[(size_t)NH*NTOK*NTOK];    // [h][i][j] attn weights
__device__ __align__(16) float d_QfT[NH*32*NTOK];            // [h][f][i]
__device__ __align__(16) float d_KfT[NH*32*NTOK];            // [h][f][j]
__device__ __align__(16) float d_vJ[NH*NTOK*64];             // [h][j][d]
__device__ __align__(16) float d_cat[NTOK*CAT_W];
__device__ __align__(16) float d_optraw[NTOK*NH*PVN*3];
__device__ __align__(16) float d_tmp[NTOK*CSD];
__device__ __align__(16) float d_tmp2[NTOK*CSD];
__device__ __align__(16) float d_part[6*NTOK*CSD];
__device__ __align__(16) float d_R[NTOK*9];
__device__ __align__(16) float d_t[NTOK*3];

// ---------------- init ----------------
__global__ void k_init(const float* __restrict__ s_in) {
    int idx = blockIdx.x*blockDim.x + threadIdx.x;
    if (idx < NTOK*CSD) d_s[idx] = s_in[idx];
    if (idx < NTOK*9)   d_R[idx] = ((idx % 9) % 4 == 0) ? 1.f : 0.f;
    if (idx < NTOK*3)   d_t[idx] = 0.f;
}

__global__ void k_catW(const float* __restrict__ wq, const float* __restrict__ wkv,
                       const float* __restrict__ wqp, const float* __restrict__ wkvp) {
    int idx = blockIdx.x*blockDim.x + threadIdx.x;
    if (idx >= CSD*QKV_W) return;
    int k = idx / QKV_W, c = idx % QKV_W;
    float v;
    if (c < 192)      v = wq[k*192 + c];
    else if (c < 576) v = wkv[k*384 + (c-192)];
    else if (c < 720) v = wqp[k*144 + (c-576)];
    else              v = wkvp[k*432 + (c-720)];
    d_Wall[idx] = v;
}

// split fp32 into tf32 hi/lo pair
__global__ void k_splitW(const float* __restrict__ src, float* __restrict__ hi,
                         float* __restrict__ lo, int n) {
    int i = blockIdx.x*blockDim.x + threadIdx.x;
    if (i >= n) return;
    float v = src[i];
    uint32_t hb; asm("cvt.rna.tf32.f32 %0, %1;" : "=r"(hb) : "f"(v));
    float hf = __uint_as_float(hb);
    float lf = v - hf;
    uint32_t lb; asm("cvt.rna.tf32.f32 %0, %1;" : "=r"(lb) : "f"(lf));
    hi[i] = hf;
    lo[i] = __uint_as_float(lb);
}

// b = wL * (z @ w_b), once per launch, layout [h][i][j]
__global__ void k_bT(const float* __restrict__ z, const float* __restrict__ wb) {
    int gwarp = (blockIdx.x*blockDim.x + threadIdx.x) >> 5;
    int lane  = threadIdx.x & 31;
    int nwarps = (gridDim.x*blockDim.x) >> 5;
    float wreg[4][NH];
    #pragma unroll
    for (int k = 0; k < 4; k++)
        #pragma unroll
        for (int h = 0; h < NH; h++)
            wreg[k][h] = wb[(lane + 32*k)*NH + h];
    for (int row = gwarp; row < NTOK*NTOK; row += nwarps) {
        const float* zr = z + (size_t)row*CZD;
        float zv[4];
        #pragma unroll
        for (int k = 0; k < 4; k++) zv[k] = zr[lane + 32*k];
        float acc[NH];
        #pragma unroll
        for (int h = 0; h < NH; h++)
            acc[h] = zv[0]*wreg[0][h] + zv[1]*wreg[1][h] + zv[2]*wreg[2][h] + zv[3]*wreg[3][h];
        #pragma unroll
        for (int h = 0; h < NH; h++)
            #pragma unroll
            for (int o = 16; o; o >>= 1)
                acc[h] += __shfl_xor_sync(0xffffffffu, acc[h], o);
        if (lane == 0) {
            int i = row >> 9, j = row & 511;
            #pragma unroll
            for (int h = 0; h < NH; h++)
                d_bT[((size_t)h*NTOK + i)*NTOK + j] = WL * acc[h];
        }
    }
}

#define MMA_TF32(d, a, b) \
    asm volatile("mma.sync.aligned.m16n8k8.row.col.f32.tf32.tf32.f32 " \
                 "{%0,%1,%2,%3},{%4,%5,%6,%7},{%8,%9},{%0,%1,%2,%3};" \
                 : "+f"(d[0]),"+f"(d[1]),"+f"(d[2]),"+f"(d[3]) \
                 : "r"(a[0]),"r"(a[1]),"r"(a[2]),"r"(a[3]),"r"(b[0]),"r"(b[1]))

// ------- 3xTF32 tensor-core GEMM, split-K: partial C[z] = A[.,Kp] @ B -------
// 64x64 tile, 256 threads (8 warps: 2x4 warp grid, 32x16 per warp).
// B pre-split into tf32 hi/lo; A split in-kernel. M%64==0, N%64==0, Kp%16==0.
__global__ void mm3(const float* __restrict__ A, const float* __restrict__ Bhi,
                    const float* __restrict__ Blo, float* __restrict__ C,
                    int M, int N, int K, int Kp) {
    __shared__ float As[2][64][20];
    __shared__ float Bh[2][16][72];
    __shared__ float Bl[2][16][72];
    int tid = threadIdx.x;
    int lane = tid & 31, warp = tid >> 5;
    int g = lane >> 2, tig = lane & 3;
    int wm = (warp >> 2) * 32;
    int wn = (warp & 3) * 16;
    int row0 = blockIdx.y * 64, col0 = blockIdx.x * 64;
    int kbase = blockIdx.z * Kp;
    const float* Ab  = A   + (size_t)row0*K + kbase;
    const float* Bhb = Bhi + (size_t)kbase*N + col0;
    const float* Blb = Blo + (size_t)kbase*N + col0;
    float* Cb = C + (size_t)blockIdx.z*M*N;

    int ar = tid >> 2, ac = (tid & 3)*4;
    int br = tid >> 4, bc = (tid & 15)*4;

    float4 aR = *reinterpret_cast<const float4*>(&Ab[(size_t)ar*K + ac]);
    float4 hR = *reinterpret_cast<const float4*>(&Bhb[(size_t)br*N + bc]);
    float4 lR = *reinterpret_cast<const float4*>(&Blb[(size_t)br*N + bc]);
    *reinterpret_cast<float4*>(&As[0][ar][ac]) = aR;
    *reinterpret_cast<float4*>(&Bh[0][br][bc]) = hR;
    *reinterpret_cast<float4*>(&Bl[0][br][bc]) = lR;
    __syncthreads();

    float acc[2][2][4] = {};
    int KT = Kp >> 4;
    for (int kt = 0; kt < KT; kt++) {
        int cur = kt & 1;
        if (kt+1 < KT) {
            aR = *reinterpret_cast<const float4*>(&Ab[(size_t)ar*K + (kt+1)*16 + ac]);
            hR = *reinterpret_cast<const float4*>(&Bhb[(size_t)((kt+1)*16 + br)*N + bc]);
            lR = *reinterpret_cast<const float4*>(&Blb[(size_t)((kt+1)*16 + br)*N + bc]);
        }
        #pragma unroll
        for (int ks = 0; ks < 2; ks++) {
            int k0 = ks*8;
            uint32_t ahi[2][4], alo[2][4];
            #pragma unroll
            for (int mt = 0; mt < 2; mt++) {
                #pragma unroll
                for (int rr = 0; rr < 4; rr++) {
                    int rm = wm + mt*16 + g + (rr & 1)*8;
                    int rk = k0 + tig + (rr >> 1)*4;
                    float av = As[cur][rm][rk];
                    uint32_t hb; asm("cvt.rna.tf32.f32 %0, %1;" : "=r"(hb) : "f"(av));
                    float hf = __uint_as_float(hb);
                    float lf = av - hf;
                    uint32_t lb; asm("cvt.rna.tf32.f32 %0, %1;" : "=r"(lb) : "f"(lf));
                    ahi[mt][rr] = hb; alo[mt][rr] = lb;
                }
            }
            uint32_t bhf[2][2], blf[2][2];
            #pragma unroll
            for (int nt = 0; nt < 2; nt++) {
                int cn = wn + nt*8 + g;
                bhf[nt][0] = __float_as_uint(Bh[cur][k0 + tig][cn]);
                bhf[nt][1] = __float_as_uint(Bh[cur][k0 + tig + 4][cn]);
                blf[nt][0] = __float_as_uint(Bl[cur][k0 + tig][cn]);
                blf[nt][1] = __float_as_uint(Bl[cur][k0 + tig + 4][cn]);
            }
            #pragma unroll
            for (int mt = 0; mt < 2; mt++)
                #pragma unroll
                for (int nt = 0; nt < 2; nt++) {
                    MMA_TF32(acc[mt][nt], ahi[mt], bhf[nt]);
                    MMA_TF32(acc[mt][nt], ahi[mt], blf[nt]);
                    MMA_TF32(acc[mt][nt], alo[mt], bhf[nt]);
                }
        }
        if (kt+1 < KT) {
            int nxt = cur ^ 1;
            *reinterpret_cast<float4*>(&As[nxt][ar][ac]) = aR;
            *reinterpret_cast<float4*>(&Bh[nxt][br][bc]) = hR;
            *reinterpret_cast<float4*>(&Bl[nxt][br][bc]) = lR;
        }
        __syncthreads();
    }
    #pragma unroll
    for (int mt = 0; mt < 2; mt++)
        #pragma unroll
        for (int nt = 0; nt < 2; nt++) {
            int r0 = row0 + wm + mt*16 + g;
            int c  = col0 + wn + nt*8 + 2*tig;
            *reinterpret_cast<float2*>(&Cb[(size_t)r0*N + c]) =
                make_float2(acc[mt][nt][0], acc[mt][nt][1]);
            *reinterpret_cast<float2*>(&Cb[(size_t)(r0+8)*N + c]) =
                make_float2(acc[mt][nt][2], acc[mt][nt][3]);
        }
}

// ---------------- point transform + feature build (sums 2 qkv split partials) ----------------
__global__ void k_transform(const float* __restrict__ hw) {
    int n = blockIdx.x;
    int tid = threadIdx.x;  // 128
    __shared__ float Rs[9], ts[3], sqk_s[NH], coef_s[NH];
    if (tid < 9)  Rs[tid] = d_R[n*9 + tid];
    if (tid < 3)  ts[tid] = d_t[n*3 + tid];
    if (tid < NH) {
        sqk_s[tid] = 0.f;
        float x = hw[tid];
        float g = (x > 20.f) ? x : log1pf(__expf(x));
        coef_s[tid] = g * HALFWC;
    }
    __syncthreads();
    const float* q0 = &d_part[(size_t)n*QKV_W];
    const float* q1 = &d_part[QOFF + (size_t)n*QKV_W];
    for (int l = tid; l < 192; l += 128) {
        int h = l >> 4, c = l & 15;
        d_QfT[(h*32 + c)*NTOK + n] = (q0[l] + q1[l]) * (0.25f*WL);
    }
    for (int l = tid; l < 384; l += 128) {
        int h = l >> 5, c = l & 31;
        float val = q0[192 + l] + q1[192 + l];
        if (c < 16) d_KfT[(h*32 + c)*NTOK + n] = val;
        else        d_vJ[((size_t)h*NTOK + n)*64 + (c-16)] = val;
    }
    for (int p = tid; p < 48; p += 128) {
        float x  = q0[576 + p*3 + 0] + q1[576 + p*3 + 0];
        float y  = q0[576 + p*3 + 1] + q1[576 + p*3 + 1];
        float zz = q0[576 + p*3 + 2] + q1[576 + p*3 + 2];
        float px = Rs[0]*x + Rs[1]*y + Rs[2]*zz + ts[0];
        float py = Rs[3]*x + Rs[4]*y + Rs[5]*zz + ts[1];
        float pz = Rs[6]*x + Rs[7]*y + Rs[8]*zz + ts[2];
        int h = p >> 2, pp = p & 3;
        float s2 = 2.f*WL*coef_s[h];
        d_QfT[(h*32 + 16 + pp*3 + 0)*NTOK + n] = px*s2;
        d_QfT[(h*32 + 16 + pp*3 + 1)*NTOK + n] = py*s2;
        d_QfT[(h*32 + 16 + pp*3 + 2)*NTOK + n] = pz*s2;
    }
    if (tid < NH) d_QfT[(tid*32 + 28)*NTOK + n] = 1.f;
    for (int p = tid; p < 144; p += 128) {
        float x  = q0[720 + p*3 + 0] + q1[720 + p*3 + 0];
        float y  = q0[720 + p*3 + 1] + q1[720 + p*3 + 1];
        float zz = q0[720 + p*3 + 2] + q1[720 + p*3 + 2];
        float px = Rs[0]*x + Rs[1]*y + Rs[2]*zz + ts[0];
        float py = Rs[3]*x + Rs[4]*y + Rs[5]*zz + ts[1];
        float pz = Rs[6]*x + Rs[7]*y + Rs[8]*zz + ts[2];
        int h = p / 12, pp = p % 12;
        if (pp < PQN) {
            d_KfT[(h*32 + 16 + pp*3 + 0)*NTOK + n] = px;
            d_KfT[(h*32 + 16 + pp*3 + 1)*NTOK + n] = py;
            d_KfT[(h*32 + 16 + pp*3 + 2)*NTOK + n] = pz;
            atomicAdd(&sqk_s[h], px*px + py*py + pz*pz);
        } else {
            int d = 16 + (pp - PQN)*3;
            size_t base = ((size_t)h*NTOK + n)*64 + d;
            d_vJ[base + 0] = px;
            d_vJ[base + 1] = py;
            d_vJ[base + 2] = pz;
        }
    }
    __syncthreads();
    if (tid < NH) d_KfT[(tid*32 + 28)*NTOK + n] = -WL*coef_s[tid]*sqk_s[tid];
}

// ------- fused logits + bT + softmax: block = (16 i-rows, one head), full j row -------
__global__ void k_lsm() {
    int i0 = blockIdx.x * 16, h = blockIdx.y;
    int tid = threadIdx.x;          // 256
    int iloc = tid >> 4, jg = tid & 15;
    __shared__ float Qs[32][16];
    __shared__ float Ks[32][68];
    for (int l = tid; l < 512; l += 256) {
        int f = l >> 4, il = l & 15;
        Qs[f][il] = d_QfT[(h*32 + f)*NTOK + i0 + il];
    }
    float lv[32];
    #pragma unroll
    for (int t = 0; t < 8; t++) {
        __syncthreads();
        #pragma unroll
        for (int u = 0; u < 8; u++) {
            int l = tid + u*256;
            int f = l >> 6, jl = l & 63;
            Ks[f][jl] = d_KfT[(h*32 + f)*NTOK + t*64 + jl];
        }
        __syncthreads();
        float a0 = 0.f, a1 = 0.f, a2 = 0.f, a3 = 0.f;
        #pragma unroll
        for (int f = 0; f < 32; f++) {
            float qf = Qs[f][iloc];
            float4 kv = *reinterpret_cast<const float4*>(&Ks[f][jg*4]);
            a0 += qf*kv.x; a1 += qf*kv.y; a2 += qf*kv.z; a3 += qf*kv.w;
        }
        lv[t*4+0] = a0; lv[t*4+1] = a1; lv[t*4+2] = a2; lv[t*4+3] = a3;
    }
    int i = i0 + iloc;
    size_t rowoff = ((size_t)h*NTOK + i)*NTOK;
    float m = -1e30f;
    #pragma unroll
    for (int t = 0; t < 8; t++) {
        float4 bt = *reinterpret_cast<const float4*>(&d_bT[rowoff + t*64 + jg*4]);
        lv[t*4+0] += bt.x; lv[t*4+1] += bt.y; lv[t*4+2] += bt.z; lv[t*4+3] += bt.w;
        m = fmaxf(m, fmaxf(fmaxf(lv[t*4+0], lv[t*4+1]), fmaxf(lv[t*4+2], lv[t*4+3])));
    }
    #pragma unroll
    for (int o = 8; o; o >>= 1) m = fmaxf(m, __shfl_xor_sync(0xffffffffu, m, o));
    float s = 0.f;
    #pragma unroll
    for (int q = 0; q < 32; q++) { lv[q] = __expf(lv[q] - m); s += lv[q]; }
    #pragma unroll
    for (int o = 8; o; o >>= 1) s += __shfl_xor_sync(0xffffffffu, s, o);
    float inv = 1.f / s;
    #pragma unroll
    for (int t = 0; t < 8; t++) {
        float4 o4 = make_float4(lv[t*4+0]*inv, lv[t*4+1]*inv, lv[t*4+2]*inv, lv[t*4+3]*inv);
        *reinterpret_cast<float4*>(&d_a[rowoff + t*64 + jg*4]) = o4;
    }
}

// ---------------- O = A @ V per head, 32-row tiles, scatter epilogue ----------------
__global__ void k_av() {
    __shared__ float As[2][16][36];
    __shared__ float Bs[2][16][64];
    int tid = threadIdx.x;   // 128
    int tx = tid & 15, ty = tid >> 4;
    int i0 = blockIdx.y * 32, h = blockIdx.z;
    const float* Ab = &d_a[((size_t)h*NTOK + i0)*NTOK];
    const float* Bb = &d_vJ[(size_t)h*NTOK*64];
    int ar = tid >> 2, ac = (tid & 3)*4;
    int br = tid >> 4, bc = (tid & 15)*4;

    float4 aR = *reinterpret_cast<const float4*>(&Ab[(size_t)ar*NTOK + ac]);
    float4 bR0 = *reinterpret_cast<const float4*>(&Bb[(size_t)br*64 + bc]);
    float4 bR1 = *reinterpret_cast<const float4*>(&Bb[(size_t)(br+8)*64 + bc]);
    As[0][ac+0][ar] = aR.x; As[0][ac+1][ar] = aR.y; As[0][ac+2][ar] = aR.z; As[0][ac+3][ar] = aR.w;
    *reinterpret_cast<float4*>(&Bs[0][br][bc]) = bR0;
    *reinterpret_cast<float4*>(&Bs[0][br+8][bc]) = bR1;
    __syncthreads();

    float acc[4][4] = {};
    const int KT = NTOK/16;
    for (int kt = 0; kt < KT; kt++) {
        int cur = kt & 1;
        if (kt+1 < KT) {
            aR  = *reinterpret_cast<const float4*>(&Ab[(size_t)ar*NTOK + (kt+1)*16 + ac]);
            bR0 = *reinterpret_cast<const float4*>(&Bb[(size_t)((kt+1)*16 + br)*64 + bc]);
            bR1 = *reinterpret_cast<const float4*>(&Bb[(size_t)((kt+1)*16 + br + 8)*64 + bc]);
        }
        #pragma unroll
        for (int k = 0; k < 16; k++) {
            float4 a4 = *reinterpret_cast<const float4*>(&As[cur][k][ty*4]);
            float4 b4 = *reinterpret_cast<const float4*>(&Bs[cur][k][tx*4]);
            float am[4] = {a4.x, a4.y, a4.z, a4.w};
            float bn[4] = {b4.x, b4.y, b4.z, b4.w};
            #pragma unroll
            for (int mi = 0; mi < 4; mi++)
                #pragma unroll
                for (int ni = 0; ni < 4; ni++)
                    acc[mi][ni] += am[mi]*bn[ni];
        }
        if (kt+1 < KT) {
            int nxt = cur ^ 1;
            As[nxt][ac+0][ar] = aR.x; As[nxt][ac+1][ar] = aR.y;
            As[nxt][ac+2][ar] = aR.z; As[nxt][ac+3][ar] = aR.w;
            *reinterpret_cast<float4*>(&Bs[nxt][br][bc]) = bR0;
            *reinterpret_cast<float4*>(&Bs[nxt][br+8][bc]) = bR1;
        }
        __syncthreads();
    }
    #pragma unroll
    for (int mi = 0; mi < 4; mi++) {
        int i = i0 + ty*4 + mi;
        #pragma unroll
        for (int ni = 0; ni < 4; ni++) {
            int d = tx*4 + ni;
            if (d < 16)      d_cat[(size_t)i*CAT_W + h*16 + d] = acc[mi][ni];
            else if (d < 40) d_optraw[i*288 + h*24 + (d-16)]   = acc[mi][ni];
        }
    }
}

// ---------------- o_pair: block per i, 3 heads per thread, z read once ----------------
__global__ void k_opair(const float* __restrict__ z) {
    int i = blockIdx.x;
    int tid = threadIdx.x;  // 128
    __shared__ float as[NH*NTOK];
    __shared__ float zs[32*CZD];
    float4* as4 = reinterpret_cast<float4*>(as);
    for (int l = tid; l < NH*128; l += 128) {
        int hh = l >> 7, q = l & 127;
        as4[hh*128 + q] = *reinterpret_cast<const float4*>(&d_a[((size_t)hh*NTOK + i)*NTOK + q*4]);
    }
    int lane = tid & 31, h0 = tid >> 5;
    float acc[3][4] = {};
    float4* zs4 = reinterpret_cast<float4*>(zs);
    for (int jt = 0; jt < NTOK; jt += 32) {
        __syncthreads();
        const float4* zsrc = reinterpret_cast<const float4*>(z + ((size_t)i*NTOK + jt)*CZD);
        for (int l = tid; l < 32*CZD/4; l += 128) zs4[l] = zsrc[l];
        __syncthreads();
        #pragma unroll 4
        for (int jj = 0; jj < 32; jj++) {
            float4 zv = zs4[jj*32 + lane];
            float a0 = as[(h0+0)*NTOK + jt + jj];
            float a1 = as[(h0+4)*NTOK + jt + jj];
            float a2 = as[(h0+8)*NTOK + jt + jj];
            acc[0][0] += a0*zv.x; acc[0][1] += a0*zv.y; acc[0][2] += a0*zv.z; acc[0][3] += a0*zv.w;
            acc[1][0] += a1*zv.x; acc[1][1] += a1*zv.y; acc[1][2] += a1*zv.z; acc[1][3] += a1*zv.w;
            acc[2][0] += a2*zv.x; acc[2][1] += a2*zv.y; acc[2][2] += a2*zv.z; acc[2][3] += a2*zv.w;
        }
    }
    #pragma unroll
    for (int hh = 0; hh < 3; hh++) {
        int h = h0 + hh*4;
        *reinterpret_cast<float4*>(&d_cat[(size_t)i*CAT_W + 576 + h*CZD + lane*4]) =
            make_float4(acc[hh][0], acc[hh][1], acc[hh][2], acc[hh][3]);
    }
}

// ---------------- o_pt back-transform + norm ----------------
__global__ void k_optback() {
    int i = blockIdx.x;
    int tid = threadIdx.x;  // 96
    __shared__ float Rs[9], ts[3];
    if (tid < 9) Rs[tid] = d_R[i*9 + tid];
    if (tid < 3) ts[tid] = d_t[i*3 + tid];
    __syncthreads();
    float gx = d_optraw[i*288 + tid*3 + 0] - ts[0];
    float gy = d_optraw[i*288 + tid*3 + 1] - ts[1];
    float gz = d_optraw[i*288 + tid*3 + 2] - ts[2];
    float lx = Rs[0]*gx + Rs[3]*gy + Rs[6]*gz;
    float ly = Rs[1]*gx + Rs[4]*gy + Rs[7]*gz;
    float lz = Rs[2]*gx + Rs[5]*gy + Rs[8]*gz;
    float* cr = &d_cat[(size_t)i*CAT_W];
    cr[192 + tid*3 + 0] = lx;
    cr[192 + tid*3 + 1] = ly;
    cr[192 + tid*3 + 2] = lz;
    cr[480 + tid] = sqrtf(lx*lx + ly*ly + lz*lz + 1e-8f);
}

// ---------------- s = LN(s + bias + sum_p part[p]) ----------------
__global__ void k_addln(const float* __restrict__ part, int P,
                        const float* __restrict__ bias,
                        const float* __restrict__ g, const float* __restrict__ b) {
    int i = blockIdx.x;
    int tid = threadIdx.x;  // 128
    __shared__ float red[4];
    float v[3];
    float sum = 0.f;
    #pragma unroll
    for (int k = 0; k < 3; k++) {
        int c = tid + k*128;
        float x = d_s[(size_t)i*CSD + c];
        if (bias) x += bias[c];
        for (int p = 0; p < P; p++) x += part[(size_t)p*MNS + (size_t)i*CSD + c];
        v[k] = x;
        sum += x;
    }
    #pragma unroll
    for (int o = 16; o; o >>= 1) sum += __shfl_xor_sync(0xffffffffu, sum, o);
    if ((tid & 31) == 0) red[tid >> 5] = sum;
    __syncthreads();
    float tot = red[tid & 3];
    #pragma unroll
    for (int o = 2; o; o >>= 1) tot += __shfl_xor_sync(0xffffffffu, tot, o);
    float mean = tot * (1.f/384.f);
    float var = 0.f;
    #pragma unroll
    for (int k = 0; k < 3; k++) { float d = v[k] - mean; var += d*d; }
    #pragma unroll
    for (int o = 16; o; o >>= 1) var += __shfl_xor_sync(0xffffffffu, var, o);
    __syncthreads();
    if ((tid & 31) == 0) red[tid >> 5] = var;
    __syncthreads();
    float tv = red[tid & 3];
    #pragma unroll
    for (int o = 2; o; o >>= 1) tv += __shfl_xor_sync(0xffffffffu, tv, o);
    float inv = rsqrtf(tv*(1.f/384.f) + 1e-5f);
    #pragma unroll
    for (int k = 0; k < 3; k++) {
        int c = tid + k*128;
        d_s[(size_t)i*CSD + c] = (v[k] - mean)*inv*g[c] + b[c];
    }
}

// ---------------- relu(sum of P partials) ----------------
__global__ void k_relusum(const float* __restrict__ part, int P, float* __restrict__ out) {
    int idx = blockIdx.x*blockDim.x + threadIdx.x;
    if (idx >= MNS) return;
    float x = 0.f;
    for (int p = 0; p < P; p++) x += part[(size_t)p*MNS + idx];
    out[idx] = fmaxf(x, 0.f);
}

// ---------------- backbone update ----------------
__global__ void k_backbone(const float* __restrict__ wbb, const float* __restrict__ bbb) {
    int i = blockIdx.x;
    int tid = threadIdx.x;  // 192
    int warp = tid >> 5, lane = tid & 31;
    __shared__ float upd[6];
    float acc = 0.f;
    for (int k = lane; k < CSD; k += 32) acc += d_s[(size_t)i*CSD + k]*wbb[k*6 + warp];
    #pragma unroll
    for (int o = 16; o; o >>= 1) acc += __shfl_xor_sync(0xffffffffu, acc, o);
    if (lane == 0) upd[warp] = acc + bbb[warp];
    __syncthreads();
    if (tid == 0) {
        float qb = upd[0], qc = upd[1], qd = upd[2];
        float inv = rsqrtf(1.f + qb*qb + qc*qc + qd*qd);
        float w = inv, x = qb*inv, y = qc*inv, zq = qd*inv;
        float Ru[9];
        Ru[0] = 1.f - 2.f*(y*y + zq*zq); Ru[1] = 2.f*(x*y - w*zq);        Ru[2] = 2.f*(x*zq + w*y);
        Ru[3] = 2.f*(x*y + w*zq);        Ru[4] = 1.f - 2.f*(x*x + zq*zq); Ru[5] = 2.f*(y*zq - w*x);
        Ru[6] = 2.f*(x*zq - w*y);        Ru[7] = 2.f*(y*zq + w*x);        Ru[8] = 1.f - 2.f*(x*x + y*y);
        float Ro[9];
        #pragma unroll
        for (int k = 0; k < 9; k++) Ro[k] = d_R[i*9 + k];
        float tu0 = upd[3], tu1 = upd[4], tu2 = upd[5];
        #pragma unroll
        for (int r = 0; r < 3; r++)
            d_t[i*3 + r] += Ro[r*3+0]*tu0 + Ro[r*3+1]*tu1 + Ro[r*3+2]*tu2;
        #pragma unroll
        for (int r = 0; r < 3; r++)
            #pragma unroll
            for (int c = 0; c < 3; c++)
                d_R[i*9 + r*3 + c] = Ro[r*3+0]*Ru[0*3+c] + Ro[r*3+1]*Ru[1*3+c] + Ro[r*3+2]*Ru[2*3+c];
    }
}

// ---------------- final output [s | t] ----------------
__global__ void k_out(float* __restrict__ out) {
    int idx = blockIdx.x*blockDim.x + threadIdx.x;
    if (idx >= NTOK*387) return;
    int i = idx / 387, c = idx % 387;
    out[idx] = (c < 384) ? d_s[(size_t)i*CSD + c] : d_t[i*3 + (c - 384)];
}

// ---------------- host ----------------
extern "C" void kernel_launch(void* const* d_in, const int* in_sizes, int n_in,
                              void* d_out, int out_size) {
    (void)in_sizes; (void)n_in; (void)out_size;
    const float* s     = (const float*)d_in[0];
    const float* z     = (const float*)d_in[1];
    const float* wq    = (const float*)d_in[2];
    const float* wkv   = (const float*)d_in[3];
    const float* wqp   = (const float*)d_in[4];
    const float* wkvp  = (const float*)d_in[5];
    const float* wb    = (const float*)d_in[6];
    const float* hw    = (const float*)d_in[7];
    const float* wout  = (const float*)d_in[8];
    const float* bout  = (const float*)d_in[9];
    const float* ln1g  = (const float*)d_in[10];
    const float* ln1b  = (const float*)d_in[11];
    const float* wt1   = (const float*)d_in[12];
    const float* wt2   = (const float*)d_in[13];
    const float* wt3   = (const float*)d_in[14];
    const float* ln2g  = (const float*)d_in[15];
    const float* ln2b  = (const float*)d_in[16];
    const float* wbb   = (const float*)d_in[17];
    const float* bbb   = (const float*)d_in[18];

    float *p_s, *p_Wall, *p_cat, *p_tmp, *p_tmp2, *p_part;
    float *p_WallHi, *p_WallLo, *p_woutHi, *p_woutLo, *p_wtHi, *p_wtLo;
    cudaGetSymbolAddress((void**)&p_s,      d_s);
    cudaGetSymbolAddress((void**)&p_Wall,   d_Wall);
    cudaGetSymbolAddress((void**)&p_cat,    d_cat);
    cudaGetSymbolAddress((void**)&p_tmp,    d_tmp);
    cudaGetSymbolAddress((void**)&p_tmp2,   d_tmp2);
    cudaGetSymbolAddress((void**)&p_part,   d_part);
    cudaGetSymbolAddress((void**)&p_WallHi, d_WallHi);
    cudaGetSymbolAddress((void**)&p_WallLo, d_WallLo);
    cudaGetSymbolAddress((void**)&p_woutHi, d_woutHi);
    cudaGetSymbolAddress((void**)&p_woutLo, d_woutLo);
    cudaGetSymbolAddress((void**)&p_wtHi,   d_wtHi);
    cudaGetSymbolAddress((void**)&p_wtLo,   d_wtLo);

    k_init<<<(NTOK*CSD + 255)/256, 256>>>(s);
    k_catW<<<(CSD*QKV_W + 255)/256, 256>>>(wq, wkv, wqp, wkvp);
    k_splitW<<<(CSD*QKV_W + 255)/256, 256>>>(p_Wall, p_WallHi, p_WallLo, CSD*QKV_W);
    k_splitW<<<(CAT_W*CSD + 255)/256, 256>>>(wout, p_woutHi, p_woutLo, CAT_W*CSD);
    k_splitW<<<(CSD*CSD + 255)/256, 256>>>(wt1, p_wtHi,             p_wtLo,             CSD*CSD);
    k_splitW<<<(CSD*CSD + 255)/256, 256>>>(wt2, p_wtHi + CSD*CSD,   p_wtLo + CSD*CSD,   CSD*CSD);
    k_splitW<<<(CSD*CSD + 255)/256, 256>>>(wt3, p_wtHi + 2*CSD*CSD, p_wtLo + 2*CSD*CSD, CSD*CSD);
    k_bT<<<512, 256>>>(z, wb);

    for (int it = 0; it < NBLK; it++) {
        // fused qkv/points projection: K=384 split 2 -> 288 blocks
        mm3<<<dim3(QKV_W/64, NTOK/64, 2), 256>>>(p_s, p_WallHi, p_WallLo, p_part,
                                                 NTOK, QKV_W, CSD, CSD/2);
        k_transform<<<NTOK, 128>>>(hw);
        k_lsm<<<dim3(32, NH), 256>>>();
        k_av<<<dim3(1, 16, NH), 128>>>();
        k_opair<<<NTOK, 128>>>(z);
        k_optback<<<NTOK, 96>>>();
        // out projection: K=2112 split 6 -> 288 blocks
        mm3<<<dim3(CSD/64, NTOK/64, 6), 256>>>(p_cat, p_woutHi, p_woutLo, p_part,
                                               NTOK, CSD, CAT_W, CAT_W/6);
        k_addln<<<NTOK, 128>>>(p_part, 6, bout, ln1g, ln1b);
        // transition, K=384 split 6 each -> 288 blocks
        mm3<<<dim3(CSD/64, NTOK/64, 6), 256>>>(p_s, p_wtHi, p_wtLo, p_part,
                                               NTOK, CSD, CSD, CSD/6);
        k_relusum<<<(MNS + 255)/256, 256>>>(p_part, 6, p_tmp);
        mm3<<<dim3(CSD/64, NTOK/64, 6), 256>>>(p_tmp, p_wtHi + CSD*CSD, p_wtLo + CSD*CSD, p_part,
                                               NTOK, CSD, CSD, CSD/6);
        k_relusum<<<(MNS + 255)/256, 256>>>(p_part, 6, p_tmp2);
        mm3<<<dim3(CSD/64, NTOK/64, 6), 256>>>(p_tmp2, p_wtHi + 2*CSD*CSD, p_wtLo + 2*CSD*CSD, p_part,
                                               NTOK, CSD, CSD, CSD/6);
        k_addln<<<NTOK, 128>>>(p_part, 6, nullptr, ln2g, ln2b);
        k_backbone<<<NTOK, 192>>>(wbb, bbb);
    }
    k_out<<<(NTOK*387 + 255)/256, 256>>>((float*)d_out);
}

// round 9
// speedup vs baseline: 2.2879x; 1.0048x over previous
#include <cuda_runtime.h>
#include <math.h>
#include <stdint.h>

#define NTOK 512
#define CSD 384
#define CZD 128
#define NH 12
#define PQN 4
#define PVN 8
#define NBLK 8
#define QKV_W 1152
#define CAT_W 2112
#define MNS (NTOK*CSD)
#define QOFF (NTOK*QKV_W)

#define WL 0.57735026918962576f             /* sqrt(1/3) */
#define HALFWC 0.11785113019775793f         /* 0.5*sqrt(2/(9*4)) */

// ---------------- device scratch ----------------
__device__ __align__(16) float d_s[NTOK*CSD];
__device__ __align__(16) float d_Wall[CSD*QKV_W];
__device__ __align__(16) float d_WallHi[CSD*QKV_W];
__device__ __align__(16) float d_WallLo[CSD*QKV_W];
__device__ __align__(16) float d_woutHi[CAT_W*CSD];
__device__ __align__(16) float d_woutLo[CAT_W*CSD];
__device__ __align__(16) float d_wtHi[3*CSD*CSD];
__device__ __align__(16) float d_wtLo[3*CSD*CSD];
__device__ __align__(16) float d_bT[(size_t)NH*NTOK*NTOK];   // [h][i][j], pre-scaled by wL
__device__ __align__(16) float d_a[(size_t)NH*NTOK*NTOK];    // [h][i][j] attn weights
__device__ __align__(16) float d_QfT[NH*32*NTOK];            // [h][f][i]
__device__ __align__(16) float d_KfT[NH*32*NTOK];            // [h][f][j]
__device__ __align__(16) float d_vJ[NH*NTOK*64];             // [h][j][d]
__device__ __align__(16) float d_cat[NTOK*CAT_W];
__device__ __align__(16) float d_optraw[NTOK*NH*PVN*3];
__device__ __align__(16) float d_tmp[NTOK*CSD];
__device__ __align__(16) float d_tmp2[NTOK*CSD];
__device__ __align__(16) float d_part[6*NTOK*CSD];
__device__ __align__(16) float d_R[NTOK*9];
__device__ __align__(16) float d_t[NTOK*3];

// ---------------- init ----------------
__global__ void k_init(const float* __restrict__ s_in) {
    int idx = blockIdx.x*blockDim.x + threadIdx.x;
    if (idx < NTOK*CSD) d_s[idx] = s_in[idx];
    if (idx < NTOK*9)   d_R[idx] = ((idx % 9) % 4 == 0) ? 1.f : 0.f;
    if (idx < NTOK*3)   d_t[idx] = 0.f;
}

__global__ void k_catW(const float* __restrict__ wq, const float* __restrict__ wkv,
                       const float* __restrict__ wqp, const float* __restrict__ wkvp) {
    int idx = blockIdx.x*blockDim.x + threadIdx.x;
    if (idx >= CSD*QKV_W) return;
    int k = idx / QKV_W, c = idx % QKV_W;
    float v;
    if (c < 192)      v = wq[k*192 + c];
    else if (c < 576) v = wkv[k*384 + (c-192)];
    else if (c < 720) v = wqp[k*144 + (c-576)];
    else              v = wkvp[k*432 + (c-720)];
    d_Wall[idx] = v;
}

// split fp32 into tf32 hi/lo pair
__global__ void k_splitW(const float* __restrict__ src, float* __restrict__ hi,
                         float* __restrict__ lo, int n) {
    int i = blockIdx.x*blockDim.x + threadIdx.x;
    if (i >= n) return;
    float v = src[i];
    uint32_t hb; asm("cvt.rna.tf32.f32 %0, %1;" : "=r"(hb) : "f"(v));
    float hf = __uint_as_float(hb);
    float lf = v - hf;
    uint32_t lb; asm("cvt.rna.tf32.f32 %0, %1;" : "=r"(lb) : "f"(lf));
    hi[i] = hf;
    lo[i] = __uint_as_float(lb);
}

// b = wL * (z @ w_b), once per launch, layout [h][i][j]
__global__ void k_bT(const float* __restrict__ z, const float* __restrict__ wb) {
    int gwarp = (blockIdx.x*blockDim.x + threadIdx.x) >> 5;
    int lane  = threadIdx.x & 31;
    int nwarps = (gridDim.x*blockDim.x) >> 5;
    float wreg[4][NH];
    #pragma unroll
    for (int k = 0; k < 4; k++)
        #pragma unroll
        for (int h = 0; h < NH; h++)
            wreg[k][h] = wb[(lane + 32*k)*NH + h];
    for (int row = gwarp; row < NTOK*NTOK; row += nwarps) {
        const float* zr = z + (size_t)row*CZD;
        float zv[4];
        #pragma unroll
        for (int k = 0; k < 4; k++) zv[k] = zr[lane + 32*k];
        float acc[NH];
        #pragma unroll
        for (int h = 0; h < NH; h++)
            acc[h] = zv[0]*wreg[0][h] + zv[1]*wreg[1][h] + zv[2]*wreg[2][h] + zv[3]*wreg[3][h];
        #pragma unroll
        for (int h = 0; h < NH; h++)
            #pragma unroll
            for (int o = 16; o; o >>= 1)
                acc[h] += __shfl_xor_sync(0xffffffffu, acc[h], o);
        if (lane == 0) {
            int i = row >> 9, j = row & 511;
            #pragma unroll
            for (int h = 0; h < NH; h++)
                d_bT[((size_t)h*NTOK + i)*NTOK + j] = WL * acc[h];
        }
    }
}

#define MMA_TF32(d, a, b) \
    asm volatile("mma.sync.aligned.m16n8k8.row.col.f32.tf32.tf32.f32 " \
                 "{%0,%1,%2,%3},{%4,%5,%6,%7},{%8,%9},{%0,%1,%2,%3};" \
                 : "+f"(d[0]),"+f"(d[1]),"+f"(d[2]),"+f"(d[3]) \
                 : "r"(a[0]),"r"(a[1]),"r"(a[2]),"r"(a[3]),"r"(b[0]),"r"(b[1]))

__device__ __forceinline__ void tf32split(float v, uint32_t& h, uint32_t& l) {
    uint32_t hb; asm("cvt.rna.tf32.f32 %0, %1;" : "=r"(hb) : "f"(v));
    float lf = v - __uint_as_float(hb);
    uint32_t lb; asm("cvt.rna.tf32.f32 %0, %1;" : "=r"(lb) : "f"(lf));
    h = hb; l = lb;
}

// ------- 3xTF32 tensor-core GEMM, split-K; A pre-split to hi/lo in smem -------
// 64x64 tile, 256 threads (8 warps: 2x4 warp grid, 32x16 per warp).
__global__ void mm3(const float* __restrict__ A, const float* __restrict__ Bhi,
                    const float* __restrict__ Blo, float* __restrict__ C,
                    int M, int N, int K, int Kp) {
    __shared__ float Ah[2][64][20];
    __shared__ float Al[2][64][20];
    __shared__ float Bh[2][16][72];
    __shared__ float Bl[2][16][72];
    int tid = threadIdx.x;
    int lane = tid & 31, warp = tid >> 5;
    int g = lane >> 2, tig = lane & 3;
    int wm = (warp >> 2) * 32;
    int wn = (warp & 3) * 16;
    int row0 = blockIdx.y * 64, col0 = blockIdx.x * 64;
    int kbase = blockIdx.z * Kp;
    const float* Ab  = A   + (size_t)row0*K + kbase;
    const float* Bhb = Bhi + (size_t)kbase*N + col0;
    const float* Blb = Blo + (size_t)kbase*N + col0;
    float* Cb = C + (size_t)blockIdx.z*M*N;

    int ar = tid >> 2, ac = (tid & 3)*4;
    int br = tid >> 4, bc = (tid & 15)*4;

    float4 aR = *reinterpret_cast<const float4*>(&Ab[(size_t)ar*K + ac]);
    float4 hR = *reinterpret_cast<const float4*>(&Bhb[(size_t)br*N + bc]);
    float4 lR = *reinterpret_cast<const float4*>(&Blb[(size_t)br*N + bc]);
    {
        float4 h4, l4;
        tf32split(aR.x, *(uint32_t*)&h4.x, *(uint32_t*)&l4.x);
        tf32split(aR.y, *(uint32_t*)&h4.y, *(uint32_t*)&l4.y);
        tf32split(aR.z, *(uint32_t*)&h4.z, *(uint32_t*)&l4.z);
        tf32split(aR.w, *(uint32_t*)&h4.w, *(uint32_t*)&l4.w);
        *reinterpret_cast<float4*>(&Ah[0][ar][ac]) = h4;
        *reinterpret_cast<float4*>(&Al[0][ar][ac]) = l4;
    }
    *reinterpret_cast<float4*>(&Bh[0][br][bc]) = hR;
    *reinterpret_cast<float4*>(&Bl[0][br][bc]) = lR;
    __syncthreads();

    float acc[2][2][4] = {};
    int KT = Kp >> 4;
    for (int kt = 0; kt < KT; kt++) {
        int cur = kt & 1;
        if (kt+1 < KT) {
            aR = *reinterpret_cast<const float4*>(&Ab[(size_t)ar*K + (kt+1)*16 + ac]);
            hR = *reinterpret_cast<const float4*>(&Bhb[(size_t)((kt+1)*16 + br)*N + bc]);
            lR = *reinterpret_cast<const float4*>(&Blb[(size_t)((kt+1)*16 + br)*N + bc]);
        }
        #pragma unroll
        for (int ks = 0; ks < 2; ks++) {
            int k0 = ks*8;
            uint32_t ahi[2][4], alo[2][4];
            #pragma unroll
            for (int mt = 0; mt < 2; mt++) {
                #pragma unroll
                for (int rr = 0; rr < 4; rr++) {
                    int rm = wm + mt*16 + g + (rr & 1)*8;
                    int rk = k0 + tig + (rr >> 1)*4;
                    ahi[mt][rr] = __float_as_uint(Ah[cur][rm][rk]);
                    alo[mt][rr] = __float_as_uint(Al[cur][rm][rk]);
                }
            }
            uint32_t bhf[2][2], blf[2][2];
            #pragma unroll
            for (int nt = 0; nt < 2; nt++) {
                int cn = wn + nt*8 + g;
                bhf[nt][0] = __float_as_uint(Bh[cur][k0 + tig][cn]);
                bhf[nt][1] = __float_as_uint(Bh[cur][k0 + tig + 4][cn]);
                blf[nt][0] = __float_as_uint(Bl[cur][k0 + tig][cn]);
                blf[nt][1] = __float_as_uint(Bl[cur][k0 + tig + 4][cn]);
            }
            #pragma unroll
            for (int mt = 0; mt < 2; mt++)
                #pragma unroll
                for (int nt = 0; nt < 2; nt++) {
                    MMA_TF32(acc[mt][nt], ahi[mt], bhf[nt]);
                    MMA_TF32(acc[mt][nt], ahi[mt], blf[nt]);
                    MMA_TF32(acc[mt][nt], alo[mt], bhf[nt]);
                }
        }
        if (kt+1 < KT) {
            int nxt = cur ^ 1;
            float4 h4, l4;
            tf32split(aR.x, *(uint32_t*)&h4.x, *(uint32_t*)&l4.x);
            tf32split(aR.y, *(uint32_t*)&h4.y, *(uint32_t*)&l4.y);
            tf32split(aR.z, *(uint32_t*)&h4.z, *(uint32_t*)&l4.z);
            tf32split(aR.w, *(uint32_t*)&h4.w, *(uint32_t*)&l4.w);
            *reinterpret_cast<float4*>(&Ah[nxt][ar][ac]) = h4;
            *reinterpret_cast<float4*>(&Al[nxt][ar][ac]) = l4;
            *reinterpret_cast<float4*>(&Bh[nxt][br][bc]) = hR;
            *reinterpret_cast<float4*>(&Bl[nxt][br][bc]) = lR;
        }
        __syncthreads();
    }
    #pragma unroll
    for (int mt = 0; mt < 2; mt++)
        #pragma unroll
        for (int nt = 0; nt < 2; nt++) {
            int r0 = row0 + wm + mt*16 + g;
            int c  = col0 + wn + nt*8 + 2*tig;
            *reinterpret_cast<float2*>(&Cb[(size_t)r0*N + c]) =
                make_float2(acc[mt][nt][0], acc[mt][nt][1]);
            *reinterpret_cast<float2*>(&Cb[(size_t)(r0+8)*N + c]) =
                make_float2(acc[mt][nt][2], acc[mt][nt][3]);
        }
}

// ---------------- point transform + feature build (sums 2 qkv split partials) ----------------
__global__ void k_transform(const float* __restrict__ hw) {
    int n = blockIdx.x;
    int tid = threadIdx.x;  // 128
    __shared__ float Rs[9], ts[3], sqk_s[NH], coef_s[NH];
    if (tid < 9)  Rs[tid] = d_R[n*9 + tid];
    if (tid < 3)  ts[tid] = d_t[n*3 + tid];
    if (tid < NH) {
        sqk_s[tid] = 0.f;
        float x = hw[tid];
        float g = (x > 20.f) ? x : log1pf(__expf(x));
        coef_s[tid] = g * HALFWC;
    }
    __syncthreads();
    const float* q0 = &d_part[(size_t)n*QKV_W];
    const float* q1 = &d_part[QOFF + (size_t)n*QKV_W];
    for (int l = tid; l < 192; l += 128) {
        int h = l >> 4, c = l & 15;
        d_QfT[(h*32 + c)*NTOK + n] = (q0[l] + q1[l]) * (0.25f*WL);
    }
    for (int l = tid; l < 384; l += 128) {
        int h = l >> 5, c = l & 31;
        float val = q0[192 + l] + q1[192 + l];
        if (c < 16) d_KfT[(h*32 + c)*NTOK + n] = val;
        else        d_vJ[((size_t)h*NTOK + n)*64 + (c-16)] = val;
    }
    for (int p = tid; p < 48; p += 128) {
        float x  = q0[576 + p*3 + 0] + q1[576 + p*3 + 0];
        float y  = q0[576 + p*3 + 1] + q1[576 + p*3 + 1];
        float zz = q0[576 + p*3 + 2] + q1[576 + p*3 + 2];
        float px = Rs[0]*x + Rs[1]*y + Rs[2]*zz + ts[0];
        float py = Rs[3]*x + Rs[4]*y + Rs[5]*zz + ts[1];
        float pz = Rs[6]*x + Rs[7]*y + Rs[8]*zz + ts[2];
        int h = p >> 2, pp = p & 3;
        float s2 = 2.f*WL*coef_s[h];
        d_QfT[(h*32 + 16 + pp*3 + 0)*NTOK + n] = px*s2;
        d_QfT[(h*32 + 16 + pp*3 + 1)*NTOK + n] = py*s2;
        d_QfT[(h*32 + 16 + pp*3 + 2)*NTOK + n] = pz*s2;
    }
    if (tid < NH) d_QfT[(tid*32 + 28)*NTOK + n] = 1.f;
    for (int p = tid; p < 144; p += 128) {
        float x  = q0[720 + p*3 + 0] + q1[720 + p*3 + 0];
        float y  = q0[720 + p*3 + 1] + q1[720 + p*3 + 1];
        float zz = q0[720 + p*3 + 2] + q1[720 + p*3 + 2];
        float px = Rs[0]*x + Rs[1]*y + Rs[2]*zz + ts[0];
        float py = Rs[3]*x + Rs[4]*y + Rs[5]*zz + ts[1];
        float pz = Rs[6]*x + Rs[7]*y + Rs[8]*zz + ts[2];
        int h = p / 12, pp = p % 12;
        if (pp < PQN) {
            d_KfT[(h*32 + 16 + pp*3 + 0)*NTOK + n] = px;
            d_KfT[(h*32 + 16 + pp*3 + 1)*NTOK + n] = py;
            d_KfT[(h*32 + 16 + pp*3 + 2)*NTOK + n] = pz;
            atomicAdd(&sqk_s[h], px*px + py*py + pz*pz);
        } else {
            int d = 16 + (pp - PQN)*3;
            size_t base = ((size_t)h*NTOK + n)*64 + d;
            d_vJ[base + 0] = px;
            d_vJ[base + 1] = py;
            d_vJ[base + 2] = pz;
        }
    }
    __syncthreads();
    if (tid < NH) d_KfT[(tid*32 + 28)*NTOK + n] = -WL*coef_s[tid]*sqk_s[tid];
}

// ------- fused logits + bT + softmax: block = (16 i-rows, one head), full j row -------
__global__ void k_lsm() {
    int i0 = blockIdx.x * 16, h = blockIdx.y;
    int tid = threadIdx.x;          // 256
    int iloc = tid >> 4, jg = tid & 15;
    __shared__ float Qs[32][16];
    __shared__ float Ks[32][68];
    for (int l = tid; l < 512; l += 256) {
        int f = l >> 4, il = l & 15;
        Qs[f][il] = d_QfT[(h*32 + f)*NTOK + i0 + il];
    }
    float lv[32];
    #pragma unroll
    for (int t = 0; t < 8; t++) {
        __syncthreads();
        #pragma unroll
        for (int u = 0; u < 8; u++) {
            int l = tid + u*256;
            int f = l >> 6, jl = l & 63;
            Ks[f][jl] = d_KfT[(h*32 + f)*NTOK + t*64 + jl];
        }
        __syncthreads();
        float a0 = 0.f, a1 = 0.f, a2 = 0.f, a3 = 0.f;
        #pragma unroll
        for (int f = 0; f < 32; f++) {
            float qf = Qs[f][iloc];
            float4 kv = *reinterpret_cast<const float4*>(&Ks[f][jg*4]);
            a0 += qf*kv.x; a1 += qf*kv.y; a2 += qf*kv.z; a3 += qf*kv.w;
        }
        lv[t*4+0] = a0; lv[t*4+1] = a1; lv[t*4+2] = a2; lv[t*4+3] = a3;
    }
    int i = i0 + iloc;
    size_t rowoff = ((size_t)h*NTOK + i)*NTOK;
    float m = -1e30f;
    #pragma unroll
    for (int t = 0; t < 8; t++) {
        float4 bt = *reinterpret_cast<const float4*>(&d_bT[rowoff + t*64 + jg*4]);
        lv[t*4+0] += bt.x; lv[t*4+1] += bt.y; lv[t*4+2] += bt.z; lv[t*4+3] += bt.w;
        m = fmaxf(m, fmaxf(fmaxf(lv[t*4+0], lv[t*4+1]), fmaxf(lv[t*4+2], lv[t*4+3])));
    }
    #pragma unroll
    for (int o = 8; o; o >>= 1) m = fmaxf(m, __shfl_xor_sync(0xffffffffu, m, o));
    float s = 0.f;
    #pragma unroll
    for (int q = 0; q < 32; q++) { lv[q] = __expf(lv[q] - m); s += lv[q]; }
    #pragma unroll
    for (int o = 8; o; o >>= 1) s += __shfl_xor_sync(0xffffffffu, s, o);
    float inv = 1.f / s;
    #pragma unroll
    for (int t = 0; t < 8; t++) {
        float4 o4 = make_float4(lv[t*4+0]*inv, lv[t*4+1]*inv, lv[t*4+2]*inv, lv[t*4+3]*inv);
        *reinterpret_cast<float4*>(&d_a[rowoff + t*64 + jg*4]) = o4;
    }
}

// ---------------- O = A @ V per head, 32-row tiles, scatter epilogue ----------------
__global__ void k_av() {
    __shared__ float As[2][16][36];
    __shared__ float Bs[2][16][64];
    int tid = threadIdx.x;   // 128
    int tx = tid & 15, ty = tid >> 4;
    int i0 = blockIdx.y * 32, h = blockIdx.z;
    const float* Ab = &d_a[((size_t)h*NTOK + i0)*NTOK];
    const float* Bb = &d_vJ[(size_t)h*NTOK*64];
    int ar = tid >> 2, ac = (tid & 3)*4;
    int br = tid >> 4, bc = (tid & 15)*4;

    float4 aR = *reinterpret_cast<const float4*>(&Ab[(size_t)ar*NTOK + ac]);
    float4 bR0 = *reinterpret_cast<const float4*>(&Bb[(size_t)br*64 + bc]);
    float4 bR1 = *reinterpret_cast<const float4*>(&Bb[(size_t)(br+8)*64 + bc]);
    As[0][ac+0][ar] = aR.x; As[0][ac+1][ar] = aR.y; As[0][ac+2][ar] = aR.z; As[0][ac+3][ar] = aR.w;
    *reinterpret_cast<float4*>(&Bs[0][br][bc]) = bR0;
    *reinterpret_cast<float4*>(&Bs[0][br+8][bc]) = bR1;
    __syncthreads();

    float acc[4][4] = {};
    const int KT = NTOK/16;
    for (int kt = 0; kt < KT; kt++) {
        int cur = kt & 1;
        if (kt+1 < KT) {
            aR  = *reinterpret_cast<const float4*>(&Ab[(size_t)ar*NTOK + (kt+1)*16 + ac]);
            bR0 = *reinterpret_cast<const float4*>(&Bb[(size_t)((kt+1)*16 + br)*64 + bc]);
            bR1 = *reinterpret_cast<const float4*>(&Bb[(size_t)((kt+1)*16 + br + 8)*64 + bc]);
        }
        #pragma unroll
        for (int k = 0; k < 16; k++) {
            float4 a4 = *reinterpret_cast<const float4*>(&As[cur][k][ty*4]);
            float4 b4 = *reinterpret_cast<const float4*>(&Bs[cur][k][tx*4]);
            float am[4] = {a4.x, a4.y, a4.z, a4.w};
            float bn[4] = {b4.x, b4.y, b4.z, b4.w};
            #pragma unroll
            for (int mi = 0; mi < 4; mi++)
                #pragma unroll
                for (int ni = 0; ni < 4; ni++)
                    acc[mi][ni] += am[mi]*bn[ni];
        }
        if (kt+1 < KT) {
            int nxt = cur ^ 1;
            As[nxt][ac+0][ar] = aR.x; As[nxt][ac+1][ar] = aR.y;
            As[nxt][ac+2][ar] = aR.z; As[nxt][ac+3][ar] = aR.w;
            *reinterpret_cast<float4*>(&Bs[nxt][br][bc]) = bR0;
            *reinterpret_cast<float4*>(&Bs[nxt][br+8][bc]) = bR1;
        }
        __syncthreads();
    }
    #pragma unroll
    for (int mi = 0; mi < 4; mi++) {
        int i = i0 + ty*4 + mi;
        #pragma unroll
        for (int ni = 0; ni < 4; ni++) {
            int d = tx*4 + ni;
            if (d < 16)      d_cat[(size_t)i*CAT_W + h*16 + d] = acc[mi][ni];
            else if (d < 40) d_optraw[i*288 + h*24 + (d-16)]   = acc[mi][ni];
        }
    }
}

// ------- o_pair (+fused o_pt back-transform): block per i, 3 heads/thread -------
__global__ void k_opair(const float* __restrict__ z) {
    int i = blockIdx.x;
    int tid = threadIdx.x;  // 128
    __shared__ float as[NH*NTOK];
    __shared__ float zs[32*CZD];
    __shared__ float Rs[9], ts[3];
    if (tid < 9) Rs[tid] = d_R[i*9 + tid];
    if (tid >= 16 && tid < 19) ts[tid-16] = d_t[i*3 + (tid-16)];
    float4* as4 = reinterpret_cast<float4*>(as);
    for (int l = tid; l < NH*128; l += 128) {
        int hh = l >> 7, q = l & 127;
        as4[hh*128 + q] = *reinterpret_cast<const float4*>(&d_a[((size_t)hh*NTOK + i)*NTOK + q*4]);
    }
    int lane = tid & 31, h0 = tid >> 5;
    float acc[3][4] = {};
    float4* zs4 = reinterpret_cast<float4*>(zs);
    for (int jt = 0; jt < NTOK; jt += 32) {
        __syncthreads();
        const float4* zsrc = reinterpret_cast<const float4*>(z + ((size_t)i*NTOK + jt)*CZD);
        for (int l = tid; l < 32*CZD/4; l += 128) zs4[l] = zsrc[l];
        __syncthreads();
        #pragma unroll 4
        for (int jj = 0; jj < 32; jj++) {
            float4 zv = zs4[jj*32 + lane];
            float a0 = as[(h0+0)*NTOK + jt + jj];
            float a1 = as[(h0+4)*NTOK + jt + jj];
            float a2 = as[(h0+8)*NTOK + jt + jj];
            acc[0][0] += a0*zv.x; acc[0][1] += a0*zv.y; acc[0][2] += a0*zv.z; acc[0][3] += a0*zv.w;
            acc[1][0] += a1*zv.x; acc[1][1] += a1*zv.y; acc[1][2] += a1*zv.z; acc[1][3] += a1*zv.w;
            acc[2][0] += a2*zv.x; acc[2][1] += a2*zv.y; acc[2][2] += a2*zv.z; acc[2][3] += a2*zv.w;
        }
    }
    #pragma unroll
    for (int hh = 0; hh < 3; hh++) {
        int h = h0 + hh*4;
        *reinterpret_cast<float4*>(&d_cat[(size_t)i*CAT_W + 576 + h*CZD + lane*4]) =
            make_float4(acc[hh][0], acc[hh][1], acc[hh][2], acc[hh][3]);
    }
    // fused o_pt back-transform + norm (was k_optback)
    __syncthreads();
    if (tid < 96) {
        float gx = d_optraw[i*288 + tid*3 + 0] - ts[0];
        float gy = d_optraw[i*288 + tid*3 + 1] - ts[1];
        float gz = d_optraw[i*288 + tid*3 + 2] - ts[2];
        float lx = Rs[0]*gx + Rs[3]*gy + Rs[6]*gz;
        float ly = Rs[1]*gx + Rs[4]*gy + Rs[7]*gz;
        float lz = Rs[2]*gx + Rs[5]*gy + Rs[8]*gz;
        float* cr = &d_cat[(size_t)i*CAT_W];
        cr[192 + tid*3 + 0] = lx;
        cr[192 + tid*3 + 1] = ly;
        cr[192 + tid*3 + 2] = lz;
        cr[480 + tid] = sqrtf(lx*lx + ly*ly + lz*lz + 1e-8f);
    }
}

// ---------------- s = LN(s + bias + sum_p part[p]) ----------------
__global__ void k_addln(const float* __restrict__ part, int P,
                        const float* __restrict__ bias,
                        const float* __restrict__ g, const float* __restrict__ b) {
    int i = blockIdx.x;
    int tid = threadIdx.x;  // 128
    __shared__ float red[4];
    float v[3];
    float sum = 0.f;
    #pragma unroll
    for (int k = 0; k < 3; k++) {
        int c = tid + k*128;
        float x = d_s[(size_t)i*CSD + c];
        if (bias) x += bias[c];
        for (int p = 0; p < P; p++) x += part[(size_t)p*MNS + (size_t)i*CSD + c];
        v[k] = x;
        sum += x;
    }
    #pragma unroll
    for (int o = 16; o; o >>= 1) sum += __shfl_xor_sync(0xffffffffu, sum, o);
    if ((tid & 31) == 0) red[tid >> 5] = sum;
    __syncthreads();
    float tot = red[tid & 3];
    #pragma unroll
    for (int o = 2; o; o >>= 1) tot += __shfl_xor_sync(0xffffffffu, tot, o);
    float mean = tot * (1.f/384.f);
    float var = 0.f;
    #pragma unroll
    for (int k = 0; k < 3; k++) { float d = v[k] - mean; var += d*d; }
    #pragma unroll
    for (int o = 16; o; o >>= 1) var += __shfl_xor_sync(0xffffffffu, var, o);
    __syncthreads();
    if ((tid & 31) == 0) red[tid >> 5] = var;
    __syncthreads();
    float tv = red[tid & 3];
    #pragma unroll
    for (int o = 2; o; o >>= 1) tv += __shfl_xor_sync(0xffffffffu, tv, o);
    float inv = rsqrtf(tv*(1.f/384.f) + 1e-5f);
    #pragma unroll
    for (int k = 0; k < 3; k++) {
        int c = tid + k*128;
        d_s[(size_t)i*CSD + c] = (v[k] - mean)*inv*g[c] + b[c];
    }
}

// ------- ln2 + fused backbone update: LN then quaternion/R/t, one block per i -------
__global__ void k_addln_bb(const float* __restrict__ part, int P,
                           const float* __restrict__ g, const float* __restrict__ b,
                           const float* __restrict__ wbb, const float* __restrict__ bbb) {
    int i = blockIdx.x;
    int tid = threadIdx.x;  // 128
    __shared__ float red[4];
    __shared__ float red6[4][6];
    __shared__ float upd[6];
    float v[3];
    float sum = 0.f;
    #pragma unroll
    for (int k = 0; k < 3; k++) {
        int c = tid + k*128;
        float x = d_s[(size_t)i*CSD + c];
        for (int p = 0; p < P; p++) x += part[(size_t)p*MNS + (size_t)i*CSD + c];
        v[k] = x;
        sum += x;
    }
    #pragma unroll
    for (int o = 16; o; o >>= 1) sum += __shfl_xor_sync(0xffffffffu, sum, o);
    if ((tid & 31) == 0) red[tid >> 5] = sum;
    __syncthreads();
    float tot = red[tid & 3];
    #pragma unroll
    for (int o = 2; o; o >>= 1) tot += __shfl_xor_sync(0xffffffffu, tot, o);
    float mean = tot * (1.f/384.f);
    float var = 0.f;
    #pragma unroll
    for (int k = 0; k < 3; k++) { float d = v[k] - mean; var += d*d; }
    #pragma unroll
    for (int o = 16; o; o >>= 1) var += __shfl_xor_sync(0xffffffffu, var, o);
    __syncthreads();
    if ((tid & 31) == 0) red[tid >> 5] = var;
    __syncthreads();
    float tv = red[tid & 3];
    #pragma unroll
    for (int o = 2; o; o >>= 1) tv += __shfl_xor_sync(0xffffffffu, tv, o);
    float inv = rsqrtf(tv*(1.f/384.f) + 1e-5f);
    float sv[3];
    #pragma unroll
    for (int k = 0; k < 3; k++) {
        int c = tid + k*128;
        sv[k] = (v[k] - mean)*inv*g[c] + b[c];
        d_s[(size_t)i*CSD + c] = sv[k];
    }
    // backbone: upd = s @ wbb + bbb (6 outputs)
    float a6[6];
    #pragma unroll
    for (int o = 0; o < 6; o++) {
        a6[o] = sv[0]*wbb[(tid      )*6 + o]
              + sv[1]*wbb[(tid + 128)*6 + o]
              + sv[2]*wbb[(tid + 256)*6 + o];
    }
    #pragma unroll
    for (int o = 0; o < 6; o++)
        #pragma unroll
        for (int off = 16; off; off >>= 1)
            a6[o] += __shfl_xor_sync(0xffffffffu, a6[o], off);
    if ((tid & 31) == 0) {
        #pragma unroll
        for (int o = 0; o < 6; o++) red6[tid >> 5][o] = a6[o];
    }
    __syncthreads();
    if (tid < 6) upd[tid] = red6[0][tid] + red6[1][tid] + red6[2][tid] + red6[3][tid] + bbb[tid];
    __syncthreads();
    if (tid == 0) {
        float qb = upd[0], qc = upd[1], qd = upd[2];
        float qi = rsqrtf(1.f + qb*qb + qc*qc + qd*qd);
        float w = qi, x = qb*qi, y = qc*qi, zq = qd*qi;
        float Ru[9];
        Ru[0] = 1.f - 2.f*(y*y + zq*zq); Ru[1] = 2.f*(x*y - w*zq);        Ru[2] = 2.f*(x*zq + w*y);
        Ru[3] = 2.f*(x*y + w*zq);        Ru[4] = 1.f - 2.f*(x*x + zq*zq); Ru[5] = 2.f*(y*zq - w*x);
        Ru[6] = 2.f*(x*zq - w*y);        Ru[7] = 2.f*(y*zq + w*x);        Ru[8] = 1.f - 2.f*(x*x + y*y);
        float Ro[9];
        #pragma unroll
        for (int k = 0; k < 9; k++) Ro[k] = d_R[i*9 + k];
        float tu0 = upd[3], tu1 = upd[4], tu2 = upd[5];
        #pragma unroll
        for (int r = 0; r < 3; r++)
            d_t[i*3 + r] += Ro[r*3+0]*tu0 + Ro[r*3+1]*tu1 + Ro[r*3+2]*tu2;
        #pragma unroll
        for (int r = 0; r < 3; r++)
            #pragma unroll
            for (int c = 0; c < 3; c++)
                d_R[i*9 + r*3 + c] = Ro[r*3+0]*Ru[0*3+c] + Ro[r*3+1]*Ru[1*3+c] + Ro[r*3+2]*Ru[2*3+c];
    }
}

// ---------------- relu(sum of P partials) ----------------
__global__ void k_relusum(const float* __restrict__ part, int P, float* __restrict__ out) {
    int idx = blockIdx.x*blockDim.x + threadIdx.x;
    if (idx >= MNS) return;
    float x = 0.f;
    for (int p = 0; p < P; p++) x += part[(size_t)p*MNS + idx];
    out[idx] = fmaxf(x, 0.f);
}

// ---------------- final output [s | t] ----------------
__global__ void k_out(float* __restrict__ out) {
    int idx = blockIdx.x*blockDim.x + threadIdx.x;
    if (idx >= NTOK*387) return;
    int i = idx / 387, c = idx % 387;
    out[idx] = (c < 384) ? d_s[(size_t)i*CSD + c] : d_t[i*3 + (c - 384)];
}

// ---------------- host ----------------
extern "C" void kernel_launch(void* const* d_in, const int* in_sizes, int n_in,
                              void* d_out, int out_size) {
    (void)in_sizes; (void)n_in; (void)out_size;
    const float* s     = (const float*)d_in[0];
    const float* z     = (const float*)d_in[1];
    const float* wq    = (const float*)d_in[2];
    const float* wkv   = (const float*)d_in[3];
    const float* wqp   = (const float*)d_in[4];
    const float* wkvp  = (const float*)d_in[5];
    const float* wb    = (const float*)d_in[6];
    const float* hw    = (const float*)d_in[7];
    const float* wout  = (const float*)d_in[8];
    const float* bout  = (const float*)d_in[9];
    const float* ln1g  = (const float*)d_in[10];
    const float* ln1b  = (const float*)d_in[11];
    const float* wt1   = (const float*)d_in[12];
    const float* wt2   = (const float*)d_in[13];
    const float* wt3   = (const float*)d_in[14];
    const float* ln2g  = (const float*)d_in[15];
    const float* ln2b  = (const float*)d_in[16];
    const float* wbb   = (const float*)d_in[17];
    const float* bbb   = (const float*)d_in[18];

    float *p_s, *p_Wall, *p_cat, *p_tmp, *p_tmp2, *p_part;
    float *p_WallHi, *p_WallLo, *p_woutHi, *p_woutLo, *p_wtHi, *p_wtLo;
    cudaGetSymbolAddress((void**)&p_s,      d_s);
    cudaGetSymbolAddress((void**)&p_Wall,   d_Wall);
    cudaGetSymbolAddress((void**)&p_cat,    d_cat);
    cudaGetSymbolAddress((void**)&p_tmp,    d_tmp);
    cudaGetSymbolAddress((void**)&p_tmp2,   d_tmp2);
    cudaGetSymbolAddress((void**)&p_part,   d_part);
    cudaGetSymbolAddress((void**)&p_WallHi, d_WallHi);
    cudaGetSymbolAddress((void**)&p_WallLo, d_WallLo);
    cudaGetSymbolAddress((void**)&p_woutHi, d_woutHi);
    cudaGetSymbolAddress((void**)&p_woutLo, d_woutLo);
    cudaGetSymbolAddress((void**)&p_wtHi,   d_wtHi);
    cudaGetSymbolAddress((void**)&p_wtLo,   d_wtLo);

    k_init<<<(NTOK*CSD + 255)/256, 256>>>(s);
    k_catW<<<(CSD*QKV_W + 255)/256, 256>>>(wq, wkv, wqp, wkvp);
    k_splitW<<<(CSD*QKV_W + 255)/256, 256>>>(p_Wall, p_WallHi, p_WallLo, CSD*QKV_W);
    k_splitW<<<(CAT_W*CSD + 255)/256, 256>>>(wout, p_woutHi, p_woutLo, CAT_W*CSD);
    k_splitW<<<(CSD*CSD + 255)/256, 256>>>(wt1, p_wtHi,             p_wtLo,             CSD*CSD);
    k_splitW<<<(CSD*CSD + 255)/256, 256>>>(wt2, p_wtHi + CSD*CSD,   p_wtLo + CSD*CSD,   CSD*CSD);
    k_splitW<<<(CSD*CSD + 255)/256, 256>>>(wt3, p_wtHi + 2*CSD*CSD, p_wtLo + 2*CSD*CSD, CSD*CSD);
    k_bT<<<512, 256>>>(z, wb);

    for (int it = 0; it < NBLK; it++) {
        // fused qkv/points projection: K=384 split 2 -> 288 blocks
        mm3<<<dim3(QKV_W/64, NTOK/64, 2), 256>>>(p_s, p_WallHi, p_WallLo, p_part,
                                                 NTOK, QKV_W, CSD, CSD/2);
        k_transform<<<NTOK, 128>>>(hw);
        k_lsm<<<dim3(32, NH), 256>>>();
        k_av<<<dim3(1, 16, NH), 128>>>();
        k_opair<<<NTOK, 128>>>(z);           // includes o_pt back-transform
        // out projection: K=2112 split 6 -> 288 blocks
        mm3<<<dim3(CSD/64, NTOK/64, 6), 256>>>(p_cat, p_woutHi, p_woutLo, p_part,
                                               NTOK, CSD, CAT_W, CAT_W/6);
        k_addln<<<NTOK, 128>>>(p_part, 6, bout, ln1g, ln1b);
        // transition, K=384 split 3 each -> 144 blocks
        mm3<<<dim3(CSD/64, NTOK/64, 3), 256>>>(p_s, p_wtHi, p_wtLo, p_part,
                                               NTOK, CSD, CSD, CSD/3);
        k_relusum<<<(MNS + 255)/256, 256>>>(p_part, 3, p_tmp);
        mm3<<<dim3(CSD/64, NTOK/64, 3), 256>>>(p_tmp, p_wtHi + CSD*CSD, p_wtLo + CSD*CSD, p_part,
                                               NTOK, CSD, CSD, CSD/3);
        k_relusum<<<(MNS + 255)/256, 256>>>(p_part, 3, p_tmp2);
        mm3<<<dim3(CSD/64, NTOK/64, 3), 256>>>(p_tmp2, p_wtHi + 2*CSD*CSD, p_wtLo + 2*CSD*CSD, p_part,
                                               NTOK, CSD, CSD, CSD/3);
        k_addln_bb<<<NTOK, 128>>>(p_part, 3, ln2g, ln2b, wbb, bbb);  // ln2 + backbone
    }
    k_out<<<(NTOK*387 + 255)/256, 256>>>((float*)d_out);
}

// round 10
// speedup vs baseline: 2.3168x; 1.0126x over previous
#include <cuda_runtime.h>
#include <math.h>
#include <stdint.h>

#define NTOK 512
#define CSD 384
#define CZD 128
#define NH 12
#define PQN 4
#define PVN 8
#define NBLK 8
#define QKV_W 1152
#define CAT_W 2112
#define MNS (NTOK*CSD)
#define QOFF (NTOK*QKV_W)

#define WL 0.57735026918962576f             /* sqrt(1/3) */
#define HALFWC 0.11785113019775793f         /* 0.5*sqrt(2/(9*4)) */

// ---------------- device scratch ----------------
__device__ __align__(16) float d_s[NTOK*CSD];
__device__ __align__(16) float d_Wall[CSD*QKV_W];
__device__ __align__(16) float d_WallHi[CSD*QKV_W];
__device__ __align__(16) float d_WallLo[CSD*QKV_W];
__device__ __align__(16) float d_woutHi[CAT_W*CSD];
__device__ __align__(16) float d_woutLo[CAT_W*CSD];
__device__ __align__(16) float d_wtHi[3*CSD*CSD];
__device__ __align__(16) float d_wtLo[3*CSD*CSD];
__device__ __align__(16) float d_bT[(size_t)NH*NTOK*NTOK];   // [h][i][j], pre-scaled by wL
__device__ __align__(16) float d_a[(size_t)NH*NTOK*NTOK];    // [h][i][j] attn weights
__device__ __align__(16) float d_QfT[NH*32*NTOK];            // [h][f][i]
__device__ __align__(16) float d_KfT[NH*32*NTOK];            // [h][f][j]
__device__ __align__(16) float d_vJ[NH*NTOK*64];             // [h][j][d]
__device__ __align__(16) float d_cat[NTOK*CAT_W];
__device__ __align__(16) float d_tmp[NTOK*CSD];
__device__ __align__(16) float d_tmp2[NTOK*CSD];
__device__ __align__(16) float d_part[6*NTOK*CSD];
__device__ __align__(16) float d_R[NTOK*9];
__device__ __align__(16) float d_t[NTOK*3];

// ---------------- init ----------------
__global__ void k_init(const float* __restrict__ s_in) {
    int idx = blockIdx.x*blockDim.x + threadIdx.x;
    if (idx < NTOK*CSD) d_s[idx] = s_in[idx];
    if (idx < NTOK*9)   d_R[idx] = ((idx % 9) % 4 == 0) ? 1.f : 0.f;
    if (idx < NTOK*3)   d_t[idx] = 0.f;
}

__global__ void k_catW(const float* __restrict__ wq, const float* __restrict__ wkv,
                       const float* __restrict__ wqp, const float* __restrict__ wkvp) {
    int idx = blockIdx.x*blockDim.x + threadIdx.x;
    if (idx >= CSD*QKV_W) return;
    int k = idx / QKV_W, c = idx % QKV_W;
    float v;
    if (c < 192)      v = wq[k*192 + c];
    else if (c < 576) v = wkv[k*384 + (c-192)];
    else if (c < 720) v = wqp[k*144 + (c-576)];
    else              v = wkvp[k*432 + (c-720)];
    d_Wall[idx] = v;
}

// split fp32 into tf32 hi/lo pair
__global__ void k_splitW(const float* __restrict__ src, float* __restrict__ hi,
                         float* __restrict__ lo, int n) {
    int i = blockIdx.x*blockDim.x + threadIdx.x;
    if (i >= n) return;
    float v = src[i];
    uint32_t hb; asm("cvt.rna.tf32.f32 %0, %1;" : "=r"(hb) : "f"(v));
    float hf = __uint_as_float(hb);
    float lf = v - hf;
    uint32_t lb; asm("cvt.rna.tf32.f32 %0, %1;" : "=r"(lb) : "f"(lf));
    hi[i] = hf;
    lo[i] = __uint_as_float(lb);
}

// b = wL * (z @ w_b), once per launch, layout [h][i][j]
__global__ void k_bT(const float* __restrict__ z, const float* __restrict__ wb) {
    int gwarp = (blockIdx.x*blockDim.x + threadIdx.x) >> 5;
    int lane  = threadIdx.x & 31;
    int nwarps = (gridDim.x*blockDim.x) >> 5;
    float wreg[4][NH];
    #pragma unroll
    for (int k = 0; k < 4; k++)
        #pragma unroll
        for (int h = 0; h < NH; h++)
            wreg[k][h] = wb[(lane + 32*k)*NH + h];
    for (int row = gwarp; row < NTOK*NTOK; row += nwarps) {
        const float* zr = z + (size_t)row*CZD;
        float zv[4];
        #pragma unroll
        for (int k = 0; k < 4; k++) zv[k] = zr[lane + 32*k];
        float acc[NH];
        #pragma unroll
        for (int h = 0; h < NH; h++)
            acc[h] = zv[0]*wreg[0][h] + zv[1]*wreg[1][h] + zv[2]*wreg[2][h] + zv[3]*wreg[3][h];
        #pragma unroll
        for (int h = 0; h < NH; h++)
            #pragma unroll
            for (int o = 16; o; o >>= 1)
                acc[h] += __shfl_xor_sync(0xffffffffu, acc[h], o);
        if (lane == 0) {
            int i = row >> 9, j = row & 511;
            #pragma unroll
            for (int h = 0; h < NH; h++)
                d_bT[((size_t)h*NTOK + i)*NTOK + j] = WL * acc[h];
        }
    }
}

#define MMA_TF32(d, a, b) \
    asm volatile("mma.sync.aligned.m16n8k8.row.col.f32.tf32.tf32.f32 " \
                 "{%0,%1,%2,%3},{%4,%5,%6,%7},{%8,%9},{%0,%1,%2,%3};" \
                 : "+f"(d[0]),"+f"(d[1]),"+f"(d[2]),"+f"(d[3]) \
                 : "r"(a[0]),"r"(a[1]),"r"(a[2]),"r"(a[3]),"r"(b[0]),"r"(b[1]))

__device__ __forceinline__ void tf32split(float v, uint32_t& h, uint32_t& l) {
    uint32_t hb; asm("cvt.rna.tf32.f32 %0, %1;" : "=r"(hb) : "f"(v));
    float lf = v - __uint_as_float(hb);
    uint32_t lb; asm("cvt.rna.tf32.f32 %0, %1;" : "=r"(lb) : "f"(lf));
    h = hb; l = lb;
}

// ------- 3xTF32 tensor-core GEMM, split-K; A pre-split to hi/lo in smem -------
__global__ void mm3(const float* __restrict__ A, const float* __restrict__ Bhi,
                    const float* __restrict__ Blo, float* __restrict__ C,
                    int M, int N, int K, int Kp) {
    __shared__ float Ah[2][64][20];
    __shared__ float Al[2][64][20];
    __shared__ float Bh[2][16][72];
    __shared__ float Bl[2][16][72];
    int tid = threadIdx.x;
    int lane = tid & 31, warp = tid >> 5;
    int g = lane >> 2, tig = lane & 3;
    int wm = (warp >> 2) * 32;
    int wn = (warp & 3) * 16;
    int row0 = blockIdx.y * 64, col0 = blockIdx.x * 64;
    int kbase = blockIdx.z * Kp;
    const float* Ab  = A   + (size_t)row0*K + kbase;
    const float* Bhb = Bhi + (size_t)kbase*N + col0;
    const float* Blb = Blo + (size_t)kbase*N + col0;
    float* Cb = C + (size_t)blockIdx.z*M*N;

    int ar = tid >> 2, ac = (tid & 3)*4;
    int br = tid >> 4, bc = (tid & 15)*4;

    float4 aR = *reinterpret_cast<const float4*>(&Ab[(size_t)ar*K + ac]);
    float4 hR = *reinterpret_cast<const float4*>(&Bhb[(size_t)br*N + bc]);
    float4 lR = *reinterpret_cast<const float4*>(&Blb[(size_t)br*N + bc]);
    {
        float4 h4, l4;
        tf32split(aR.x, *(uint32_t*)&h4.x, *(uint32_t*)&l4.x);
        tf32split(aR.y, *(uint32_t*)&h4.y, *(uint32_t*)&l4.y);
        tf32split(aR.z, *(uint32_t*)&h4.z, *(uint32_t*)&l4.z);
        tf32split(aR.w, *(uint32_t*)&h4.w, *(uint32_t*)&l4.w);
        *reinterpret_cast<float4*>(&Ah[0][ar][ac]) = h4;
        *reinterpret_cast<float4*>(&Al[0][ar][ac]) = l4;
    }
    *reinterpret_cast<float4*>(&Bh[0][br][bc]) = hR;
    *reinterpret_cast<float4*>(&Bl[0][br][bc]) = lR;
    __syncthreads();

    float acc[2][2][4] = {};
    int KT = Kp >> 4;
    for (int kt = 0; kt < KT; kt++) {
        int cur = kt & 1;
        if (kt+1 < KT) {
            aR = *reinterpret_cast<const float4*>(&Ab[(size_t)ar*K + (kt+1)*16 + ac]);
            hR = *reinterpret_cast<const float4*>(&Bhb[(size_t)((kt+1)*16 + br)*N + bc]);
            lR = *reinterpret_cast<const float4*>(&Blb[(size_t)((kt+1)*16 + br)*N + bc]);
        }
        #pragma unroll
        for (int ks = 0; ks < 2; ks++) {
            int k0 = ks*8;
            uint32_t ahi[2][4], alo[2][4];
            #pragma unroll
            for (int mt = 0; mt < 2; mt++) {
                #pragma unroll
                for (int rr = 0; rr < 4; rr++) {
                    int rm = wm + mt*16 + g + (rr & 1)*8;
                    int rk = k0 + tig + (rr >> 1)*4;
                    ahi[mt][rr] = __float_as_uint(Ah[cur][rm][rk]);
                    alo[mt][rr] = __float_as_uint(Al[cur][rm][rk]);
                }
            }
            uint32_t bhf[2][2], blf[2][2];
            #pragma unroll
            for (int nt = 0; nt < 2; nt++) {
                int cn = wn + nt*8 + g;
                bhf[nt][0] = __float_as_uint(Bh[cur][k0 + tig][cn]);
                bhf[nt][1] = __float_as_uint(Bh[cur][k0 + tig + 4][cn]);
                blf[nt][0] = __float_as_uint(Bl[cur][k0 + tig][cn]);
                blf[nt][1] = __float_as_uint(Bl[cur][k0 + tig + 4][cn]);
            }
            #pragma unroll
            for (int mt = 0; mt < 2; mt++)
                #pragma unroll
                for (int nt = 0; nt < 2; nt++) {
                    MMA_TF32(acc[mt][nt], ahi[mt], bhf[nt]);
                    MMA_TF32(acc[mt][nt], ahi[mt], blf[nt]);
                    MMA_TF32(acc[mt][nt], alo[mt], bhf[nt]);
                }
        }
        if (kt+1 < KT) {
            int nxt = cur ^ 1;
            float4 h4, l4;
            tf32split(aR.x, *(uint32_t*)&h4.x, *(uint32_t*)&l4.x);
            tf32split(aR.y, *(uint32_t*)&h4.y, *(uint32_t*)&l4.y);
            tf32split(aR.z, *(uint32_t*)&h4.z, *(uint32_t*)&l4.z);
            tf32split(aR.w, *(uint32_t*)&h4.w, *(uint32_t*)&l4.w);
            *reinterpret_cast<float4*>(&Ah[nxt][ar][ac]) = h4;
            *reinterpret_cast<float4*>(&Al[nxt][ar][ac]) = l4;
            *reinterpret_cast<float4*>(&Bh[nxt][br][bc]) = hR;
            *reinterpret_cast<float4*>(&Bl[nxt][br][bc]) = lR;
        }
        __syncthreads();
    }
    #pragma unroll
    for (int mt = 0; mt < 2; mt++)
        #pragma unroll
        for (int nt = 0; nt < 2; nt++) {
            int r0 = row0 + wm + mt*16 + g;
            int c  = col0 + wn + nt*8 + 2*tig;
            *reinterpret_cast<float2*>(&Cb[(size_t)r0*N + c]) =
                make_float2(acc[mt][nt][0], acc[mt][nt][1]);
            *reinterpret_cast<float2*>(&Cb[(size_t)(r0+8)*N + c]) =
                make_float2(acc[mt][nt][2], acc[mt][nt][3]);
        }
}

// ---------------- point transform + feature build (sums 2 qkv split partials) ----------------
__global__ void k_transform(const float* __restrict__ hw) {
    int n = blockIdx.x;
    int tid = threadIdx.x;  // 128
    __shared__ float Rs[9], ts[3], sqk_s[NH], coef_s[NH];
    if (tid < 9)  Rs[tid] = d_R[n*9 + tid];
    if (tid < 3)  ts[tid] = d_t[n*3 + tid];
    if (tid < NH) {
        sqk_s[tid] = 0.f;
        float x = hw[tid];
        float g = (x > 20.f) ? x : log1pf(__expf(x));
        coef_s[tid] = g * HALFWC;
    }
    __syncthreads();
    const float* q0 = &d_part[(size_t)n*QKV_W];
    const float* q1 = &d_part[QOFF + (size_t)n*QKV_W];
    for (int l = tid; l < 192; l += 128) {
        int h = l >> 4, c = l & 15;
        d_QfT[(h*32 + c)*NTOK + n] = (q0[l] + q1[l]) * (0.25f*WL);
    }
    for (int l = tid; l < 384; l += 128) {
        int h = l >> 5, c = l & 31;
        float val = q0[192 + l] + q1[192 + l];
        if (c < 16) d_KfT[(h*32 + c)*NTOK + n] = val;
        else        d_vJ[((size_t)h*NTOK + n)*64 + (c-16)] = val;
    }
    for (int p = tid; p < 48; p += 128) {
        float x  = q0[576 + p*3 + 0] + q1[576 + p*3 + 0];
        float y  = q0[576 + p*3 + 1] + q1[576 + p*3 + 1];
        float zz = q0[576 + p*3 + 2] + q1[576 + p*3 + 2];
        float px = Rs[0]*x + Rs[1]*y + Rs[2]*zz + ts[0];
        float py = Rs[3]*x + Rs[4]*y + Rs[5]*zz + ts[1];
        float pz = Rs[6]*x + Rs[7]*y + Rs[8]*zz + ts[2];
        int h = p >> 2, pp = p & 3;
        float s2 = 2.f*WL*coef_s[h];
        d_QfT[(h*32 + 16 + pp*3 + 0)*NTOK + n] = px*s2;
        d_QfT[(h*32 + 16 + pp*3 + 1)*NTOK + n] = py*s2;
        d_QfT[(h*32 + 16 + pp*3 + 2)*NTOK + n] = pz*s2;
    }
    if (tid < NH) d_QfT[(tid*32 + 28)*NTOK + n] = 1.f;
    for (int p = tid; p < 144; p += 128) {
        float x  = q0[720 + p*3 + 0] + q1[720 + p*3 + 0];
        float y  = q0[720 + p*3 + 1] + q1[720 + p*3 + 1];
        float zz = q0[720 + p*3 + 2] + q1[720 + p*3 + 2];
        float px = Rs[0]*x + Rs[1]*y + Rs[2]*zz + ts[0];
        float py = Rs[3]*x + Rs[4]*y + Rs[5]*zz + ts[1];
        float pz = Rs[6]*x + Rs[7]*y + Rs[8]*zz + ts[2];
        int h = p / 12, pp = p % 12;
        if (pp < PQN) {
            d_KfT[(h*32 + 16 + pp*3 + 0)*NTOK + n] = px;
            d_KfT[(h*32 + 16 + pp*3 + 1)*NTOK + n] = py;
            d_KfT[(h*32 + 16 + pp*3 + 2)*NTOK + n] = pz;
            atomicAdd(&sqk_s[h], px*px + py*py + pz*pz);
        } else {
            int d = 16 + (pp - PQN)*3;
            size_t base = ((size_t)h*NTOK + n)*64 + d;
            d_vJ[base + 0] = px;
            d_vJ[base + 1] = py;
            d_vJ[base + 2] = pz;
        }
    }
    __syncthreads();
    if (tid < NH) d_KfT[(tid*32 + 28)*NTOK + n] = -WL*coef_s[tid]*sqk_s[tid];
}

// ------- fused logits + bT + softmax, double-buffered K tiles -------
__global__ void k_lsm() {
    int i0 = blockIdx.x * 16, h = blockIdx.y;
    int tid = threadIdx.x;          // 256
    int iloc = tid >> 4, jg = tid & 15;
    __shared__ float Qs[32][16];
    __shared__ float Ks[2][32][68];
    for (int l = tid; l < 512; l += 256) {
        int f = l >> 4, il = l & 15;
        Qs[f][il] = d_QfT[(h*32 + f)*NTOK + i0 + il];
    }
    int lf[8], lj[8];
    #pragma unroll
    for (int u = 0; u < 8; u++) {
        int l = tid + u*256;
        lf[u] = l >> 6; lj[u] = l & 63;
    }
    #pragma unroll
    for (int u = 0; u < 8; u++)
        Ks[0][lf[u]][lj[u]] = d_KfT[(h*32 + lf[u])*NTOK + lj[u]];
    __syncthreads();
    float lv[32];
    #pragma unroll
    for (int t = 0; t < 8; t++) {
        float kr[8];
        if (t < 7) {
            #pragma unroll
            for (int u = 0; u < 8; u++)
                kr[u] = d_KfT[(h*32 + lf[u])*NTOK + (t+1)*64 + lj[u]];
        }
        int cur = t & 1;
        float a0 = 0.f, a1 = 0.f, a2 = 0.f, a3 = 0.f;
        #pragma unroll
        for (int f = 0; f < 32; f++) {
            float qf = Qs[f][iloc];
            float4 kv = *reinterpret_cast<const float4*>(&Ks[cur][f][jg*4]);
            a0 += qf*kv.x; a1 += qf*kv.y; a2 += qf*kv.z; a3 += qf*kv.w;
        }
        lv[t*4+0] = a0; lv[t*4+1] = a1; lv[t*4+2] = a2; lv[t*4+3] = a3;
        if (t < 7) {
            #pragma unroll
            for (int u = 0; u < 8; u++)
                Ks[cur ^ 1][lf[u]][lj[u]] = kr[u];
        }
        __syncthreads();
    }
    int i = i0 + iloc;
    size_t rowoff = ((size_t)h*NTOK + i)*NTOK;
    float m = -1e30f;
    #pragma unroll
    for (int t = 0; t < 8; t++) {
        float4 bt = *reinterpret_cast<const float4*>(&d_bT[rowoff + t*64 + jg*4]);
        lv[t*4+0] += bt.x; lv[t*4+1] += bt.y; lv[t*4+2] += bt.z; lv[t*4+3] += bt.w;
        m = fmaxf(m, fmaxf(fmaxf(lv[t*4+0], lv[t*4+1]), fmaxf(lv[t*4+2], lv[t*4+3])));
    }
    #pragma unroll
    for (int o = 8; o; o >>= 1) m = fmaxf(m, __shfl_xor_sync(0xffffffffu, m, o));
    float s = 0.f;
    #pragma unroll
    for (int q = 0; q < 32; q++) { lv[q] = __expf(lv[q] - m); s += lv[q]; }
    #pragma unroll
    for (int o = 8; o; o >>= 1) s += __shfl_xor_sync(0xffffffffu, s, o);
    float inv = 1.f / s;
    #pragma unroll
    for (int t = 0; t < 8; t++) {
        float4 o4 = make_float4(lv[t*4+0]*inv, lv[t*4+1]*inv, lv[t*4+2]*inv, lv[t*4+3]*inv);
        *reinterpret_cast<float4*>(&d_a[rowoff + t*64 + jg*4]) = o4;
    }
}

// ======== fused A@V (+o_pt back-transform) AND o_pair in ONE kernel ========
// grid: 512 opair blocks first (long, memory-bound), then 192 av blocks.
// 128 threads. dynamic smem 57344 B.
__global__ void k_avop(const float* __restrict__ z) {
    extern __shared__ float smf[];
    int tid = threadIdx.x;  // 128

    if (blockIdx.x < NTOK) {
        // ---------- o_pair part: block per i, 3 heads/thread, double-buffered z ----------
        int i = blockIdx.x;
        float* as = smf;                 // 6144 floats
        float* zsA = smf + 6144;         // 4096 floats
        float* zsB = smf + 6144 + 4096;  // 4096 floats
        float4* as4 = reinterpret_cast<float4*>(as);
        const float4* asrc = reinterpret_cast<const float4*>(d_a);
        #pragma unroll
        for (int u = 0; u < 12; u++) {
            int l = tid + u*128;
            int hh = l >> 7, q = l & 127;
            as4[hh*128 + q] = asrc[(((size_t)hh*NTOK + i)*NTOK >> 2) + q];
        }
        const float4* zsrc = reinterpret_cast<const float4*>(z + (size_t)i*NTOK*CZD);
        float4* zA4 = reinterpret_cast<float4*>(zsA);
        float4* zB4 = reinterpret_cast<float4*>(zsB);
        #pragma unroll
        for (int u = 0; u < 8; u++) zA4[u*128 + tid] = zsrc[u*128 + tid];
        __syncthreads();
        int lane = tid & 31, h0 = tid >> 5;
        float acc[3][4] = {};
        for (int t = 0; t < 16; t++) {
            float4* cur = (t & 1) ? zB4 : zA4;
            float4* nxt = (t & 1) ? zA4 : zB4;
            float4 pre[8];
            if (t < 15) {
                #pragma unroll
                for (int u = 0; u < 8; u++)
                    pre[u] = zsrc[(size_t)(t+1)*1024 + u*128 + tid];
            }
            int jt = t*32;
            #pragma unroll 4
            for (int jj = 0; jj < 32; jj++) {
                float4 zv = cur[jj*32 + lane];
                float a0 = as[(h0+0)*NTOK + jt + jj];
                float a1 = as[(h0+4)*NTOK + jt + jj];
                float a2 = as[(h0+8)*NTOK + jt + jj];
                acc[0][0] += a0*zv.x; acc[0][1] += a0*zv.y; acc[0][2] += a0*zv.z; acc[0][3] += a0*zv.w;
                acc[1][0] += a1*zv.x; acc[1][1] += a1*zv.y; acc[1][2] += a1*zv.z; acc[1][3] += a1*zv.w;
                acc[2][0] += a2*zv.x; acc[2][1] += a2*zv.y; acc[2][2] += a2*zv.z; acc[2][3] += a2*zv.w;
            }
            if (t < 15) {
                #pragma unroll
                for (int u = 0; u < 8; u++) nxt[u*128 + tid] = pre[u];
            }
            __syncthreads();
        }
        #pragma unroll
        for (int hh = 0; hh < 3; hh++) {
            int h = h0 + hh*4;
            *reinterpret_cast<float4*>(&d_cat[(size_t)i*CAT_W + 576 + h*CZD + lane*4]) =
                make_float4(acc[hh][0], acc[hh][1], acc[hh][2], acc[hh][3]);
        }
    } else {
        // ---------- A@V part: 32-row tile per (i-tile, head) + fused o_pt transform ----------
        int idx = blockIdx.x - NTOK;
        int h = idx >> 4, i0 = (idx & 15) * 32;
        float* As = smf;          // [2][16][36] = 1152
        float* Bs = smf + 1152;   // [2][16][64] = 2048
        float* pt = smf + 3200;   // [32][24]    = 768
        int tx = tid & 15, ty = tid >> 4;
        const float* Ab = &d_a[((size_t)h*NTOK + i0)*NTOK];
        const float* Bb = &d_vJ[(size_t)h*NTOK*64];
        int ar = tid >> 2, ac = (tid & 3)*4;
        int br = tid >> 4, bc = (tid & 15)*4;

        float4 aR = *reinterpret_cast<const float4*>(&Ab[(size_t)ar*NTOK + ac]);
        float4 bR0 = *reinterpret_cast<const float4*>(&Bb[(size_t)br*64 + bc]);
        float4 bR1 = *reinterpret_cast<const float4*>(&Bb[(size_t)(br+8)*64 + bc]);
        As[(ac+0)*36 + ar] = aR.x; As[(ac+1)*36 + ar] = aR.y;
        As[(ac+2)*36 + ar] = aR.z; As[(ac+3)*36 + ar] = aR.w;
        *reinterpret_cast<float4*>(&Bs[br*64 + bc]) = bR0;
        *reinterpret_cast<float4*>(&Bs[(br+8)*64 + bc]) = bR1;
        __syncthreads();

        float acc[4][4] = {};
        const int KT = NTOK/16;
        for (int kt = 0; kt < KT; kt++) {
            int cur = kt & 1;
            float* Asb = As + cur*576;
            float* Bsb = Bs + cur*1024;
            if (kt+1 < KT) {
                aR  = *reinterpret_cast<const float4*>(&Ab[(size_t)ar*NTOK + (kt+1)*16 + ac]);
                bR0 = *reinterpret_cast<const float4*>(&Bb[(size_t)((kt+1)*16 + br)*64 + bc]);
                bR1 = *reinterpret_cast<const float4*>(&Bb[(size_t)((kt+1)*16 + br + 8)*64 + bc]);
            }
            #pragma unroll
            for (int k = 0; k < 16; k++) {
                float4 a4 = *reinterpret_cast<const float4*>(&Asb[k*36 + ty*4]);
                float4 b4 = *reinterpret_cast<const float4*>(&Bsb[k*64 + tx*4]);
                float am[4] = {a4.x, a4.y, a4.z, a4.w};
                float bn[4] = {b4.x, b4.y, b4.z, b4.w};
                #pragma unroll
                for (int mi = 0; mi < 4; mi++)
                    #pragma unroll
                    for (int ni = 0; ni < 4; ni++)
                        acc[mi][ni] += am[mi]*bn[ni];
            }
            if (kt+1 < KT) {
                float* Asn = As + (cur^1)*576;
                float* Bsn = Bs + (cur^1)*1024;
                Asn[(ac+0)*36 + ar] = aR.x; Asn[(ac+1)*36 + ar] = aR.y;
                Asn[(ac+2)*36 + ar] = aR.z; Asn[(ac+3)*36 + ar] = aR.w;
                *reinterpret_cast<float4*>(&Bsn[br*64 + bc]) = bR0;
                *reinterpret_cast<float4*>(&Bsn[(br+8)*64 + bc]) = bR1;
            }
            __syncthreads();
        }
        #pragma unroll
        for (int mi = 0; mi < 4; mi++) {
            int iloc = ty*4 + mi;
            int i = i0 + iloc;
            #pragma unroll
            for (int ni = 0; ni < 4; ni++) {
                int d = tx*4 + ni;
                if (d < 16)      d_cat[(size_t)i*CAT_W + h*16 + d] = acc[mi][ni];
                else if (d < 40) pt[iloc*24 + (d-16)] = acc[mi][ni];
            }
        }
        __syncthreads();
        // fused o_pt back-transform + norm for this (i-tile, head)
        #pragma unroll
        for (int q = tid; q < 256; q += 128) {
            int iloc = q >> 3, p = q & 7;
            int i = i0 + iloc;
            float v0 = pt[iloc*24 + p*3 + 0];
            float v1 = pt[iloc*24 + p*3 + 1];
            float v2 = pt[iloc*24 + p*3 + 2];
            const float* Rp = &d_R[i*9];
            float t0 = d_t[i*3+0], t1 = d_t[i*3+1], t2 = d_t[i*3+2];
            float gx = v0 - t0, gy = v1 - t1, gz = v2 - t2;
            float lx = Rp[0]*gx + Rp[3]*gy + Rp[6]*gz;
            float ly = Rp[1]*gx + Rp[4]*gy + Rp[7]*gz;
            float lz = Rp[2]*gx + Rp[5]*gy + Rp[8]*gz;
            float* cr = &d_cat[(size_t)i*CAT_W];
            cr[192 + h*24 + p*3 + 0] = lx;
            cr[192 + h*24 + p*3 + 1] = ly;
            cr[192 + h*24 + p*3 + 2] = lz;
            cr[480 + h*8 + p] = sqrtf(lx*lx + ly*ly + lz*lz + 1e-8f);
        }
    }
}

// ---------------- s = LN(s + bias + sum_p part[p]) ----------------
__global__ void k_addln(const float* __restrict__ part, int P,
                        const float* __restrict__ bias,
                        const float* __restrict__ g, const float* __restrict__ b) {
    int i = blockIdx.x;
    int tid = threadIdx.x;  // 128
    __shared__ float red[4];
    float v[3];
    float sum = 0.f;
    #pragma unroll
    for (int k = 0; k < 3; k++) {
        int c = tid + k*128;
        float x = d_s[(size_t)i*CSD + c];
        if (bias) x += bias[c];
        for (int p = 0; p < P; p++) x += part[(size_t)p*MNS + (size_t)i*CSD + c];
        v[k] = x;
        sum += x;
    }
    #pragma unroll
    for (int o = 16; o; o >>= 1) sum += __shfl_xor_sync(0xffffffffu, sum, o);
    if ((tid & 31) == 0) red[tid >> 5] = sum;
    __syncthreads();
    float tot = red[tid & 3];
    #pragma unroll
    for (int o = 2; o; o >>= 1) tot += __shfl_xor_sync(0xffffffffu, tot, o);
    float mean = tot * (1.f/384.f);
    float var = 0.f;
    #pragma unroll
    for (int k = 0; k < 3; k++) { float d = v[k] - mean; var += d*d; }
    #pragma unroll
    for (int o = 16; o; o >>= 1) var += __shfl_xor_sync(0xffffffffu, var, o);
    __syncthreads();
    if ((tid & 31) == 0) red[tid >> 5] = var;
    __syncthreads();
    float tv = red[tid & 3];
    #pragma unroll
    for (int o = 2; o; o >>= 1) tv += __shfl_xor_sync(0xffffffffu, tv, o);
    float inv = rsqrtf(tv*(1.f/384.f) + 1e-5f);
    #pragma unroll
    for (int k = 0; k < 3; k++) {
        int c = tid + k*128;
        d_s[(size_t)i*CSD + c] = (v[k] - mean)*inv*g[c] + b[c];
    }
}

// ------- ln2 + fused backbone update -------
__global__ void k_addln_bb(const float* __restrict__ part, int P,
                           const float* __restrict__ g, const float* __restrict__ b,
                           const float* __restrict__ wbb, const float* __restrict__ bbb) {
    int i = blockIdx.x;
    int tid = threadIdx.x;  // 128
    __shared__ float red[4];
    __shared__ float red6[4][6];
    __shared__ float upd[6];
    float v[3];
    float sum = 0.f;
    #pragma unroll
    for (int k = 0; k < 3; k++) {
        int c = tid + k*128;
        float x = d_s[(size_t)i*CSD + c];
        for (int p = 0; p < P; p++) x += part[(size_t)p*MNS + (size_t)i*CSD + c];
        v[k] = x;
        sum += x;
    }
    #pragma unroll
    for (int o = 16; o; o >>= 1) sum += __shfl_xor_sync(0xffffffffu, sum, o);
    if ((tid & 31) == 0) red[tid >> 5] = sum;
    __syncthreads();
    float tot = red[tid & 3];
    #pragma unroll
    for (int o = 2; o; o >>= 1) tot += __shfl_xor_sync(0xffffffffu, tot, o);
    float mean = tot * (1.f/384.f);
    float var = 0.f;
    #pragma unroll
    for (int k = 0; k < 3; k++) { float d = v[k] - mean; var += d*d; }
    #pragma unroll
    for (int o = 16; o; o >>= 1) var += __shfl_xor_sync(0xffffffffu, var, o);
    __syncthreads();
    if ((tid & 31) == 0) red[tid >> 5] = var;
    __syncthreads();
    float tv = red[tid & 3];
    #pragma unroll
    for (int o = 2; o; o >>= 1) tv += __shfl_xor_sync(0xffffffffu, tv, o);
    float inv = rsqrtf(tv*(1.f/384.f) + 1e-5f);
    float sv[3];
    #pragma unroll
    for (int k = 0; k < 3; k++) {
        int c = tid + k*128;
        sv[k] = (v[k] - mean)*inv*g[c] + b[c];
        d_s[(size_t)i*CSD + c] = sv[k];
    }
    float a6[6];
    #pragma unroll
    for (int o = 0; o < 6; o++) {
        a6[o] = sv[0]*wbb[(tid      )*6 + o]
              + sv[1]*wbb[(tid + 128)*6 + o]
              + sv[2]*wbb[(tid + 256)*6 + o];
    }
    #pragma unroll
    for (int o = 0; o < 6; o++)
        #pragma unroll
        for (int off = 16; off; off >>= 1)
            a6[o] += __shfl_xor_sync(0xffffffffu, a6[o], off);
    if ((tid & 31) == 0) {
        #pragma unroll
        for (int o = 0; o < 6; o++) red6[tid >> 5][o] = a6[o];
    }
    __syncthreads();
    if (tid < 6) upd[tid] = red6[0][tid] + red6[1][tid] + red6[2][tid] + red6[3][tid] + bbb[tid];
    __syncthreads();
    if (tid == 0) {
        float qb = upd[0], qc = upd[1], qd = upd[2];
        float qi = rsqrtf(1.f + qb*qb + qc*qc + qd*qd);
        float w = qi, x = qb*qi, y = qc*qi, zq = qd*qi;
        float Ru[9];
        Ru[0] = 1.f - 2.f*(y*y + zq*zq); Ru[1] = 2.f*(x*y - w*zq);        Ru[2] = 2.f*(x*zq + w*y);
        Ru[3] = 2.f*(x*y + w*zq);        Ru[4] = 1.f - 2.f*(x*x + zq*zq); Ru[5] = 2.f*(y*zq - w*x);
        Ru[6] = 2.f*(x*zq - w*y);        Ru[7] = 2.f*(y*zq + w*x);        Ru[8] = 1.f - 2.f*(x*x + y*y);
        float Ro[9];
        #pragma unroll
        for (int k = 0; k < 9; k++) Ro[k] = d_R[i*9 + k];
        float tu0 = upd[3], tu1 = upd[4], tu2 = upd[5];
        #pragma unroll
        for (int r = 0; r < 3; r++)
            d_t[i*3 + r] += Ro[r*3+0]*tu0 + Ro[r*3+1]*tu1 + Ro[r*3+2]*tu2;
        #pragma unroll
        for (int r = 0; r < 3; r++)
            #pragma unroll
            for (int c = 0; c < 3; c++)
                d_R[i*9 + r*3 + c] = Ro[r*3+0]*Ru[0*3+c] + Ro[r*3+1]*Ru[1*3+c] + Ro[r*3+2]*Ru[2*3+c];
    }
}

// ---------------- relu(sum of P partials) ----------------
__global__ void k_relusum(const float* __restrict__ part, int P, float* __restrict__ out) {
    int idx = blockIdx.x*blockDim.x + threadIdx.x;
    if (idx >= MNS) return;
    float x = 0.f;
    for (int p = 0; p < P; p++) x += part[(size_t)p*MNS + idx];
    out[idx] = fmaxf(x, 0.f);
}

// ---------------- final output [s | t] ----------------
__global__ void k_out(float* __restrict__ out) {
    int idx = blockIdx.x*blockDim.x + threadIdx.x;
    if (idx >= NTOK*387) return;
    int i = idx / 387, c = idx % 387;
    out[idx] = (c < 384) ? d_s[(size_t)i*CSD + c] : d_t[i*3 + (c - 384)];
}

// ---------------- host ----------------
extern "C" void kernel_launch(void* const* d_in, const int* in_sizes, int n_in,
                              void* d_out, int out_size) {
    (void)in_sizes; (void)n_in; (void)out_size;
    const float* s     = (const float*)d_in[0];
    const float* z     = (const float*)d_in[1];
    const float* wq    = (const float*)d_in[2];
    const float* wkv   = (const float*)d_in[3];
    const float* wqp   = (const float*)d_in[4];
    const float* wkvp  = (const float*)d_in[5];
    const float* wb    = (const float*)d_in[6];
    const float* hw    = (const float*)d_in[7];
    const float* wout  = (const float*)d_in[8];
    const float* bout  = (const float*)d_in[9];
    const float* ln1g  = (const float*)d_in[10];
    const float* ln1b  = (const float*)d_in[11];
    const float* wt1   = (const float*)d_in[12];
    const float* wt2   = (const float*)d_in[13];
    const float* wt3   = (const float*)d_in[14];
    const float* ln2g  = (const float*)d_in[15];
    const float* ln2b  = (const float*)d_in[16];
    const float* wbb   = (const float*)d_in[17];
    const float* bbb   = (const float*)d_in[18];

    float *p_s, *p_Wall, *p_cat, *p_tmp, *p_tmp2, *p_part;
    float *p_WallHi, *p_WallLo, *p_woutHi, *p_woutLo, *p_wtHi, *p_wtLo;
    cudaGetSymbolAddress((void**)&p_s,      d_s);
    cudaGetSymbolAddress((void**)&p_Wall,   d_Wall);
    cudaGetSymbolAddress((void**)&p_cat,    d_cat);
    cudaGetSymbolAddress((void**)&p_tmp,    d_tmp);
    cudaGetSymbolAddress((void**)&p_tmp2,   d_tmp2);
    cudaGetSymbolAddress((void**)&p_part,   d_part);
    cudaGetSymbolAddress((void**)&p_WallHi, d_WallHi);
    cudaGetSymbolAddress((void**)&p_WallLo, d_WallLo);
    cudaGetSymbolAddress((void**)&p_woutHi, d_woutHi);
    cudaGetSymbolAddress((void**)&p_woutLo, d_woutLo);
    cudaGetSymbolAddress((void**)&p_wtHi,   d_wtHi);
    cudaGetSymbolAddress((void**)&p_wtLo,   d_wtLo);

    cudaFuncSetAttribute(k_avop, cudaFuncAttributeMaxDynamicSharedMemorySize, 57344);

    k_init<<<(NTOK*CSD + 255)/256, 256>>>(s);
    k_catW<<<(CSD*QKV_W + 255)/256, 256>>>(wq, wkv, wqp, wkvp);
    k_splitW<<<(CSD*QKV_W + 255)/256, 256>>>(p_Wall, p_WallHi, p_WallLo, CSD*QKV_W);
    k_splitW<<<(CAT_W*CSD + 255)/256, 256>>>(wout, p_woutHi, p_woutLo, CAT_W*CSD);
    k_splitW<<<(CSD*CSD + 255)/256, 256>>>(wt1, p_wtHi,             p_wtLo,             CSD*CSD);
    k_splitW<<<(CSD*CSD + 255)/256, 256>>>(wt2, p_wtHi + CSD*CSD,   p_wtLo + CSD*CSD,   CSD*CSD);
    k_splitW<<<(CSD*CSD + 255)/256, 256>>>(wt3, p_wtHi + 2*CSD*CSD, p_wtLo + 2*CSD*CSD, CSD*CSD);
    k_bT<<<512, 256>>>(z, wb);

    for (int it = 0; it < NBLK; it++) {
        // qkv/points projection: K=384 split 2 -> 288 blocks
        mm3<<<dim3(QKV_W/64, NTOK/64, 2), 256>>>(p_s, p_WallHi, p_WallLo, p_part,
                                                 NTOK, QKV_W, CSD, CSD/2);
        k_transform<<<NTOK, 128>>>(hw);
        k_lsm<<<dim3(32, NH), 256>>>();
        // fused o_pair (512 blocks) + A@V/o_pt (192 blocks)
        k_avop<<<NTOK + 16*NH, 128, 57344>>>(z);
        // out projection: K=2112 split 6 -> 288 blocks
        mm3<<<dim3(CSD/64, NTOK/64, 6), 256>>>(p_cat, p_woutHi, p_woutLo, p_part,
                                               NTOK, CSD, CAT_W, CAT_W/6);
        k_addln<<<NTOK, 128>>>(p_part, 6, bout, ln1g, ln1b);
        // transition, K=384 split 3 each -> 144 blocks
        mm3<<<dim3(CSD/64, NTOK/64, 3), 256>>>(p_s, p_wtHi, p_wtLo, p_part,
                                               NTOK, CSD, CSD, CSD/3);
        k_relusum<<<(MNS + 255)/256, 256>>>(p_part, 3, p_tmp);
        mm3<<<dim3(CSD/64, NTOK/64, 3), 256>>>(p_tmp, p_wtHi + CSD*CSD, p_wtLo + CSD*CSD, p_part,
                                               NTOK, CSD, CSD, CSD/3);
        k_relusum<<<(MNS + 255)/256, 256>>>(p_part, 3, p_tmp2);
        mm3<<<dim3(CSD/64, NTOK/64, 3), 256>>>(p_tmp2, p_wtHi + 2*CSD*CSD, p_wtLo + 2*CSD*CSD, p_part,
                                               NTOK, CSD, CSD, CSD/3);
        k_addln_bb<<<NTOK, 128>>>(p_part, 3, ln2g, ln2b, wbb, bbb);
    }
    k_out<<<(NTOK*387 + 255)/256, 256>>>((float*)d_out);
}

// round 11
// speedup vs baseline: 2.3220x; 1.0022x over previous
#include <cuda_runtime.h>
#include <math.h>
#include <stdint.h>

#define NTOK 512
#define CSD 384
#define CZD 128
#define NH 12
#define PQN 4
#define PVN 8
#define NBLK 8
#define QKV_W 1152
#define CAT_W 2112
#define MNS (NTOK*CSD)
#define QOFF (NTOK*QKV_W)

#define WL 0.57735026918962576f             /* sqrt(1/3) */
#define HALFWC 0.11785113019775793f         /* 0.5*sqrt(2/(9*4)) */

// ---------------- device scratch ----------------
__device__ __align__(16) float d_s[NTOK*CSD];
__device__ __align__(16) float d_Wall[CSD*QKV_W];
__device__ __align__(16) float d_WallHi[CSD*QKV_W];
__device__ __align__(16) float d_WallLo[CSD*QKV_W];
__device__ __align__(16) float d_woutHi[CAT_W*CSD];
__device__ __align__(16) float d_woutLo[CAT_W*CSD];
__device__ __align__(16) float d_wtHi[3*CSD*CSD];
__device__ __align__(16) float d_wtLo[3*CSD*CSD];
__device__ __align__(16) float d_bT[(size_t)NH*NTOK*NTOK];   // [h][i][j], pre-scaled by wL
__device__ __align__(16) float d_a[(size_t)NH*NTOK*NTOK];    // [h][i][j] attn weights
__device__ __align__(16) float d_QfT[NH*32*NTOK];            // [h][f][i]
__device__ __align__(16) float d_KfT[NH*32*NTOK];            // [h][f][j]
__device__ __align__(16) float d_vJ[NH*NTOK*64];             // [h][j][d]
__device__ __align__(16) float d_cat[NTOK*CAT_W];
__device__ __align__(16) float d_part[6*NTOK*CSD];
__device__ __align__(16) float d_R[NTOK*9];
__device__ __align__(16) float d_t[NTOK*3];

// ---------------- init ----------------
__global__ void k_init(const float* __restrict__ s_in) {
    int idx = blockIdx.x*blockDim.x + threadIdx.x;
    if (idx < NTOK*CSD) d_s[idx] = s_in[idx];
    if (idx < NTOK*9)   d_R[idx] = ((idx % 9) % 4 == 0) ? 1.f : 0.f;
    if (idx < NTOK*3)   d_t[idx] = 0.f;
}

__global__ void k_catW(const float* __restrict__ wq, const float* __restrict__ wkv,
                       const float* __restrict__ wqp, const float* __restrict__ wkvp) {
    int idx = blockIdx.x*blockDim.x + threadIdx.x;
    if (idx >= CSD*QKV_W) return;
    int k = idx / QKV_W, c = idx % QKV_W;
    float v;
    if (c < 192)      v = wq[k*192 + c];
    else if (c < 576) v = wkv[k*384 + (c-192)];
    else if (c < 720) v = wqp[k*144 + (c-576)];
    else              v = wkvp[k*432 + (c-720)];
    d_Wall[idx] = v;
}

// split fp32 into tf32 hi/lo pair
__global__ void k_splitW(const float* __restrict__ src, float* __restrict__ hi,
                         float* __restrict__ lo, int n) {
    int i = blockIdx.x*blockDim.x + threadIdx.x;
    if (i >= n) return;
    float v = src[i];
    uint32_t hb; asm("cvt.rna.tf32.f32 %0, %1;" : "=r"(hb) : "f"(v));
    float hf = __uint_as_float(hb);
    float lf = v - hf;
    uint32_t lb; asm("cvt.rna.tf32.f32 %0, %1;" : "=r"(lb) : "f"(lf));
    hi[i] = hf;
    lo[i] = __uint_as_float(lb);
}

// b = wL * (z @ w_b), once per launch, layout [h][i][j]
__global__ void k_bT(const float* __restrict__ z, const float* __restrict__ wb) {
    int gwarp = (blockIdx.x*blockDim.x + threadIdx.x) >> 5;
    int lane  = threadIdx.x & 31;
    int nwarps = (gridDim.x*blockDim.x) >> 5;
    float wreg[4][NH];
    #pragma unroll
    for (int k = 0; k < 4; k++)
        #pragma unroll
        for (int h = 0; h < NH; h++)
            wreg[k][h] = wb[(lane + 32*k)*NH + h];
    for (int row = gwarp; row < NTOK*NTOK; row += nwarps) {
        const float* zr = z + (size_t)row*CZD;
        float zv[4];
        #pragma unroll
        for (int k = 0; k < 4; k++) zv[k] = zr[lane + 32*k];
        float acc[NH];
        #pragma unroll
        for (int h = 0; h < NH; h++)
            acc[h] = zv[0]*wreg[0][h] + zv[1]*wreg[1][h] + zv[2]*wreg[2][h] + zv[3]*wreg[3][h];
        #pragma unroll
        for (int h = 0; h < NH; h++)
            #pragma unroll
            for (int o = 16; o; o >>= 1)
                acc[h] += __shfl_xor_sync(0xffffffffu, acc[h], o);
        if (lane == 0) {
            int i = row >> 9, j = row & 511;
            #pragma unroll
            for (int h = 0; h < NH; h++)
                d_bT[((size_t)h*NTOK + i)*NTOK + j] = WL * acc[h];
        }
    }
}

#define MMA_TF32(d, a, b) \
    asm volatile("mma.sync.aligned.m16n8k8.row.col.f32.tf32.tf32.f32 " \
                 "{%0,%1,%2,%3},{%4,%5,%6,%7},{%8,%9},{%0,%1,%2,%3};" \
                 : "+f"(d[0]),"+f"(d[1]),"+f"(d[2]),"+f"(d[3]) \
                 : "r"(a[0]),"r"(a[1]),"r"(a[2]),"r"(a[3]),"r"(b[0]),"r"(b[1]))

__device__ __forceinline__ void tf32split(float v, uint32_t& h, uint32_t& l) {
    uint32_t hb; asm("cvt.rna.tf32.f32 %0, %1;" : "=r"(hb) : "f"(v));
    float lf = v - __uint_as_float(hb);
    uint32_t lb; asm("cvt.rna.tf32.f32 %0, %1;" : "=r"(lb) : "f"(lf));
    h = hb; l = lb;
}

// A-operand loader: plain, or relu(sum of 3 split-K partials)
__device__ __forceinline__ float4 loadA4(const float* p, size_t off, int fuseRelu) {
    float4 a = *reinterpret_cast<const float4*>(p + off);
    if (fuseRelu) {
        float4 b = *reinterpret_cast<const float4*>(p + off + (size_t)MNS);
        float4 c = *reinterpret_cast<const float4*>(p + off + (size_t)2*MNS);
        a.x = fmaxf(a.x + b.x + c.x, 0.f);
        a.y = fmaxf(a.y + b.y + c.y, 0.f);
        a.z = fmaxf(a.z + b.z + c.z, 0.f);
        a.w = fmaxf(a.w + b.w + c.w, 0.f);
    }
    return a;
}

// ------- 3xTF32 tensor-core GEMM, split-K; A pre-split to hi/lo in smem -------
// fuseRelu: A element = relu(A0+A1+A2) where Ap = A + p*MNS (transition chain fusion)
__global__ void mm3(const float* __restrict__ A, const float* __restrict__ Bhi,
                    const float* __restrict__ Blo, float* __restrict__ C,
                    int M, int N, int K, int Kp, int fuseRelu) {
    __shared__ float Ah[2][64][20];
    __shared__ float Al[2][64][20];
    __shared__ float Bh[2][16][72];
    __shared__ float Bl[2][16][72];
    int tid = threadIdx.x;
    int lane = tid & 31, warp = tid >> 5;
    int g = lane >> 2, tig = lane & 3;
    int wm = (warp >> 2) * 32;
    int wn = (warp & 3) * 16;
    int row0 = blockIdx.y * 64, col0 = blockIdx.x * 64;
    int kbase = blockIdx.z * Kp;
    const float* Ab  = A   + (size_t)row0*K + kbase;
    const float* Bhb = Bhi + (size_t)kbase*N + col0;
    const float* Blb = Blo + (size_t)kbase*N + col0;
    float* Cb = C + (size_t)blockIdx.z*M*N;

    int ar = tid >> 2, ac = (tid & 3)*4;
    int br = tid >> 4, bc = (tid & 15)*4;

    float4 aR = loadA4(Ab, (size_t)ar*K + ac, fuseRelu);
    float4 hR = *reinterpret_cast<const float4*>(&Bhb[(size_t)br*N + bc]);
    float4 lR = *reinterpret_cast<const float4*>(&Blb[(size_t)br*N + bc]);
    {
        float4 h4, l4;
        tf32split(aR.x, *(uint32_t*)&h4.x, *(uint32_t*)&l4.x);
        tf32split(aR.y, *(uint32_t*)&h4.y, *(uint32_t*)&l4.y);
        tf32split(aR.z, *(uint32_t*)&h4.z, *(uint32_t*)&l4.z);
        tf32split(aR.w, *(uint32_t*)&h4.w, *(uint32_t*)&l4.w);
        *reinterpret_cast<float4*>(&Ah[0][ar][ac]) = h4;
        *reinterpret_cast<float4*>(&Al[0][ar][ac]) = l4;
    }
    *reinterpret_cast<float4*>(&Bh[0][br][bc]) = hR;
    *reinterpret_cast<float4*>(&Bl[0][br][bc]) = lR;
    __syncthreads();

    float acc[2][2][4] = {};
    int KT = Kp >> 4;
    for (int kt = 0; kt < KT; kt++) {
        int cur = kt & 1;
        if (kt+1 < KT) {
            aR = loadA4(Ab, (size_t)ar*K + (kt+1)*16 + ac, fuseRelu);
            hR = *reinterpret_cast<const float4*>(&Bhb[(size_t)((kt+1)*16 + br)*N + bc]);
            lR = *reinterpret_cast<const float4*>(&Blb[(size_t)((kt+1)*16 + br)*N + bc]);
        }
        #pragma unroll
        for (int ks = 0; ks < 2; ks++) {
            int k0 = ks*8;
            uint32_t ahi[2][4], alo[2][4];
            #pragma unroll
            for (int mt = 0; mt < 2; mt++) {
                #pragma unroll
                for (int rr = 0; rr < 4; rr++) {
                    int rm = wm + mt*16 + g + (rr & 1)*8;
                    int rk = k0 + tig + (rr >> 1)*4;
                    ahi[mt][rr] = __float_as_uint(Ah[cur][rm][rk]);
                    alo[mt][rr] = __float_as_uint(Al[cur][rm][rk]);
                }
            }
            uint32_t bhf[2][2], blf[2][2];
            #pragma unroll
            for (int nt = 0; nt < 2; nt++) {
                int cn = wn + nt*8 + g;
                bhf[nt][0] = __float_as_uint(Bh[cur][k0 + tig][cn]);
                bhf[nt][1] = __float_as_uint(Bh[cur][k0 + tig + 4][cn]);
                blf[nt][0] = __float_as_uint(Bl[cur][k0 + tig][cn]);
                blf[nt][1] = __float_as_uint(Bl[cur][k0 + tig + 4][cn]);
            }
            #pragma unroll
            for (int mt = 0; mt < 2; mt++)
                #pragma unroll
                for (int nt = 0; nt < 2; nt++) {
                    MMA_TF32(acc[mt][nt], ahi[mt], bhf[nt]);
                    MMA_TF32(acc[mt][nt], ahi[mt], blf[nt]);
                    MMA_TF32(acc[mt][nt], alo[mt], bhf[nt]);
                }
        }
        if (kt+1 < KT) {
            int nxt = cur ^ 1;
            float4 h4, l4;
            tf32split(aR.x, *(uint32_t*)&h4.x, *(uint32_t*)&l4.x);
            tf32split(aR.y, *(uint32_t*)&h4.y, *(uint32_t*)&l4.y);
            tf32split(aR.z, *(uint32_t*)&h4.z, *(uint32_t*)&l4.z);
            tf32split(aR.w, *(uint32_t*)&h4.w, *(uint32_t*)&l4.w);
            *reinterpret_cast<float4*>(&Ah[nxt][ar][ac]) = h4;
            *reinterpret_cast<float4*>(&Al[nxt][ar][ac]) = l4;
            *reinterpret_cast<float4*>(&Bh[nxt][br][bc]) = hR;
            *reinterpret_cast<float4*>(&Bl[nxt][br][bc]) = lR;
        }
        __syncthreads();
    }
    #pragma unroll
    for (int mt = 0; mt < 2; mt++)
        #pragma unroll
        for (int nt = 0; nt < 2; nt++) {
            int r0 = row0 + wm + mt*16 + g;
            int c  = col0 + wn + nt*8 + 2*tig;
            *reinterpret_cast<float2*>(&Cb[(size_t)r0*N + c]) =
                make_float2(acc[mt][nt][0], acc[mt][nt][1]);
            *reinterpret_cast<float2*>(&Cb[(size_t)(r0+8)*N + c]) =
                make_float2(acc[mt][nt][2], acc[mt][nt][3]);
        }
}

// ---------------- point transform + feature build (sums 2 qkv split partials) ----------------
__global__ void k_transform(const float* __restrict__ hw) {
    int n = blockIdx.x;
    int tid = threadIdx.x;  // 128
    __shared__ float Rs[9], ts[3], sqk_s[NH], coef_s[NH];
    if (tid < 9)  Rs[tid] = d_R[n*9 + tid];
    if (tid < 3)  ts[tid] = d_t[n*3 + tid];
    if (tid < NH) {
        sqk_s[tid] = 0.f;
        float x = hw[tid];
        float g = (x > 20.f) ? x : log1pf(__expf(x));
        coef_s[tid] = g * HALFWC;
    }
    __syncthreads();
    const float* q0 = &d_part[(size_t)n*QKV_W];
    const float* q1 = &d_part[QOFF + (size_t)n*QKV_W];
    for (int l = tid; l < 192; l += 128) {
        int h = l >> 4, c = l & 15;
        d_QfT[(h*32 + c)*NTOK + n] = (q0[l] + q1[l]) * (0.25f*WL);
    }
    for (int l = tid; l < 384; l += 128) {
        int h = l >> 5, c = l & 31;
        float val = q0[192 + l] + q1[192 + l];
        if (c < 16) d_KfT[(h*32 + c)*NTOK + n] = val;
        else        d_vJ[((size_t)h*NTOK + n)*64 + (c-16)] = val;
    }
    for (int p = tid; p < 48; p += 128) {
        float x  = q0[576 + p*3 + 0] + q1[576 + p*3 + 0];
        float y  = q0[576 + p*3 + 1] + q1[576 + p*3 + 1];
        float zz = q0[576 + p*3 + 2] + q1[576 + p*3 + 2];
        float px = Rs[0]*x + Rs[1]*y + Rs[2]*zz + ts[0];
        float py = Rs[3]*x + Rs[4]*y + Rs[5]*zz + ts[1];
        float pz = Rs[6]*x + Rs[7]*y + Rs[8]*zz + ts[2];
        int h = p >> 2, pp = p & 3;
        float s2 = 2.f*WL*coef_s[h];
        d_QfT[(h*32 + 16 + pp*3 + 0)*NTOK + n] = px*s2;
        d_QfT[(h*32 + 16 + pp*3 + 1)*NTOK + n] = py*s2;
        d_QfT[(h*32 + 16 + pp*3 + 2)*NTOK + n] = pz*s2;
    }
    if (tid < NH) d_QfT[(tid*32 + 28)*NTOK + n] = 1.f;
    for (int p = tid; p < 144; p += 128) {
        float x  = q0[720 + p*3 + 0] + q1[720 + p*3 + 0];
        float y  = q0[720 + p*3 + 1] + q1[720 + p*3 + 1];
        float zz = q0[720 + p*3 + 2] + q1[720 + p*3 + 2];
        float px = Rs[0]*x + Rs[1]*y + Rs[2]*zz + ts[0];
        float py = Rs[3]*x + Rs[4]*y + Rs[5]*zz + ts[1];
        float pz = Rs[6]*x + Rs[7]*y + Rs[8]*zz + ts[2];
        int h = p / 12, pp = p % 12;
        if (pp < PQN) {
            d_KfT[(h*32 + 16 + pp*3 + 0)*NTOK + n] = px;
            d_KfT[(h*32 + 16 + pp*3 + 1)*NTOK + n] = py;
            d_KfT[(h*32 + 16 + pp*3 + 2)*NTOK + n] = pz;
            atomicAdd(&sqk_s[h], px*px + py*py + pz*pz);
        } else {
            int d = 16 + (pp - PQN)*3;
            size_t base = ((size_t)h*NTOK + n)*64 + d;
            d_vJ[base + 0] = px;
            d_vJ[base + 1] = py;
            d_vJ[base + 2] = pz;
        }
    }
    __syncthreads();
    if (tid < NH) d_KfT[(tid*32 + 28)*NTOK + n] = -WL*coef_s[tid]*sqk_s[tid];
}

// ------- fused logits + bT + softmax, double-buffered K tiles -------
__global__ void k_lsm() {
    int i0 = blockIdx.x * 16, h = blockIdx.y;
    int tid = threadIdx.x;          // 256
    int iloc = tid >> 4, jg = tid & 15;
    __shared__ float Qs[32][16];
    __shared__ float Ks[2][32][68];
    for (int l = tid; l < 512; l += 256) {
        int f = l >> 4, il = l & 15;
        Qs[f][il] = d_QfT[(h*32 + f)*NTOK + i0 + il];
    }
    int lf[8], lj[8];
    #pragma unroll
    for (int u = 0; u < 8; u++) {
        int l = tid + u*256;
        lf[u] = l >> 6; lj[u] = l & 63;
    }
    #pragma unroll
    for (int u = 0; u < 8; u++)
        Ks[0][lf[u]][lj[u]] = d_KfT[(h*32 + lf[u])*NTOK + lj[u]];
    __syncthreads();
    float lv[32];
    #pragma unroll
    for (int t = 0; t < 8; t++) {
        float kr[8];
        if (t < 7) {
            #pragma unroll
            for (int u = 0; u < 8; u++)
                kr[u] = d_KfT[(h*32 + lf[u])*NTOK + (t+1)*64 + lj[u]];
        }
        int cur = t & 1;
        float a0 = 0.f, a1 = 0.f, a2 = 0.f, a3 = 0.f;
        #pragma unroll
        for (int f = 0; f < 32; f++) {
            float qf = Qs[f][iloc];
            float4 kv = *reinterpret_cast<const float4*>(&Ks[cur][f][jg*4]);
            a0 += qf*kv.x; a1 += qf*kv.y; a2 += qf*kv.z; a3 += qf*kv.w;
        }
        lv[t*4+0] = a0; lv[t*4+1] = a1; lv[t*4+2] = a2; lv[t*4+3] = a3;
        if (t < 7) {
            #pragma unroll
            for (int u = 0; u < 8; u++)
                Ks[cur ^ 1][lf[u]][lj[u]] = kr[u];
        }
        __syncthreads();
    }
    int i = i0 + iloc;
    size_t rowoff = ((size_t)h*NTOK + i)*NTOK;
    float m = -1e30f;
    #pragma unroll
    for (int t = 0; t < 8; t++) {
        float4 bt = *reinterpret_cast<const float4*>(&d_bT[rowoff + t*64 + jg*4]);
        lv[t*4+0] += bt.x; lv[t*4+1] += bt.y; lv[t*4+2] += bt.z; lv[t*4+3] += bt.w;
        m = fmaxf(m, fmaxf(fmaxf(lv[t*4+0], lv[t*4+1]), fmaxf(lv[t*4+2], lv[t*4+3])));
    }
    #pragma unroll
    for (int o = 8; o; o >>= 1) m = fmaxf(m, __shfl_xor_sync(0xffffffffu, m, o));
    float s = 0.f;
    #pragma unroll
    for (int q = 0; q < 32; q++) { lv[q] = __expf(lv[q] - m); s += lv[q]; }
    #pragma unroll
    for (int o = 8; o; o >>= 1) s += __shfl_xor_sync(0xffffffffu, s, o);
    float inv = 1.f / s;
    #pragma unroll
    for (int t = 0; t < 8; t++) {
        float4 o4 = make_float4(lv[t*4+0]*inv, lv[t*4+1]*inv, lv[t*4+2]*inv, lv[t*4+3]*inv);
        *reinterpret_cast<float4*>(&d_a[rowoff + t*64 + jg*4]) = o4;
    }
}

// ======== fused A@V (+o_pt back-transform) AND o_pair in ONE kernel ========
__global__ void k_avop(const float* __restrict__ z) {
    extern __shared__ float smf[];
    int tid = threadIdx.x;  // 128

    if (blockIdx.x < NTOK) {
        int i = blockIdx.x;
        float* as = smf;
        float* zsA = smf + 6144;
        float* zsB = smf + 6144 + 4096;
        float4* as4 = reinterpret_cast<float4*>(as);
        const float4* asrc = reinterpret_cast<const float4*>(d_a);
        #pragma unroll
        for (int u = 0; u < 12; u++) {
            int l = tid + u*128;
            int hh = l >> 7, q = l & 127;
            as4[hh*128 + q] = asrc[(((size_t)hh*NTOK + i)*NTOK >> 2) + q];
        }
        const float4* zsrc = reinterpret_cast<const float4*>(z + (size_t)i*NTOK*CZD);
        float4* zA4 = reinterpret_cast<float4*>(zsA);
        float4* zB4 = reinterpret_cast<float4*>(zsB);
        #pragma unroll
        for (int u = 0; u < 8; u++) zA4[u*128 + tid] = zsrc[u*128 + tid];
        __syncthreads();
        int lane = tid & 31, h0 = tid >> 5;
        float acc[3][4] = {};
        for (int t = 0; t < 16; t++) {
            float4* cur = (t & 1) ? zB4 : zA4;
            float4* nxt = (t & 1) ? zA4 : zB4;
            float4 pre[8];
            if (t < 15) {
                #pragma unroll
                for (int u = 0; u < 8; u++)
                    pre[u] = zsrc[(size_t)(t+1)*1024 + u*128 + tid];
            }
            int jt = t*32;
            #pragma unroll 4
            for (int jj = 0; jj < 32; jj++) {
                float4 zv = cur[jj*32 + lane];
                float a0 = as[(h0+0)*NTOK + jt + jj];
                float a1 = as[(h0+4)*NTOK + jt + jj];
                float a2 = as[(h0+8)*NTOK + jt + jj];
                acc[0][0] += a0*zv.x; acc[0][1] += a0*zv.y; acc[0][2] += a0*zv.z; acc[0][3] += a0*zv.w;
                acc[1][0] += a1*zv.x; acc[1][1] += a1*zv.y; acc[1][2] += a1*zv.z; acc[1][3] += a1*zv.w;
                acc[2][0] += a2*zv.x; acc[2][1] += a2*zv.y; acc[2][2] += a2*zv.z; acc[2][3] += a2*zv.w;
            }
            if (t < 15) {
                #pragma unroll
                for (int u = 0; u < 8; u++) nxt[u*128 + tid] = pre[u];
            }
            __syncthreads();
        }
        #pragma unroll
        for (int hh = 0; hh < 3; hh++) {
            int h = h0 + hh*4;
            *reinterpret_cast<float4*>(&d_cat[(size_t)i*CAT_W + 576 + h*CZD + lane*4]) =
                make_float4(acc[hh][0], acc[hh][1], acc[hh][2], acc[hh][3]);
        }
    } else {
        int idx = blockIdx.x - NTOK;
        int h = idx >> 4, i0 = (idx & 15) * 32;
        float* As = smf;
        float* Bs = smf + 1152;
        float* pt = smf + 3200;
        int tx = tid & 15, ty = tid >> 4;
        const float* Ab = &d_a[((size_t)h*NTOK + i0)*NTOK];
        const float* Bb = &d_vJ[(size_t)h*NTOK*64];
        int ar = tid >> 2, ac = (tid & 3)*4;
        int br = tid >> 4, bc = (tid & 15)*4;

        float4 aR = *reinterpret_cast<const float4*>(&Ab[(size_t)ar*NTOK + ac]);
        float4 bR0 = *reinterpret_cast<const float4*>(&Bb[(size_t)br*64 + bc]);
        float4 bR1 = *reinterpret_cast<const float4*>(&Bb[(size_t)(br+8)*64 + bc]);
        As[(ac+0)*36 + ar] = aR.x; As[(ac+1)*36 + ar] = aR.y;
        As[(ac+2)*36 + ar] = aR.z; As[(ac+3)*36 + ar] = aR.w;
        *reinterpret_cast<float4*>(&Bs[br*64 + bc]) = bR0;
        *reinterpret_cast<float4*>(&Bs[(br+8)*64 + bc]) = bR1;
        __syncthreads();

        float acc[4][4] = {};
        const int KT = NTOK/16;
        for (int kt = 0; kt < KT; kt++) {
            int cur = kt & 1;
            float* Asb = As + cur*576;
            float* Bsb = Bs + cur*1024;
            if (kt+1 < KT) {
                aR  = *reinterpret_cast<const float4*>(&Ab[(size_t)ar*NTOK + (kt+1)*16 + ac]);
                bR0 = *reinterpret_cast<const float4*>(&Bb[(size_t)((kt+1)*16 + br)*64 + bc]);
                bR1 = *reinterpret_cast<const float4*>(&Bb[(size_t)((kt+1)*16 + br + 8)*64 + bc]);
            }
            #pragma unroll
            for (int k = 0; k < 16; k++) {
                float4 a4 = *reinterpret_cast<const float4*>(&Asb[k*36 + ty*4]);
                float4 b4 = *reinterpret_cast<const float4*>(&Bsb[k*64 + tx*4]);
                float am[4] = {a4.x, a4.y, a4.z, a4.w};
                float bn[4] = {b4.x, b4.y, b4.z, b4.w};
                #pragma unroll
                for (int mi = 0; mi < 4; mi++)
                    #pragma unroll
                    for (int ni = 0; ni < 4; ni++)
                        acc[mi][ni] += am[mi]*bn[ni];
            }
            if (kt+1 < KT) {
                float* Asn = As + (cur^1)*576;
                float* Bsn = Bs + (cur^1)*1024;
                Asn[(ac+0)*36 + ar] = aR.x; Asn[(ac+1)*36 + ar] = aR.y;
                Asn[(ac+2)*36 + ar] = aR.z; Asn[(ac+3)*36 + ar] = aR.w;
                *reinterpret_cast<float4*>(&Bsn[br*64 + bc]) = bR0;
                *reinterpret_cast<float4*>(&Bsn[(br+8)*64 + bc]) = bR1;
            }
            __syncthreads();
        }
        #pragma unroll
        for (int mi = 0; mi < 4; mi++) {
            int iloc = ty*4 + mi;
            int i = i0 + iloc;
            #pragma unroll
            for (int ni = 0; ni < 4; ni++) {
                int d = tx*4 + ni;
                if (d < 16)      d_cat[(size_t)i*CAT_W + h*16 + d] = acc[mi][ni];
                else if (d < 40) pt[iloc*24 + (d-16)] = acc[mi][ni];
            }
        }
        __syncthreads();
        #pragma unroll
        for (int q = tid; q < 256; q += 128) {
            int iloc = q >> 3, p = q & 7;
            int i = i0 + iloc;
            float v0 = pt[iloc*24 + p*3 + 0];
            float v1 = pt[iloc*24 + p*3 + 1];
            float v2 = pt[iloc*24 + p*3 + 2];
            const float* Rp = &d_R[i*9];
            float t0 = d_t[i*3+0], t1 = d_t[i*3+1], t2 = d_t[i*3+2];
            float gx = v0 - t0, gy = v1 - t1, gz = v2 - t2;
            float lx = Rp[0]*gx + Rp[3]*gy + Rp[6]*gz;
            float ly = Rp[1]*gx + Rp[4]*gy + Rp[7]*gz;
            float lz = Rp[2]*gx + Rp[5]*gy + Rp[8]*gz;
            float* cr = &d_cat[(size_t)i*CAT_W];
            cr[192 + h*24 + p*3 + 0] = lx;
            cr[192 + h*24 + p*3 + 1] = ly;
            cr[192 + h*24 + p*3 + 2] = lz;
            cr[480 + h*8 + p] = sqrtf(lx*lx + ly*ly + lz*lz + 1e-8f);
        }
    }
}

// ---------------- s = LN(s + bias + sum_p part[p]) ----------------
__global__ void k_addln(const float* __restrict__ part, int P,
                        const float* __restrict__ bias,
                        const float* __restrict__ g, const float* __restrict__ b) {
    int i = blockIdx.x;
    int tid = threadIdx.x;  // 128
    __shared__ float red[4];
    float v[3];
    float sum = 0.f;
    #pragma unroll
    for (int k = 0; k < 3; k++) {
        int c = tid + k*128;
        float x = d_s[(size_t)i*CSD + c];
        if (bias) x += bias[c];
        for (int p = 0; p < P; p++) x += part[(size_t)p*MNS + (size_t)i*CSD + c];
        v[k] = x;
        sum += x;
    }
    #pragma unroll
    for (int o = 16; o; o >>= 1) sum += __shfl_xor_sync(0xffffffffu, sum, o);
    if ((tid & 31) == 0) red[tid >> 5] = sum;
    __syncthreads();
    float tot = red[tid & 3];
    #pragma unroll
    for (int o = 2; o; o >>= 1) tot += __shfl_xor_sync(0xffffffffu, tot, o);
    float mean = tot * (1.f/384.f);
    float var = 0.f;
    #pragma unroll
    for (int k = 0; k < 3; k++) { float d = v[k] - mean; var += d*d; }
    #pragma unroll
    for (int o = 16; o; o >>= 1) var += __shfl_xor_sync(0xffffffffu, var, o);
    __syncthreads();
    if ((tid & 31) == 0) red[tid >> 5] = var;
    __syncthreads();
    float tv = red[tid & 3];
    #pragma unroll
    for (int o = 2; o; o >>= 1) tv += __shfl_xor_sync(0xffffffffu, tv, o);
    float inv = rsqrtf(tv*(1.f/384.f) + 1e-5f);
    #pragma unroll
    for (int k = 0; k < 3; k++) {
        int c = tid + k*128;
        d_s[(size_t)i*CSD + c] = (v[k] - mean)*inv*g[c] + b[c];
    }
}

// ------- ln2 + fused backbone update -------
__global__ void k_addln_bb(const float* __restrict__ part, int P,
                           const float* __restrict__ g, const float* __restrict__ b,
                           const float* __restrict__ wbb, const float* __restrict__ bbb) {
    int i = blockIdx.x;
    int tid = threadIdx.x;  // 128
    __shared__ float red[4];
    __shared__ float red6[4][6];
    __shared__ float upd[6];
    float v[3];
    float sum = 0.f;
    #pragma unroll
    for (int k = 0; k < 3; k++) {
        int c = tid + k*128;
        float x = d_s[(size_t)i*CSD + c];
        for (int p = 0; p < P; p++) x += part[(size_t)p*MNS + (size_t)i*CSD + c];
        v[k] = x;
        sum += x;
    }
    #pragma unroll
    for (int o = 16; o; o >>= 1) sum += __shfl_xor_sync(0xffffffffu, sum, o);
    if ((tid & 31) == 0) red[tid >> 5] = sum;
    __syncthreads();
    float tot = red[tid & 3];
    #pragma unroll
    for (int o = 2; o; o >>= 1) tot += __shfl_xor_sync(0xffffffffu, tot, o);
    float mean = tot * (1.f/384.f);
    float var = 0.f;
    #pragma unroll
    for (int k = 0; k < 3; k++) { float d = v[k] - mean; var += d*d; }
    #pragma unroll
    for (int o = 16; o; o >>= 1) var += __shfl_xor_sync(0xffffffffu, var, o);
    __syncthreads();
    if ((tid & 31) == 0) red[tid >> 5] = var;
    __syncthreads();
    float tv = red[tid & 3];
    #pragma unroll
    for (int o = 2; o; o >>= 1) tv += __shfl_xor_sync(0xffffffffu, tv, o);
    float inv = rsqrtf(tv*(1.f/384.f) + 1e-5f);
    float sv[3];
    #pragma unroll
    for (int k = 0; k < 3; k++) {
        int c = tid + k*128;
        sv[k] = (v[k] - mean)*inv*g[c] + b[c];
        d_s[(size_t)i*CSD + c] = sv[k];
    }
    float a6[6];
    #pragma unroll
    for (int o = 0; o < 6; o++) {
        a6[o] = sv[0]*wbb[(tid      )*6 + o]
              + sv[1]*wbb[(tid + 128)*6 + o]
              + sv[2]*wbb[(tid + 256)*6 + o];
    }
    #pragma unroll
    for (int o = 0; o < 6; o++)
        #pragma unroll
        for (int off = 16; off; off >>= 1)
            a6[o] += __shfl_xor_sync(0xffffffffu, a6[o], off);
    if ((tid & 31) == 0) {
        #pragma unroll
        for (int o = 0; o < 6; o++) red6[tid >> 5][o] = a6[o];
    }
    __syncthreads();
    if (tid < 6) upd[tid] = red6[0][tid] + red6[1][tid] + red6[2][tid] + red6[3][tid] + bbb[tid];
    __syncthreads();
    if (tid == 0) {
        float qb = upd[0], qc = upd[1], qd = upd[2];
        float qi = rsqrtf(1.f + qb*qb + qc*qc + qd*qd);
        float w = qi, x = qb*qi, y = qc*qi, zq = qd*qi;
        float Ru[9];
        Ru[0] = 1.f - 2.f*(y*y + zq*zq); Ru[1] = 2.f*(x*y - w*zq);        Ru[2] = 2.f*(x*zq + w*y);
        Ru[3] = 2.f*(x*y + w*zq);        Ru[4] = 1.f - 2.f*(x*x + zq*zq); Ru[5] = 2.f*(y*zq - w*x);
        Ru[6] = 2.f*(x*zq - w*y);        Ru[7] = 2.f*(y*zq + w*x);        Ru[8] = 1.f - 2.f*(x*x + y*y);
        float Ro[9];
        #pragma unroll
        for (int k = 0; k < 9; k++) Ro[k] = d_R[i*9 + k];
        float tu0 = upd[3], tu1 = upd[4], tu2 = upd[5];
        #pragma unroll
        for (int r = 0; r < 3; r++)
            d_t[i*3 + r] += Ro[r*3+0]*tu0 + Ro[r*3+1]*tu1 + Ro[r*3+2]*tu2;
        #pragma unroll
        for (int r = 0; r < 3; r++)
            #pragma unroll
            for (int c = 0; c < 3; c++)
                d_R[i*9 + r*3 + c] = Ro[r*3+0]*Ru[0*3+c] + Ro[r*3+1]*Ru[1*3+c] + Ro[r*3+2]*Ru[2*3+c];
    }
}

// ---------------- final output [s | t] ----------------
__global__ void k_out(float* __restrict__ out) {
    int idx = blockIdx.x*blockDim.x + threadIdx.x;
    if (idx >= NTOK*387) return;
    int i = idx / 387, c = idx % 387;
    out[idx] = (c < 384) ? d_s[(size_t)i*CSD + c] : d_t[i*3 + (c - 384)];
}

// ---------------- host ----------------
extern "C" void kernel_launch(void* const* d_in, const int* in_sizes, int n_in,
                              void* d_out, int out_size) {
    (void)in_sizes; (void)n_in; (void)out_size;
    const float* s     = (const float*)d_in[0];
    const float* z     = (const float*)d_in[1];
    const float* wq    = (const float*)d_in[2];
    const float* wkv   = (const float*)d_in[3];
    const float* wqp   = (const float*)d_in[4];
    const float* wkvp  = (const float*)d_in[5];
    const float* wb    = (const float*)d_in[6];
    const float* hw    = (const float*)d_in[7];
    const float* wout  = (const float*)d_in[8];
    const float* bout  = (const float*)d_in[9];
    const float* ln1g  = (const float*)d_in[10];
    const float* ln1b  = (const float*)d_in[11];
    const float* wt1   = (const float*)d_in[12];
    const float* wt2   = (const float*)d_in[13];
    const float* wt3   = (const float*)d_in[14];
    const float* ln2g  = (const float*)d_in[15];
    const float* ln2b  = (const float*)d_in[16];
    const float* wbb   = (const float*)d_in[17];
    const float* bbb   = (const float*)d_in[18];

    float *p_s, *p_Wall, *p_cat, *p_part;
    float *p_WallHi, *p_WallLo, *p_woutHi, *p_woutLo, *p_wtHi, *p_wtLo;
    cudaGetSymbolAddress((void**)&p_s,      d_s);
    cudaGetSymbolAddress((void**)&p_Wall,   d_Wall);
    cudaGetSymbolAddress((void**)&p_cat,    d_cat);
    cudaGetSymbolAddress((void**)&p_part,   d_part);
    cudaGetSymbolAddress((void**)&p_WallHi, d_WallHi);
    cudaGetSymbolAddress((void**)&p_WallLo, d_WallLo);
    cudaGetSymbolAddress((void**)&p_woutHi, d_woutHi);
    cudaGetSymbolAddress((void**)&p_woutLo, d_woutLo);
    cudaGetSymbolAddress((void**)&p_wtHi,   d_wtHi);
    cudaGetSymbolAddress((void**)&p_wtLo,   d_wtLo);

    cudaFuncSetAttribute(k_avop, cudaFuncAttributeMaxDynamicSharedMemorySize, 57344);

    k_init<<<(NTOK*CSD + 255)/256, 256>>>(s);
    k_catW<<<(CSD*QKV_W + 255)/256, 256>>>(wq, wkv, wqp, wkvp);
    k_splitW<<<(CSD*QKV_W + 255)/256, 256>>>(p_Wall, p_WallHi, p_WallLo, CSD*QKV_W);
    k_splitW<<<(CAT_W*CSD + 255)/256, 256>>>(wout, p_woutHi, p_woutLo, CAT_W*CSD);
    k_splitW<<<(CSD*CSD + 255)/256, 256>>>(wt1, p_wtHi,             p_wtLo,             CSD*CSD);
    k_splitW<<<(CSD*CSD + 255)/256, 256>>>(wt2, p_wtHi + CSD*CSD,   p_wtLo + CSD*CSD,   CSD*CSD);
    k_splitW<<<(CSD*CSD + 255)/256, 256>>>(wt3, p_wtHi + 2*CSD*CSD, p_wtLo + 2*CSD*CSD, CSD*CSD);
    k_bT<<<512, 256>>>(z, wb);

    for (int it = 0; it < NBLK; it++) {
        // qkv/points projection: K=384 split 2 -> 288 blocks
        mm3<<<dim3(QKV_W/64, NTOK/64, 2), 256>>>(p_s, p_WallHi, p_WallLo, p_part,
                                                 NTOK, QKV_W, CSD, CSD/2, 0);
        k_transform<<<NTOK, 128>>>(hw);
        k_lsm<<<dim3(32, NH), 256>>>();
        // fused o_pair (512 blocks) + A@V/o_pt (192 blocks)
        k_avop<<<NTOK + 16*NH, 128, 57344>>>(z);
        // out projection: K=2112 split 6 -> 288 blocks
        mm3<<<dim3(CSD/64, NTOK/64, 6), 256>>>(p_cat, p_woutHi, p_woutLo, p_part,
                                               NTOK, CSD, CAT_W, CAT_W/6, 0);
        k_addln<<<NTOK, 128>>>(p_part, 6, bout, ln1g, ln1b);
        // transition: t1 (A=s), t2/t3 fused relu-of-3-partials A-load; ping-pong slots 0-2 / 3-5
        mm3<<<dim3(CSD/64, NTOK/64, 3), 256>>>(p_s, p_wtHi, p_wtLo, p_part,
                                               NTOK, CSD, CSD, CSD/3, 0);
        mm3<<<dim3(CSD/64, NTOK/64, 3), 256>>>(p_part, p_wtHi + CSD*CSD, p_wtLo + CSD*CSD,
                                               p_part + (size_t)3*MNS,
                                               NTOK, CSD, CSD, CSD/3, 1);
        mm3<<<dim3(CSD/64, NTOK/64, 3), 256>>>(p_part + (size_t)3*MNS,
                                               p_wtHi + 2*CSD*CSD, p_wtLo + 2*CSD*CSD, p_part,
                                               NTOK, CSD, CSD, CSD/3, 1);
        k_addln_bb<<<NTOK, 128>>>(p_part, 3, ln2g, ln2b, wbb, bbb);
    }
    k_out<<<(NTOK*387 + 255)/256, 256>>>((float*)d_out);
}

// round 14
// speedup vs baseline: 2.3883x; 1.0286x over previous
#include <cuda_runtime.h>
#include <math.h>
#include <stdint.h>

#define NTOK 512
#define CSD 384
#define CZD 128
#define NH 12
#define PQN 4
#define PVN 8
#define NBLK 8
#define QKV_W 1152
#define CAT_W 2112
#define MNS (NTOK*CSD)
#define QOFF (NTOK*QKV_W)

#define WL 0.57735026918962576f             /* sqrt(1/3) */
#define HALFWC 0.11785113019775793f         /* 0.5*sqrt(2/(9*4)) */

// ---------------- device scratch ----------------
__device__ __align__(16) float d_s[NTOK*CSD];
__device__ __align__(16) float d_Wall[CSD*QKV_W];
__device__ __align__(16) float d_WallHi[CSD*QKV_W];
__device__ __align__(16) float d_WallLo[CSD*QKV_W];
__device__ __align__(16) float d_woutHi[CAT_W*CSD];
__device__ __align__(16) float d_woutLo[CAT_W*CSD];
__device__ __align__(16) float d_wtHi[3*CSD*CSD];
__device__ __align__(16) float d_wtLo[3*CSD*CSD];
__device__ __align__(16) float d_bT[(size_t)NH*NTOK*NTOK];   // [h][i][j], pre-scaled by wL
__device__ __align__(16) float d_a[(size_t)NH*NTOK*NTOK];    // [h][i][j] attn weights
__device__ __align__(16) float d_QfT[NH*32*NTOK];            // [h][f][i]
__device__ __align__(16) float d_KfT[NH*32*NTOK];            // [h][f][j]
__device__ __align__(16) float d_vJ[NH*NTOK*64];             // [h][j][d]
__device__ __align__(16) float d_cat[NTOK*CAT_W];
__device__ __align__(16) float d_part[6*NTOK*CSD];
__device__ __align__(16) float d_R[NTOK*9];
__device__ __align__(16) float d_t[NTOK*3];

// ---------------- init ----------------
__global__ void k_init(const float* __restrict__ s_in) {
    int idx = blockIdx.x*blockDim.x + threadIdx.x;
    if (idx < NTOK*CSD) d_s[idx] = s_in[idx];
    if (idx < NTOK*9)   d_R[idx] = ((idx % 9) % 4 == 0) ? 1.f : 0.f;
    if (idx < NTOK*3)   d_t[idx] = 0.f;
}

__global__ void k_catW(const float* __restrict__ wq, const float* __restrict__ wkv,
                       const float* __restrict__ wqp, const float* __restrict__ wkvp) {
    int idx = blockIdx.x*blockDim.x + threadIdx.x;
    if (idx >= CSD*QKV_W) return;
    int k = idx / QKV_W, c = idx % QKV_W;
    float v;
    if (c < 192)      v = wq[k*192 + c];
    else if (c < 576) v = wkv[k*384 + (c-192)];
    else if (c < 720) v = wqp[k*144 + (c-576)];
    else              v = wkvp[k*432 + (c-720)];
    d_Wall[idx] = v;
}

// split fp32 into tf32 hi/lo pair
__global__ void k_splitW(const float* __restrict__ src, float* __restrict__ hi,
                         float* __restrict__ lo, int n) {
    int i = blockIdx.x*blockDim.x + threadIdx.x;
    if (i >= n) return;
    float v = src[i];
    uint32_t hb; asm("cvt.rna.tf32.f32 %0, %1;" : "=r"(hb) : "f"(v));
    float hf = __uint_as_float(hb);
    float lf = v - hf;
    uint32_t lb; asm("cvt.rna.tf32.f32 %0, %1;" : "=r"(lb) : "f"(lf));
    hi[i] = hf;
    lo[i] = __uint_as_float(lb);
}

// b = wL * (z @ w_b), once per launch, layout [h][i][j]
__global__ void k_bT(const float* __restrict__ z, const float* __restrict__ wb) {
    int gwarp = (blockIdx.x*blockDim.x + threadIdx.x) >> 5;
    int lane  = threadIdx.x & 31;
    int nwarps = (gridDim.x*blockDim.x) >> 5;
    float wreg[4][NH];
    #pragma unroll
    for (int k = 0; k < 4; k++)
        #pragma unroll
        for (int h = 0; h < NH; h++)
            wreg[k][h] = wb[(lane + 32*k)*NH + h];
    for (int row = gwarp; row < NTOK*NTOK; row += nwarps) {
        const float* zr = z + (size_t)row*CZD;
        float zv[4];
        #pragma unroll
        for (int k = 0; k < 4; k++) zv[k] = zr[lane + 32*k];
        float acc[NH];
        #pragma unroll
        for (int h = 0; h < NH; h++)
            acc[h] = zv[0]*wreg[0][h] + zv[1]*wreg[1][h] + zv[2]*wreg[2][h] + zv[3]*wreg[3][h];
        #pragma unroll
        for (int h = 0; h < NH; h++)
            #pragma unroll
            for (int o = 16; o; o >>= 1)
                acc[h] += __shfl_xor_sync(0xffffffffu, acc[h], o);
        if (lane == 0) {
            int i = row >> 9, j = row & 511;
            #pragma unroll
            for (int h = 0; h < NH; h++)
                d_bT[((size_t)h*NTOK + i)*NTOK + j] = WL * acc[h];
        }
    }
}

#define MMA_TF32(d, a, b) \
    asm volatile("mma.sync.aligned.m16n8k8.row.col.f32.tf32.tf32.f32 " \
                 "{%0,%1,%2,%3},{%4,%5,%6,%7},{%8,%9},{%0,%1,%2,%3};" \
                 : "+f"(d[0]),"+f"(d[1]),"+f"(d[2]),"+f"(d[3]) \
                 : "r"(a[0]),"r"(a[1]),"r"(a[2]),"r"(a[3]),"r"(b[0]),"r"(b[1]))

__device__ __forceinline__ void tf32split(float v, uint32_t& h, uint32_t& l) {
    uint32_t hb; asm("cvt.rna.tf32.f32 %0, %1;" : "=r"(hb) : "f"(v));
    float lf = v - __uint_as_float(hb);
    uint32_t lb; asm("cvt.rna.tf32.f32 %0, %1;" : "=r"(lb) : "f"(lf));
    h = hb; l = lb;
}

// A-operand loader: plain, or relu(sum of 3 split-K partials)
__device__ __forceinline__ float4 loadA4(const float* p, size_t off, int fuseRelu) {
    float4 a = *reinterpret_cast<const float4*>(p + off);
    if (fuseRelu) {
        float4 b = *reinterpret_cast<const float4*>(p + off + (size_t)MNS);
        float4 c = *reinterpret_cast<const float4*>(p + off + (size_t)2*MNS);
        a.x = fmaxf(a.x + b.x + c.x, 0.f);
        a.y = fmaxf(a.y + b.y + c.y, 0.f);
        a.z = fmaxf(a.z + b.z + c.z, 0.f);
        a.w = fmaxf(a.w + b.w + c.w, 0.f);
    }
    return a;
}

// ------- 3xTF32 tensor-core GEMM, split-K; A pre-split to hi/lo in smem -------
__global__ void mm3(const float* __restrict__ A, const float* __restrict__ Bhi,
                    const float* __restrict__ Blo, float* __restrict__ C,
                    int M, int N, int K, int Kp, int fuseRelu) {
    __shared__ float Ah[2][64][20];
    __shared__ float Al[2][64][20];
    __shared__ float Bh[2][16][72];
    __shared__ float Bl[2][16][72];
    int tid = threadIdx.x;
    int lane = tid & 31, warp = tid >> 5;
    int g = lane >> 2, tig = lane & 3;
    int wm = (warp >> 2) * 32;
    int wn = (warp & 3) * 16;
    int row0 = blockIdx.y * 64, col0 = blockIdx.x * 64;
    int kbase = blockIdx.z * Kp;
    const float* Ab  = A   + (size_t)row0*K + kbase;
    const float* Bhb = Bhi + (size_t)kbase*N + col0;
    const float* Blb = Blo + (size_t)kbase*N + col0;
    float* Cb = C + (size_t)blockIdx.z*M*N;

    int ar = tid >> 2, ac = (tid & 3)*4;
    int br = tid >> 4, bc = (tid & 15)*4;

    float4 aR = loadA4(Ab, (size_t)ar*K + ac, fuseRelu);
    float4 hR = *reinterpret_cast<const float4*>(&Bhb[(size_t)br*N + bc]);
    float4 lR = *reinterpret_cast<const float4*>(&Blb[(size_t)br*N + bc]);
    {
        float4 h4, l4;
        tf32split(aR.x, *(uint32_t*)&h4.x, *(uint32_t*)&l4.x);
        tf32split(aR.y, *(uint32_t*)&h4.y, *(uint32_t*)&l4.y);
        tf32split(aR.z, *(uint32_t*)&h4.z, *(uint32_t*)&l4.z);
        tf32split(aR.w, *(uint32_t*)&h4.w, *(uint32_t*)&l4.w);
        *reinterpret_cast<float4*>(&Ah[0][ar][ac]) = h4;
        *reinterpret_cast<float4*>(&Al[0][ar][ac]) = l4;
    }
    *reinterpret_cast<float4*>(&Bh[0][br][bc]) = hR;
    *reinterpret_cast<float4*>(&Bl[0][br][bc]) = lR;
    __syncthreads();

    float acc[2][2][4] = {};
    int KT = Kp >> 4;
    for (int kt = 0; kt < KT; kt++) {
        int cur = kt & 1;
        if (kt+1 < KT) {
            aR = loadA4(Ab, (size_t)ar*K + (kt+1)*16 + ac, fuseRelu);
            hR = *reinterpret_cast<const float4*>(&Bhb[(size_t)((kt+1)*16 + br)*N + bc]);
            lR = *reinterpret_cast<const float4*>(&Blb[(size_t)((kt+1)*16 + br)*N + bc]);
        }
        #pragma unroll
        for (int ks = 0; ks < 2; ks++) {
            int k0 = ks*8;
            uint32_t ahi[2][4], alo[2][4];
            #pragma unroll
            for (int mt = 0; mt < 2; mt++) {
                #pragma unroll
                for (int rr = 0; rr < 4; rr++) {
                    int rm = wm + mt*16 + g + (rr & 1)*8;
                    int rk = k0 + tig + (rr >> 1)*4;
                    ahi[mt][rr] = __float_as_uint(Ah[cur][rm][rk]);
                    alo[mt][rr] = __float_as_uint(Al[cur][rm][rk]);
                }
            }
            uint32_t bhf[2][2], blf[2][2];
            #pragma unroll
            for (int nt = 0; nt < 2; nt++) {
                int cn = wn + nt*8 + g;
                bhf[nt][0] = __float_as_uint(Bh[cur][k0 + tig][cn]);
                bhf[nt][1] = __float_as_uint(Bh[cur][k0 + tig + 4][cn]);
                blf[nt][0] = __float_as_uint(Bl[cur][k0 + tig][cn]);
                blf[nt][1] = __float_as_uint(Bl[cur][k0 + tig + 4][cn]);
            }
            #pragma unroll
            for (int mt = 0; mt < 2; mt++)
                #pragma unroll
                for (int nt = 0; nt < 2; nt++) {
                    MMA_TF32(acc[mt][nt], ahi[mt], bhf[nt]);
                    MMA_TF32(acc[mt][nt], ahi[mt], blf[nt]);
                    MMA_TF32(acc[mt][nt], alo[mt], bhf[nt]);
                }
        }
        if (kt+1 < KT) {
            int nxt = cur ^ 1;
            float4 h4, l4;
            tf32split(aR.x, *(uint32_t*)&h4.x, *(uint32_t*)&l4.x);
            tf32split(aR.y, *(uint32_t*)&h4.y, *(uint32_t*)&l4.y);
            tf32split(aR.z, *(uint32_t*)&h4.z, *(uint32_t*)&l4.z);
            tf32split(aR.w, *(uint32_t*)&h4.w, *(uint32_t*)&l4.w);
            *reinterpret_cast<float4*>(&Ah[nxt][ar][ac]) = h4;
            *reinterpret_cast<float4*>(&Al[nxt][ar][ac]) = l4;
            *reinterpret_cast<float4*>(&Bh[nxt][br][bc]) = hR;
            *reinterpret_cast<float4*>(&Bl[nxt][br][bc]) = lR;
        }
        __syncthreads();
    }
    #pragma unroll
    for (int mt = 0; mt < 2; mt++)
        #pragma unroll
        for (int nt = 0; nt < 2; nt++) {
            int r0 = row0 + wm + mt*16 + g;
            int c  = col0 + wn + nt*8 + 2*tig;
            *reinterpret_cast<float2*>(&Cb[(size_t)r0*N + c]) =
                make_float2(acc[mt][nt][0], acc[mt][nt][1]);
            *reinterpret_cast<float2*>(&Cb[(size_t)(r0+8)*N + c]) =
                make_float2(acc[mt][nt][2], acc[mt][nt][3]);
        }
}

// ---------------- point transform + feature build (sums 2 qkv split partials) ----------------
__global__ void k_transform(const float* __restrict__ hw) {
    int n = blockIdx.x;
    int tid = threadIdx.x;  // 128
    __shared__ float Rs[9], ts[3], sqk_s[NH], coef_s[NH];
    if (tid < 9)  Rs[tid] = d_R[n*9 + tid];
    if (tid < 3)  ts[tid] = d_t[n*3 + tid];
    if (tid < NH) {
        sqk_s[tid] = 0.f;
        float x = hw[tid];
        float g = (x > 20.f) ? x : log1pf(__expf(x));
        coef_s[tid] = g * HALFWC;
    }
    __syncthreads();
    const float* q0 = &d_part[(size_t)n*QKV_W];
    const float* q1 = &d_part[QOFF + (size_t)n*QKV_W];
    for (int l = tid; l < 192; l += 128) {
        int h = l >> 4, c = l & 15;
        d_QfT[(h*32 + c)*NTOK + n] = (q0[l] + q1[l]) * (0.25f*WL);
    }
    for (int l = tid; l < 384; l += 128) {
        int h = l >> 5, c = l & 31;
        float val = q0[192 + l] + q1[192 + l];
        if (c < 16) d_KfT[(h*32 + c)*NTOK + n] = val;
        else        d_vJ[((size_t)h*NTOK + n)*64 + (c-16)] = val;
    }
    for (int p = tid; p < 48; p += 128) {
        float x  = q0[576 + p*3 + 0] + q1[576 + p*3 + 0];
        float y  = q0[576 + p*3 + 1] + q1[576 + p*3 + 1];
        float zz = q0[576 + p*3 + 2] + q1[576 + p*3 + 2];
        float px = Rs[0]*x + Rs[1]*y + Rs[2]*zz + ts[0];
        float py = Rs[3]*x + Rs[4]*y + Rs[5]*zz + ts[1];
        float pz = Rs[6]*x + Rs[7]*y + Rs[8]*zz + ts[2];
        int h = p >> 2, pp = p & 3;
        float s2 = 2.f*WL*coef_s[h];
        d_QfT[(h*32 + 16 + pp*3 + 0)*NTOK + n] = px*s2;
        d_QfT[(h*32 + 16 + pp*3 + 1)*NTOK + n] = py*s2;
        d_QfT[(h*32 + 16 + pp*3 + 2)*NTOK + n] = pz*s2;
    }
    if (tid < NH) d_QfT[(tid*32 + 28)*NTOK + n] = 1.f;
    for (int p = tid; p < 144; p += 128) {
        float x  = q0[720 + p*3 + 0] + q1[720 + p*3 + 0];
        float y  = q0[720 + p*3 + 1] + q1[720 + p*3 + 1];
        float zz = q0[720 + p*3 + 2] + q1[720 + p*3 + 2];
        float px = Rs[0]*x + Rs[1]*y + Rs[2]*zz + ts[0];
        float py = Rs[3]*x + Rs[4]*y + Rs[5]*zz + ts[1];
        float pz = Rs[6]*x + Rs[7]*y + Rs[8]*zz + ts[2];
        int h = p / 12, pp = p % 12;
        if (pp < PQN) {
            d_KfT[(h*32 + 16 + pp*3 + 0)*NTOK + n] = px;
            d_KfT[(h*32 + 16 + pp*3 + 1)*NTOK + n] = py;
            d_KfT[(h*32 + 16 + pp*3 + 2)*NTOK + n] = pz;
            atomicAdd(&sqk_s[h], px*px + py*py + pz*pz);
        } else {
            int d = 16 + (pp - PQN)*3;
            size_t base = ((size_t)h*NTOK + n)*64 + d;
            d_vJ[base + 0] = px;
            d_vJ[base + 1] = py;
            d_vJ[base + 2] = pz;
        }
    }
    __syncthreads();
    if (tid < NH) d_KfT[(tid*32 + 28)*NTOK + n] = -WL*coef_s[tid]*sqk_s[tid];
}

// ======== fused logits + bT + softmax + A@V + o_pt back-transform ========
// block = (16 i-rows, one head), 256 threads, dynamic smem.
// layout: as_s[16*512] @0 | Ks[2*32*68] @8192 (reused as v tiles) | Qs[512] | pt[16*24]
__global__ void k_lsmav() {
    extern __shared__ float sm[];
    float* as_s = sm;                      // 8192 floats
    float* Ksb  = sm + 8192;               // 4352 floats
    float* Qs   = sm + 8192 + 4352;        // 512 floats
    float* pt   = sm + 8192 + 4352 + 512;  // 384 floats
    int i0 = blockIdx.x * 16, h = blockIdx.y;
    int tid = threadIdx.x;          // 256
    int iloc = tid >> 4, jg = tid & 15;

    for (int l = tid; l < 512; l += 256)
        Qs[l] = d_QfT[(h*32 + (l & 15)*0 + (l >> 4))*NTOK + i0 + (l & 15)];
    // note: Qs layout [f][16]: index f*16 + il
    int lf[8], lj[8];
    #pragma unroll
    for (int u = 0; u < 8; u++) {
        int l = tid + u*256;
        lf[u] = l >> 6; lj[u] = l & 63;
    }
    #pragma unroll
    for (int u = 0; u < 8; u++)
        Ksb[0*2176 + lf[u]*68 + lj[u]] = d_KfT[(h*32 + lf[u])*NTOK + lj[u]];
    __syncthreads();
    float lv[32];
    #pragma unroll
    for (int t = 0; t < 8; t++) {
        float kr[8];
        if (t < 7) {
            #pragma unroll
            for (int u = 0; u < 8; u++)
                kr[u] = d_KfT[(h*32 + lf[u])*NTOK + (t+1)*64 + lj[u]];
        }
        int cur = t & 1;
        float a0 = 0.f, a1 = 0.f, a2 = 0.f, a3 = 0.f;
        #pragma unroll
        for (int f = 0; f < 32; f++) {
            float qf = Qs[f*16 + iloc];
            float4 kv = *reinterpret_cast<const float4*>(&Ksb[cur*2176 + f*68 + jg*4]);
            a0 += qf*kv.x; a1 += qf*kv.y; a2 += qf*kv.z; a3 += qf*kv.w;
        }
        lv[t*4+0] = a0; lv[t*4+1] = a1; lv[t*4+2] = a2; lv[t*4+3] = a3;
        if (t < 7) {
            #pragma unroll
            for (int u = 0; u < 8; u++)
                Ksb[(cur ^ 1)*2176 + lf[u]*68 + lj[u]] = kr[u];
        }
        __syncthreads();
    }
    int i = i0 + iloc;
    size_t rowoff = ((size_t)h*NTOK + i)*NTOK;
    float m = -1e30f;
    #pragma unroll
    for (int t = 0; t < 8; t++) {
        float4 bt = *reinterpret_cast<const float4*>(&d_bT[rowoff + t*64 + jg*4]);
        lv[t*4+0] += bt.x; lv[t*4+1] += bt.y; lv[t*4+2] += bt.z; lv[t*4+3] += bt.w;
        m = fmaxf(m, fmaxf(fmaxf(lv[t*4+0], lv[t*4+1]), fmaxf(lv[t*4+2], lv[t*4+3])));
    }
    #pragma unroll
    for (int o = 8; o; o >>= 1) m = fmaxf(m, __shfl_xor_sync(0xffffffffu, m, o));
    float s = 0.f;
    #pragma unroll
    for (int q = 0; q < 32; q++) { lv[q] = __expf(lv[q] - m); s += lv[q]; }
    #pragma unroll
    for (int o = 8; o; o >>= 1) s += __shfl_xor_sync(0xffffffffu, s, o);
    float inv = 1.f / s;
    #pragma unroll
    for (int t = 0; t < 8; t++) {
        float4 o4 = make_float4(lv[t*4+0]*inv, lv[t*4+1]*inv, lv[t*4+2]*inv, lv[t*4+3]*inv);
        *reinterpret_cast<float4*>(&d_a[rowoff + t*64 + jg*4]) = o4;
        *reinterpret_cast<float4*>(&as_s[iloc*512 + t*64 + jg*4]) = o4;
    }
    __syncthreads();   // as_s complete; Ksb free for v tiles

    // ---- A@V phase: C[16][40] = as_s[16][512] @ vJ[h][512][64(40)] ----
    const float4* Vb = reinterpret_cast<const float4*>(&d_vJ[(size_t)h*NTOK*64]);
    float4* vb0 = reinterpret_cast<float4*>(Ksb);
    float4* vb1 = vb0 + 512;
    vb0[tid]       = Vb[tid];
    vb0[256 + tid] = Vb[256 + tid];
    __syncthreads();
    int r = tid >> 4, q = tid & 15;
    float4 acc = make_float4(0.f, 0.f, 0.f, 0.f);
    for (int t = 0; t < 16; t++) {
        float4* curv = (t & 1) ? vb1 : vb0;
        float4 pre0, pre1;
        if (t < 15) {
            pre0 = Vb[(t+1)*512 + tid];
            pre1 = Vb[(t+1)*512 + 256 + tid];
        }
        if (q < 10) {
            #pragma unroll 8
            for (int jj = 0; jj < 32; jj++) {
                float av = as_s[r*512 + t*32 + jj];
                float4 v4 = curv[jj*16 + q];
                acc.x += av*v4.x; acc.y += av*v4.y; acc.z += av*v4.z; acc.w += av*v4.w;
            }
        }
        if (t < 15) {
            float4* nx = (t & 1) ? vb0 : vb1;
            nx[tid] = pre0;
            nx[256 + tid] = pre1;
        }
        __syncthreads();
    }
    int irow = i0 + r;
    if (q < 4) {
        *reinterpret_cast<float4*>(&d_cat[(size_t)irow*CAT_W + h*16 + q*4]) = acc;
    } else if (q < 10) {
        pt[r*24 + (q-4)*4 + 0] = acc.x;
        pt[r*24 + (q-4)*4 + 1] = acc.y;
        pt[r*24 + (q-4)*4 + 2] = acc.z;
        pt[r*24 + (q-4)*4 + 3] = acc.w;
    }
    __syncthreads();
    // o_pt back-transform + norm
    if (tid < 128) {
        int rr = tid >> 3, p = tid & 7;
        int ii = i0 + rr;
        float v0 = pt[rr*24 + p*3 + 0];
        float v1 = pt[rr*24 + p*3 + 1];
        float v2 = pt[rr*24 + p*3 + 2];
        const float* Rp = &d_R[ii*9];
        float t0 = d_t[ii*3+0], t1 = d_t[ii*3+1], t2 = d_t[ii*3+2];
        float gx = v0 - t0, gy = v1 - t1, gz = v2 - t2;
        float lx = Rp[0]*gx + Rp[3]*gy + Rp[6]*gz;
        float ly = Rp[1]*gx + Rp[4]*gy + Rp[7]*gz;
        float lz = Rp[2]*gx + Rp[5]*gy + Rp[8]*gz;
        float* cr = &d_cat[(size_t)ii*CAT_W];
        cr[192 + h*24 + p*3 + 0] = lx;
        cr[192 + h*24 + p*3 + 1] = ly;
        cr[192 + h*24 + p*3 + 2] = lz;
        cr[480 + h*8 + p] = sqrtf(lx*lx + ly*ly + lz*lz + 1e-8f);
    }
}

// ======== o_pair: 256 threads = 4 compute warps + 4 loader warps ========
__global__ void k_opair(const float* __restrict__ z) {
    extern __shared__ float smf[];
    int tid = threadIdx.x;  // 256
    int i = blockIdx.x;
    float* as = smf;                 // 6144 floats
    float4* zb0 = reinterpret_cast<float4*>(smf + 6144);
    float4* zb1 = zb0 + 1024;
    float4* as4 = reinterpret_cast<float4*>(as);
    const float4* asrc = reinterpret_cast<const float4*>(d_a);
    #pragma unroll
    for (int u = 0; u < 6; u++) {
        int l = tid + u*256;
        int hh = l >> 7, qq = l & 127;
        as4[hh*128 + qq] = asrc[(((size_t)hh*NTOK + i)*NTOK >> 2) + qq];
    }
    const float4* zsrc = reinterpret_cast<const float4*>(z + (size_t)i*NTOK*CZD);
    bool loader = (tid >= 128);
    int lt = tid - 128;
    if (loader) {
        #pragma unroll
        for (int u = 0; u < 8; u++) zb0[u*128 + lt] = zsrc[u*128 + lt];
    }
    __syncthreads();
    int lane = tid & 31, h0 = tid >> 5;   // compute path uses tid<128
    float acc[3][4] = {};
    for (int t = 0; t < 16; t++) {
        float4* cur = (t & 1) ? zb1 : zb0;
        if (loader) {
            if (t < 15) {
                float4* nxt = (t & 1) ? zb0 : zb1;
                #pragma unroll
                for (int u = 0; u < 8; u++)
                    nxt[u*128 + lt] = zsrc[(size_t)(t+1)*1024 + u*128 + lt];
            }
        } else {
            int jt = t*32;
            #pragma unroll 4
            for (int jj = 0; jj < 32; jj++) {
                float4 zv = cur[jj*32 + lane];
                float a0 = as[(h0+0)*NTOK + jt + jj];
                float a1 = as[(h0+4)*NTOK + jt + jj];
                float a2 = as[(h0+8)*NTOK + jt + jj];
                acc[0][0] += a0*zv.x; acc[0][1] += a0*zv.y; acc[0][2] += a0*zv.z; acc[0][3] += a0*zv.w;
                acc[1][0] += a1*zv.x; acc[1][1] += a1*zv.y; acc[1][2] += a1*zv.z; acc[1][3] += a1*zv.w;
                acc[2][0] += a2*zv.x; acc[2][1] += a2*zv.y; acc[2][2] += a2*zv.z; acc[2][3] += a2*zv.w;
            }
        }
        __syncthreads();
    }
    if (!loader) {
        #pragma unroll
        for (int hh = 0; hh < 3; hh++) {
            int h = h0 + hh*4;
            *reinterpret_cast<float4*>(&d_cat[(size_t)i*CAT_W + 576 + h*CZD + lane*4]) =
                make_float4(acc[hh][0], acc[hh][1], acc[hh][2], acc[hh][3]);
        }
    }
}

// ---------------- s = LN(s + bias + sum_p part[p]) ----------------
__global__ void k_addln(const float* __restrict__ part, int P,
                        const float* __restrict__ bias,
                        const float* __restrict__ g, const float* __restrict__ b) {
    int i = blockIdx.x;
    int tid = threadIdx.x;  // 128
    __shared__ float red[4];
    float v[3];
    float sum = 0.f;
    #pragma unroll
    for (int k = 0; k < 3; k++) {
        int c = tid + k*128;
        float x = d_s[(size_t)i*CSD + c];
        if (bias) x += bias[c];
        for (int p = 0; p < P; p++) x += part[(size_t)p*MNS + (size_t)i*CSD + c];
        v[k] = x;
        sum += x;
    }
    #pragma unroll
    for (int o = 16; o; o >>= 1) sum += __shfl_xor_sync(0xffffffffu, sum, o);
    if ((tid & 31) == 0) red[tid >> 5] = sum;
    __syncthreads();
    float tot = red[tid & 3];
    #pragma unroll
    for (int o = 2; o; o >>= 1) tot += __shfl_xor_sync(0xffffffffu, tot, o);
    float mean = tot * (1.f/384.f);
    float var = 0.f;
    #pragma unroll
    for (int k = 0; k < 3; k++) { float d = v[k] - mean; var += d*d; }
    #pragma unroll
    for (int o = 16; o; o >>= 1) var += __shfl_xor_sync(0xffffffffu, var, o);
    __syncthreads();
    if ((tid & 31) == 0) red[tid >> 5] = var;
    __syncthreads();
    float tv = red[tid & 3];
    #pragma unroll
    for (int o = 2; o; o >>= 1) tv += __shfl_xor_sync(0xffffffffu, tv, o);
    float inv = rsqrtf(tv*(1.f/384.f) + 1e-5f);
    #pragma unroll
    for (int k = 0; k < 3; k++) {
        int c = tid + k*128;
        d_s[(size_t)i*CSD + c] = (v[k] - mean)*inv*g[c] + b[c];
    }
}

// ------- ln2 + fused backbone update -------
__global__ void k_addln_bb(const float* __restrict__ part, int P,
                           const float* __restrict__ g, const float* __restrict__ b,
                           const float* __restrict__ wbb, const float* __restrict__ bbb) {
    int i = blockIdx.x;
    int tid = threadIdx.x;  // 128
    __shared__ float red[4];
    __shared__ float red6[4][6];
    __shared__ float upd[6];
    float v[3];
    float sum = 0.f;
    #pragma unroll
    for (int k = 0; k < 3; k++) {
        int c = tid + k*128;
        float x = d_s[(size_t)i*CSD + c];
        for (int p = 0; p < P; p++) x += part[(size_t)p*MNS + (size_t)i*CSD + c];
        v[k] = x;
        sum += x;
    }
    #pragma unroll
    for (int o = 16; o; o >>= 1) sum += __shfl_xor_sync(0xffffffffu, sum, o);
    if ((tid & 31) == 0) red[tid >> 5] = sum;
    __syncthreads();
    float tot = red[tid & 3];
    #pragma unroll
    for (int o = 2; o; o >>= 1) tot += __shfl_xor_sync(0xffffffffu, tot, o);
    float mean = tot * (1.f/384.f);
    float var = 0.f;
    #pragma unroll
    for (int k = 0; k < 3; k++) { float d = v[k] - mean; var += d*d; }
    #pragma unroll
    for (int o = 16; o; o >>= 1) var += __shfl_xor_sync(0xffffffffu, var, o);
    __syncthreads();
    if ((tid & 31) == 0) red[tid >> 5] = var;
    __syncthreads();
    float tv = red[tid & 3];
    #pragma unroll
    for (int o = 2; o; o >>= 1) tv += __shfl_xor_sync(0xffffffffu, tv, o);
    float inv = rsqrtf(tv*(1.f/384.f) + 1e-5f);
    float sv[3];
    #pragma unroll
    for (int k = 0; k < 3; k++) {
        int c = tid + k*128;
        sv[k] = (v[k] - mean)*inv*g[c] + b[c];
        d_s[(size_t)i*CSD + c] = sv[k];
    }
    float a6[6];
    #pragma unroll
    for (int o = 0; o < 6; o++) {
        a6[o] = sv[0]*wbb[(tid      )*6 + o]
              + sv[1]*wbb[(tid + 128)*6 + o]
              + sv[2]*wbb[(tid + 256)*6 + o];
    }
    #pragma unroll
    for (int o = 0; o < 6; o++)
        #pragma unroll
        for (int off = 16; off; off >>= 1)
            a6[o] += __shfl_xor_sync(0xffffffffu, a6[o], off);
    if ((tid & 31) == 0) {
        #pragma unroll
        for (int o = 0; o < 6; o++) red6[tid >> 5][o] = a6[o];
    }
    __syncthreads();
    if (tid < 6) upd[tid] = red6[0][tid] + red6[1][tid] + red6[2][tid] + red6[3][tid] + bbb[tid];
    __syncthreads();
    if (tid == 0) {
        float qb = upd[0], qc = upd[1], qd = upd[2];
        float qi = rsqrtf(1.f + qb*qb + qc*qc + qd*qd);
        float w = qi, x = qb*qi, y = qc*qi, zq = qd*qi;
        float Ru[9];
        Ru[0] = 1.f - 2.f*(y*y + zq*zq); Ru[1] = 2.f*(x*y - w*zq);        Ru[2] = 2.f*(x*zq + w*y);
        Ru[3] = 2.f*(x*y + w*zq);        Ru[4] = 1.f - 2.f*(x*x + zq*zq); Ru[5] = 2.f*(y*zq - w*x);
        Ru[6] = 2.f*(x*zq - w*y);        Ru[7] = 2.f*(y*zq + w*x);        Ru[8] = 1.f - 2.f*(x*x + y*y);
        float Ro[9];
        #pragma unroll
        for (int k = 0; k < 9; k++) Ro[k] = d_R[i*9 + k];
        float tu0 = upd[3], tu1 = upd[4], tu2 = upd[5];
        #pragma unroll
        for (int r = 0; r < 3; r++)
            d_t[i*3 + r] += Ro[r*3+0]*tu0 + Ro[r*3+1]*tu1 + Ro[r*3+2]*tu2;
        #pragma unroll
        for (int r = 0; r < 3; r++)
            #pragma unroll
            for (int c = 0; c < 3; c++)
                d_R[i*9 + r*3 + c] = Ro[r*3+0]*Ru[0*3+c] + Ro[r*3+1]*Ru[1*3+c] + Ro[r*3+2]*Ru[2*3+c];
    }
}

// ---------------- final output [s | t] ----------------
__global__ void k_out(float* __restrict__ out) {
    int idx = blockIdx.x*blockDim.x + threadIdx.x;
    if (idx >= NTOK*387) return;
    int i = idx / 387, c = idx % 387;
    out[idx] = (c < 384) ? d_s[(size_t)i*CSD + c] : d_t[i*3 + (c - 384)];
}

// ---------------- host ----------------
extern "C" void kernel_launch(void* const* d_in, const int* in_sizes, int n_in,
                              void* d_out, int out_size) {
    (void)in_sizes; (void)n_in; (void)out_size;
    const float* s     = (const float*)d_in[0];
    const float* z     = (const float*)d_in[1];
    const float* wq    = (const float*)d_in[2];
    const float* wkv   = (const float*)d_in[3];
    const float* wqp   = (const float*)d_in[4];
    const float* wkvp  = (const float*)d_in[5];
    const float* wb    = (const float*)d_in[6];
    const float* hw    = (const float*)d_in[7];
    const float* wout  = (const float*)d_in[8];
    const float* bout  = (const float*)d_in[9];
    const float* ln1g  = (const float*)d_in[10];
    const float* ln1b  = (const float*)d_in[11];
    const float* wt1   = (const float*)d_in[12];
    const float* wt2   = (const float*)d_in[13];
    const float* wt3   = (const float*)d_in[14];
    const float* ln2g  = (const float*)d_in[15];
    const float* ln2b  = (const float*)d_in[16];
    const float* wbb   = (const float*)d_in[17];
    const float* bbb   = (const float*)d_in[18];

    float *p_s, *p_Wall, *p_cat, *p_part;
    float *p_WallHi, *p_WallLo, *p_woutHi, *p_woutLo, *p_wtHi, *p_wtLo;
    cudaGetSymbolAddress((void**)&p_s,      d_s);
    cudaGetSymbolAddress((void**)&p_Wall,   d_Wall);
    cudaGetSymbolAddress((void**)&p_cat,    d_cat);
    cudaGetSymbolAddress((void**)&p_part,   d_part);
    cudaGetSymbolAddress((void**)&p_WallHi, d_WallHi);
    cudaGetSymbolAddress((void**)&p_WallLo, d_WallLo);
    cudaGetSymbolAddress((void**)&p_woutHi, d_woutHi);
    cudaGetSymbolAddress((void**)&p_woutLo, d_woutLo);
    cudaGetSymbolAddress((void**)&p_wtHi,   d_wtHi);
    cudaGetSymbolAddress((void**)&p_wtLo,   d_wtLo);

    cudaFuncSetAttribute(k_lsmav, cudaFuncAttributeMaxDynamicSharedMemorySize, 53760);
    cudaFuncSetAttribute(k_opair, cudaFuncAttributeMaxDynamicSharedMemorySize, 57344);

    k_init<<<(NTOK*CSD + 255)/256, 256>>>(s);
    k_catW<<<(CSD*QKV_W + 255)/256, 256>>>(wq, wkv, wqp, wkvp);
    k_splitW<<<(CSD*QKV_W + 255)/256, 256>>>(p_Wall, p_WallHi, p_WallLo, CSD*QKV_W);
    k_splitW<<<(CAT_W*CSD + 255)/256, 256>>>(wout, p_woutHi, p_woutLo, CAT_W*CSD);
    k_splitW<<<(CSD*CSD + 255)/256, 256>>>(wt1, p_wtHi,             p_wtLo,             CSD*CSD);
    k_splitW<<<(CSD*CSD + 255)/256, 256>>>(wt2, p_wtHi + CSD*CSD,   p_wtLo + CSD*CSD,   CSD*CSD);
    k_splitW<<<(CSD*CSD + 255)/256, 256>>>(wt3, p_wtHi + 2*CSD*CSD, p_wtLo + 2*CSD*CSD, CSD*CSD);
    k_bT<<<512, 256>>>(z, wb);

    for (int it = 0; it < NBLK; it++) {
        // qkv/points projection: K=384 split 2 -> 288 blocks
        mm3<<<dim3(QKV_W/64, NTOK/64, 2), 256>>>(p_s, p_WallHi, p_WallLo, p_part,
                                                 NTOK, QKV_W, CSD, CSD/2, 0);
        k_transform<<<NTOK, 128>>>(hw);
        // fused logits/softmax/A@V/o_pt: 384 blocks
        k_lsmav<<<dim3(32, NH), 256, 53760>>>();
        // o_pair with loader warps: 512 blocks
        k_opair<<<NTOK, 256, 57344>>>(z);
        // out projection: K=2112 split 6 -> 288 blocks
        mm3<<<dim3(CSD/64, NTOK/64, 6), 256>>>(p_cat, p_woutHi, p_woutLo, p_part,
                                               NTOK, CSD, CAT_W, CAT_W/6, 0);
        k_addln<<<NTOK, 128>>>(p_part, 6, bout, ln1g, ln1b);
        // transition: t1 plain, t2/t3 fused relu-of-3-partials A-load
        mm3<<<dim3(CSD/64, NTOK/64, 3), 256>>>(p_s, p_wtHi, p_wtLo, p_part,
                                               NTOK, CSD, CSD, CSD/3, 0);
        mm3<<<dim3(CSD/64, NTOK/64, 3), 256>>>(p_part, p_wtHi + CSD*CSD, p_wtLo + CSD*CSD,
                                               p_part + (size_t)3*MNS,
                                               NTOK, CSD, CSD, CSD/3, 1);
        mm3<<<dim3(CSD/64, NTOK/64, 3), 256>>>(p_part + (size_t)3*MNS,
                                               p_wtHi + 2*CSD*CSD, p_wtLo + 2*CSD*CSD, p_part,
                                               NTOK, CSD, CSD, CSD/3, 1);
        k_addln_bb<<<NTOK, 128>>>(p_part, 3, ln2g, ln2b, wbb, bbb);
    }
    k_out<<<(NTOK*387 + 255)/256, 256>>>((float*)d_out);
}